// round 1
// baseline (speedup 1.0000x reference)
#include <cuda_runtime.h>
#include <math.h>

#define BB     16
#define NN     1024
#define DIMV   384
#define DEPTH  6
#define HEADS  6
#define DH     64
#define INNER  384
#define MLPV   1536
#define ROWS   (BB*NN)       // 16384
#define BHN    (BB*HEADS)    // 96
#define QKVW   (3*INNER)     // 1152

// ---------------- scratch (static device allocations; no cudaMalloc) ----------------
__device__ float g_ln[(size_t)ROWS * DIMV];              //  25 MB
__device__ float g_qkv[(size_t)ROWS * QKVW];             //  75 MB
__device__ float g_dots[(size_t)BHN * NN * NN];          // 402 MB
__device__ float g_attn[(size_t)ROWS * INNER];           //  25 MB
__device__ float g_ff[(size_t)ROWS * MLPV];              // 100 MB

// ---------------- LayerNorm: one block (128 thr) per row of 384 ----------------
__global__ void ln_kernel(const float* __restrict__ x,
                          const float* __restrict__ gamma,
                          const float* __restrict__ beta,
                          float* __restrict__ y) {
    int row = blockIdx.x;
    const float* xr = x + (size_t)row * DIMV;
    float*       yr = y + (size_t)row * DIMV;
    int t = threadIdx.x;
    float v0 = xr[t], v1 = xr[t + 128], v2 = xr[t + 256];
    float s = v0 + v1 + v2;
    float q = v0 * v0 + v1 * v1 + v2 * v2;
    #pragma unroll
    for (int o = 16; o > 0; o >>= 1) {
        s += __shfl_down_sync(0xffffffffu, s, o);
        q += __shfl_down_sync(0xffffffffu, q, o);
    }
    __shared__ float shs[4], shq[4];
    __shared__ float s_mean, s_inv;
    int w = t >> 5, lane = t & 31;
    if (lane == 0) { shs[w] = s; shq[w] = q; }
    __syncthreads();
    if (t == 0) {
        float S = shs[0] + shs[1] + shs[2] + shs[3];
        float Q = shq[0] + shq[1] + shq[2] + shq[3];
        float m = S * (1.0f / 384.0f);
        float var = Q * (1.0f / 384.0f) - m * m;
        s_mean = m;
        s_inv  = rsqrtf(var + 1e-5f);
    }
    __syncthreads();
    float m = s_mean, inv = s_inv;
    yr[t]       = (v0 - m) * inv * gamma[t]       + beta[t];
    yr[t + 128] = (v1 - m) * inv * gamma[t + 128] + beta[t + 128];
    yr[t + 256] = (v2 - m) * inv * gamma[t + 256] + beta[t + 256];
}

// ---------------- Generic fp32 GEMM: C[M,N] = A[M,K] @ B[K,N] (+ epilogue) ----------
// 128x128 tile, BK=16, 256 threads, 8x8 micro-tile per thread.
// EPI 0: C = AB            (qkv projection)
// EPI 1: C = res + AB + b  (residual projections; res == C is allowed)
// EPI 2: C = gelu(AB + b)  (FF1)
template <int EPI>
__global__ void gemm_kernel(const float* __restrict__ A,
                            const float* __restrict__ Bw,
                            const float* __restrict__ bias,
                            const float* __restrict__ res,
                            float* __restrict__ C,
                            int M, int Nn, int K) {
    __shared__ float As[16][132];   // transposed A tile  [k][m], padded for 16B-aligned rows
    __shared__ float Bs[16][128];   // B tile [k][n]
    int tid = threadIdx.x;          // 256
    int tx = tid & 15, ty = tid >> 4;
    int m0 = blockIdx.y * 128, n0 = blockIdx.x * 128;

    float acc[8][8];
    #pragma unroll
    for (int i = 0; i < 8; i++)
        #pragma unroll
        for (int j = 0; j < 8; j++) acc[i][j] = 0.0f;

    for (int kt = 0; kt < K; kt += 16) {
        #pragma unroll
        for (int i = 0; i < 2; i++) {
            int f = tid + i * 256;                 // 0..511
            // A tile: 128 rows x 16 k  = 512 float4
            int r  = f >> 2;
            int c4 = (f & 3) * 4;
            float4 a4 = *(const float4*)(A + (size_t)(m0 + r) * K + kt + c4);
            As[c4 + 0][r] = a4.x;
            As[c4 + 1][r] = a4.y;
            As[c4 + 2][r] = a4.z;
            As[c4 + 3][r] = a4.w;
            // B tile: 16 k x 128 n = 512 float4
            int k  = f >> 5;
            int n4 = (f & 31) * 4;
            *(float4*)&Bs[k][n4] = *(const float4*)(Bw + (size_t)(kt + k) * Nn + n0 + n4);
        }
        __syncthreads();
        #pragma unroll
        for (int k = 0; k < 16; k++) {
            float4 a0 = *(const float4*)&As[k][ty * 4];
            float4 a1 = *(const float4*)&As[k][64 + ty * 4];
            float4 b0 = *(const float4*)&Bs[k][tx * 4];
            float4 b1 = *(const float4*)&Bs[k][64 + tx * 4];
            float av_[8] = {a0.x, a0.y, a0.z, a0.w, a1.x, a1.y, a1.z, a1.w};
            float bv_[8] = {b0.x, b0.y, b0.z, b0.w, b1.x, b1.y, b1.z, b1.w};
            #pragma unroll
            for (int i = 0; i < 8; i++)
                #pragma unroll
                for (int j = 0; j < 8; j++)
                    acc[i][j] += av_[i] * bv_[j];
        }
        __syncthreads();
    }

    #pragma unroll
    for (int ih = 0; ih < 2; ih++) {
        #pragma unroll
        for (int i = 0; i < 4; i++) {
            int gr = m0 + ih * 64 + ty * 4 + i;
            #pragma unroll
            for (int jh = 0; jh < 2; jh++) {
                int gc = n0 + jh * 64 + tx * 4;
                float4 o;
                float* op = (float*)&o;
                #pragma unroll
                for (int j = 0; j < 4; j++) {
                    float v = acc[ih * 4 + i][jh * 4 + j];
                    if (EPI >= 1) v += bias[gc + j];
                    if (EPI == 1) v += res[(size_t)gr * Nn + gc + j];
                    if (EPI == 2) v = 0.5f * v * (1.0f + erff(v * 0.70710678118654752f));
                    op[j] = v;
                }
                *(float4*)(C + (size_t)gr * Nn + gc) = o;
            }
        }
    }
}

// ---------------- Attention scores: dots[bh,i,j] = scale * q_i . k_j ; diag = -FLT_MAX
// 64x64 output tile per block, 256 threads, 4x4 micro-tile. K-dim = DH = 64 (single pass).
__global__ void dots_kernel(const float* __restrict__ qkv,
                            float* __restrict__ dots,
                            const float* __restrict__ temp,
                            int layer) {
    __shared__ float Qs[64][65];
    __shared__ float Ks[64][65];
    int bh = blockIdx.z;
    int b = bh / HEADS, h = bh - b * HEADS;
    int rt = blockIdx.y * 64, ct = blockIdx.x * 64;
    int tid = threadIdx.x;
    int tx = tid & 15, ty = tid >> 4;

    const float* qb = qkv + (size_t)b * NN * QKVW + h * DH;
    const float* kb = qb + INNER;

    #pragma unroll
    for (int i = 0; i < 4; i++) {
        int idx = tid + i * 256;       // 0..1023 -> 64 rows x 16 float4
        int r  = idx >> 4;
        int c4 = (idx & 15) * 4;
        float4 q4 = *(const float4*)(qb + (size_t)(rt + r) * QKVW + c4);
        Qs[r][c4 + 0] = q4.x; Qs[r][c4 + 1] = q4.y; Qs[r][c4 + 2] = q4.z; Qs[r][c4 + 3] = q4.w;
        float4 k4 = *(const float4*)(kb + (size_t)(ct + r) * QKVW + c4);
        Ks[r][c4 + 0] = k4.x; Ks[r][c4 + 1] = k4.y; Ks[r][c4 + 2] = k4.z; Ks[r][c4 + 3] = k4.w;
    }
    __syncthreads();

    float acc[4][4];
    #pragma unroll
    for (int i = 0; i < 4; i++)
        #pragma unroll
        for (int j = 0; j < 4; j++) acc[i][j] = 0.0f;

    #pragma unroll
    for (int d = 0; d < 64; d++) {
        float a[4], bv[4];
        #pragma unroll
        for (int i = 0; i < 4; i++) a[i]  = Qs[ty * 4 + i][d];
        #pragma unroll
        for (int j = 0; j < 4; j++) bv[j] = Ks[tx * 4 + j][d];
        #pragma unroll
        for (int i = 0; i < 4; i++)
            #pragma unroll
            for (int j = 0; j < 4; j++)
                acc[i][j] += a[i] * bv[j];
    }

    float scale = expf(temp[layer]);
    float* out = dots + (size_t)bh * NN * NN;
    #pragma unroll
    for (int i = 0; i < 4; i++) {
        int gi = rt + ty * 4 + i;
        #pragma unroll
        for (int j = 0; j < 4; j++) {
            int gj = ct + tx * 4 + j;
            out[(size_t)gi * NN + gj] =
                (gi == gj) ? -3.4028234663852886e38f : acc[i][j] * scale;
        }
    }
}

// ---------------- Row softmax over 1024 elems (one block of 256 per row) ------------
__global__ void softmax_kernel(float* __restrict__ dots) {
    float* p = dots + ((size_t)blockIdx.y * NN + blockIdx.x) * NN;
    int t = threadIdx.x;
    float v0 = p[t], v1 = p[t + 256], v2 = p[t + 512], v3 = p[t + 768];
    float m = fmaxf(fmaxf(v0, v1), fmaxf(v2, v3));
    #pragma unroll
    for (int o = 16; o > 0; o >>= 1) m = fmaxf(m, __shfl_xor_sync(0xffffffffu, m, o));
    __shared__ float sh[8];
    __shared__ float s_m, s_s;
    int w = t >> 5, lane = t & 31;
    if (lane == 0) sh[w] = m;
    __syncthreads();
    if (t == 0) {
        float mm = sh[0];
        #pragma unroll
        for (int i = 1; i < 8; i++) mm = fmaxf(mm, sh[i]);
        s_m = mm;
    }
    __syncthreads();
    m = s_m;
    float e0 = expf(v0 - m), e1 = expf(v1 - m), e2 = expf(v2 - m), e3 = expf(v3 - m);
    float s = e0 + e1 + e2 + e3;
    #pragma unroll
    for (int o = 16; o > 0; o >>= 1) s += __shfl_xor_sync(0xffffffffu, s, o);
    if (lane == 0) sh[w] = s;
    __syncthreads();
    if (t == 0) {
        float ss = sh[0];
        #pragma unroll
        for (int i = 1; i < 8; i++) ss += sh[i];
        s_s = ss;
    }
    __syncthreads();
    float inv = 1.0f / s_s;
    p[t] = e0 * inv; p[t + 256] = e1 * inv; p[t + 512] = e2 * inv; p[t + 768] = e3 * inv;
}

// ---------------- o = attn @ v : [1024,1024] @ [1024,64] per (b,h) ------------------
// block = 64 output rows x 64 head-dim cols; loop K=1024 in 64-chunks.
__global__ void av_kernel(const float* __restrict__ dots,
                          const float* __restrict__ qkv,
                          float* __restrict__ o) {
    __shared__ float As[64][65];
    __shared__ float Vs[64][65];
    int bh = blockIdx.y;
    int b = bh / HEADS, h = bh - b * HEADS;
    int rt = blockIdx.x * 64;
    int tid = threadIdx.x;
    int tx = tid & 15, ty = tid >> 4;

    const float* vb = qkv + (size_t)b * NN * QKVW + 2 * INNER + h * DH;
    const float* dp = dots + (size_t)bh * NN * NN;

    float acc[4][4];
    #pragma unroll
    for (int i = 0; i < 4; i++)
        #pragma unroll
        for (int j = 0; j < 4; j++) acc[i][j] = 0.0f;

    for (int kt = 0; kt < NN; kt += 64) {
        #pragma unroll
        for (int i = 0; i < 4; i++) {
            int idx = tid + i * 256;
            int r  = idx >> 4;
            int c4 = (idx & 15) * 4;
            float4 a4 = *(const float4*)(dp + (size_t)(rt + r) * NN + kt + c4);
            As[r][c4 + 0] = a4.x; As[r][c4 + 1] = a4.y; As[r][c4 + 2] = a4.z; As[r][c4 + 3] = a4.w;
            float4 v4 = *(const float4*)(vb + (size_t)(kt + r) * QKVW + c4);
            Vs[r][c4 + 0] = v4.x; Vs[r][c4 + 1] = v4.y; Vs[r][c4 + 2] = v4.z; Vs[r][c4 + 3] = v4.w;
        }
        __syncthreads();
        #pragma unroll
        for (int kk = 0; kk < 64; kk++) {
            float a[4], bv[4];
            #pragma unroll
            for (int i = 0; i < 4; i++) a[i]  = As[ty * 4 + i][kk];
            #pragma unroll
            for (int j = 0; j < 4; j++) bv[j] = Vs[kk][tx * 4 + j];
            #pragma unroll
            for (int i = 0; i < 4; i++)
                #pragma unroll
                for (int j = 0; j < 4; j++)
                    acc[i][j] += a[i] * bv[j];
        }
        __syncthreads();
    }

    #pragma unroll
    for (int i = 0; i < 4; i++) {
        int gr = b * NN + rt + ty * 4 + i;
        float4 ov;
        ov.x = acc[i][0]; ov.y = acc[i][1]; ov.z = acc[i][2]; ov.w = acc[i][3];
        *(float4*)(o + (size_t)gr * INNER + h * DH + tx * 4) = ov;
    }
}

// ---------------- driver ----------------
extern "C" void kernel_launch(void* const* d_in, const int* in_sizes, int n_in,
                              void* d_out, int out_size) {
    const float* x_in  = (const float*)d_in[0];
    const float* ln1_g = (const float*)d_in[1];
    const float* ln1_b = (const float*)d_in[2];
    const float* qkv_w = (const float*)d_in[3];
    const float* temp  = (const float*)d_in[4];
    const float* out_w = (const float*)d_in[5];
    const float* out_b = (const float*)d_in[6];
    const float* ln2_g = (const float*)d_in[7];
    const float* ln2_b = (const float*)d_in[8];
    const float* ff_w1 = (const float*)d_in[9];
    const float* ff_b1 = (const float*)d_in[10];
    const float* ff_w2 = (const float*)d_in[11];
    const float* ff_b2 = (const float*)d_in[12];
    float* x = (float*)d_out;                       // [ROWS, DIMV] running activation

    float *p_ln, *p_qkv, *p_dots, *p_attn, *p_ff;
    cudaGetSymbolAddress((void**)&p_ln,   g_ln);
    cudaGetSymbolAddress((void**)&p_qkv,  g_qkv);
    cudaGetSymbolAddress((void**)&p_dots, g_dots);
    cudaGetSymbolAddress((void**)&p_attn, g_attn);
    cudaGetSymbolAddress((void**)&p_ff,   g_ff);

    cudaMemcpyAsync(x, x_in, (size_t)ROWS * DIMV * sizeof(float),
                    cudaMemcpyDeviceToDevice);

    for (int l = 0; l < DEPTH; l++) {
        // --- attention block ---
        ln_kernel<<<ROWS, 128>>>(x, ln1_g + l * DIMV, ln1_b + l * DIMV, p_ln);
        gemm_kernel<0><<<dim3(QKVW / 128, ROWS / 128), 256>>>(
            p_ln, qkv_w + (size_t)l * DIMV * QKVW, nullptr, nullptr, p_qkv,
            ROWS, QKVW, DIMV);
        dots_kernel<<<dim3(NN / 64, NN / 64, BHN), 256>>>(p_qkv, p_dots, temp, l);
        softmax_kernel<<<dim3(NN, BHN), 256>>>(p_dots);
        av_kernel<<<dim3(NN / 64, BHN), 256>>>(p_dots, p_qkv, p_attn);
        gemm_kernel<1><<<dim3(DIMV / 128, ROWS / 128), 256>>>(
            p_attn, out_w + (size_t)l * INNER * DIMV, out_b + l * DIMV, x, x,
            ROWS, DIMV, INNER);
        // --- feed-forward block ---
        ln_kernel<<<ROWS, 128>>>(x, ln2_g + l * DIMV, ln2_b + l * DIMV, p_ln);
        gemm_kernel<2><<<dim3(MLPV / 128, ROWS / 128), 256>>>(
            p_ln, ff_w1 + (size_t)l * DIMV * MLPV, ff_b1 + l * MLPV, nullptr, p_ff,
            ROWS, MLPV, DIMV);
        gemm_kernel<1><<<dim3(DIMV / 128, ROWS / 128), 256>>>(
            p_ff, ff_w2 + (size_t)l * MLPV * DIMV, ff_b2 + l * DIMV, x, x,
            ROWS, DIMV, MLPV);
    }
}

// round 3
// speedup vs baseline: 2.6396x; 2.6396x over previous
#include <cuda_runtime.h>
#include <math.h>
#include <stdint.h>

#define BB     16
#define NN     1024
#define DIMV   384
#define DEPTH  6
#define HEADS  6
#define DH     64
#define INNER  384
#define MLPV   1536
#define ROWS   (BB*NN)       // 16384
#define BHN    (BB*HEADS)    // 96
#define QKVW   (3*INNER)     // 1152
#define NEGMAX -3.4028234663852886e38f

// ---------------- scratch (static device allocations; no cudaMalloc) ----------------
__device__ float g_ln[(size_t)ROWS * DIMV];              //  25 MB
__device__ float g_qkv[(size_t)ROWS * QKVW];             //  75 MB
__device__ float g_dots[(size_t)BHN * NN * NN];          // 402 MB
__device__ float g_attn[(size_t)ROWS * INNER];           //  25 MB
__device__ float g_ff[(size_t)ROWS * MLPV];              // 100 MB
// transposed weights: qkvT | woT | w1T | w2T  (per-layer contiguous, K-major rows)
#define WT_QKV_OFF  0
#define WT_QKV_PER  (QKVW*DIMV)
#define WT_WO_OFF   (WT_QKV_OFF + DEPTH*WT_QKV_PER)
#define WT_WO_PER   (DIMV*INNER)
#define WT_W1_OFF   (WT_WO_OFF + DEPTH*WT_WO_PER)
#define WT_W1_PER   (MLPV*DIMV)
#define WT_W2_OFF   (WT_W1_OFF + DEPTH*WT_W1_PER)
#define WT_W2_PER   (DIMV*MLPV)
__device__ float g_wt[(size_t)(WT_W2_OFF + DEPTH*WT_W2_PER)];   // ~40.5 MB

// ================= helpers =================
__device__ __forceinline__ uint32_t smem_u32(const void* p) {
    uint32_t r;
    asm("{ .reg .u64 t; cvta.to.shared.u64 t, %1; cvt.u32.u64 %0, t; }" : "=r"(r) : "l"(p));
    return r;
}
__device__ __forceinline__ uint32_t f2tf(float x) {
    uint32_t r;
    asm("cvt.rna.tf32.f32 %0, %1;" : "=r"(r) : "f"(x));
    return r;
}
__device__ __forceinline__ void cp16(uint32_t dst, const void* src) {
    asm volatile("cp.async.cg.shared.global [%0], [%1], 16;" :: "r"(dst), "l"(src));
}
__device__ __forceinline__ void mma8(float c[4], const uint32_t a[4], const uint32_t b[2]) {
    asm volatile(
        "mma.sync.aligned.m16n8k8.row.col.f32.tf32.tf32.f32 "
        "{%0,%1,%2,%3}, {%4,%5,%6,%7}, {%8,%9}, {%0,%1,%2,%3};"
        : "+f"(c[0]), "+f"(c[1]), "+f"(c[2]), "+f"(c[3])
        : "r"(a[0]), "r"(a[1]), "r"(a[2]), "r"(a[3]), "r"(b[0]), "r"(b[1]));
}

// ================= dense tf32 GEMM: C[M,Nn] = A[M,K] @ Bt[Nn,K]^T =================
// 128x128 tile, BK=32, 256 thr (8 warps: 2m x 4n), cp.async double-buffered.
// EPI 0: C = AB ; EPI 1: C = res + AB + bias ; EPI 2: C = gelu(AB + bias)
#define GS_BUF   9216u     // floats per buffer (A 128x36 + B 128x36)
#define GS_BYTES (2u * GS_BUF * 4u)   // 73728 B dynamic smem
template <int EPI>
__global__ void __launch_bounds__(256) mma_gemm(
    const float* __restrict__ A, const float* __restrict__ Bt,
    const float* __restrict__ bias, const float* __restrict__ res,
    float* __restrict__ C, int M, int Nn, int K) {
    extern __shared__ float sm[];
    const int tid = threadIdx.x;
    const int wid = tid >> 5, lane = tid & 31;
    const int g = lane >> 2, tg = lane & 3;
    const int wm = (wid & 1) * 64, wn = (wid >> 1) * 32;
    const int m0 = blockIdx.y * 128, n0 = blockIdx.x * 128;

    float c[4][4][4];
    #pragma unroll
    for (int mt = 0; mt < 4; ++mt)
        #pragma unroll
        for (int nt = 0; nt < 4; ++nt)
            #pragma unroll
            for (int k = 0; k < 4; ++k) c[mt][nt][k] = 0.0f;

    const int nc = K >> 5;

    // prologue: load chunk 0 into buf 0
    {
        uint32_t base = smem_u32(sm);
        #pragma unroll
        for (int i = 0; i < 4; ++i) {
            int f = tid + i * 256;
            int r = f >> 3, c4 = (f & 7) << 2;
            cp16(base + (uint32_t)(r * 36 + c4) * 4u,
                 A + (size_t)(m0 + r) * K + c4);
            cp16(base + (4608u + (uint32_t)(r * 36 + c4)) * 4u,
                 Bt + (size_t)(n0 + r) * K + c4);
        }
        asm volatile("cp.async.commit_group;" ::: "memory");
    }

    for (int ci = 0; ci < nc; ++ci) {
        if (ci + 1 < nc) {
            uint32_t base = smem_u32(sm) + ((ci + 1) & 1) * GS_BUF * 4u;
            int kt = (ci + 1) << 5;
            #pragma unroll
            for (int i = 0; i < 4; ++i) {
                int f = tid + i * 256;
                int r = f >> 3, c4 = (f & 7) << 2;
                cp16(base + (uint32_t)(r * 36 + c4) * 4u,
                     A + (size_t)(m0 + r) * K + kt + c4);
                cp16(base + (4608u + (uint32_t)(r * 36 + c4)) * 4u,
                     Bt + (size_t)(n0 + r) * K + kt + c4);
            }
            asm volatile("cp.async.commit_group;" ::: "memory");
            asm volatile("cp.async.wait_group 1;" ::: "memory");
        } else {
            asm volatile("cp.async.wait_group 0;" ::: "memory");
        }
        __syncthreads();

        const float* sA = sm + (ci & 1) * GS_BUF;
        const float* sB = sA + 4608;
        #pragma unroll
        for (int ks = 0; ks < 4; ++ks) {
            const int kb = ks * 8;
            uint32_t af[4][4], bf[4][2];
            #pragma unroll
            for (int mt = 0; mt < 4; ++mt) {
                int r = wm + mt * 16 + g;
                af[mt][0] = f2tf(sA[r * 36 + kb + tg]);
                af[mt][1] = f2tf(sA[(r + 8) * 36 + kb + tg]);
                af[mt][2] = f2tf(sA[r * 36 + kb + tg + 4]);
                af[mt][3] = f2tf(sA[(r + 8) * 36 + kb + tg + 4]);
            }
            #pragma unroll
            for (int nt = 0; nt < 4; ++nt) {
                int r = wn + nt * 8 + g;
                bf[nt][0] = f2tf(sB[r * 36 + kb + tg]);
                bf[nt][1] = f2tf(sB[r * 36 + kb + tg + 4]);
            }
            #pragma unroll
            for (int mt = 0; mt < 4; ++mt)
                #pragma unroll
                for (int nt = 0; nt < 4; ++nt)
                    mma8(c[mt][nt], af[mt], bf[nt]);
        }
        __syncthreads();
    }

    // epilogue: fragment regs -> global (float2 per row-half)
    #pragma unroll
    for (int mt = 0; mt < 4; ++mt) {
        #pragma unroll
        for (int nt = 0; nt < 4; ++nt) {
            int col = n0 + wn + nt * 8 + 2 * tg;
            #pragma unroll
            for (int h = 0; h < 2; ++h) {
                int row = m0 + wm + mt * 16 + g + h * 8;
                float v0 = c[mt][nt][h * 2 + 0];
                float v1 = c[mt][nt][h * 2 + 1];
                if (EPI >= 1) { v0 += bias[col]; v1 += bias[col + 1]; }
                if (EPI == 1) {
                    float2 r2 = *(const float2*)(res + (size_t)row * Nn + col);
                    v0 += r2.x; v1 += r2.y;
                }
                if (EPI == 2) {
                    v0 = 0.5f * v0 * (1.0f + erff(v0 * 0.70710678118654752f));
                    v1 = 0.5f * v1 * (1.0f + erff(v1 * 0.70710678118654752f));
                }
                float2 o; o.x = v0; o.y = v1;
                *(float2*)(C + (size_t)row * Nn + col) = o;
            }
        }
    }
}

// ================= attention scores via tf32 mma =================
// block 128 thr (4 warps, warp = 16-row strip), 64x64 out tile, K=DH=64.
__global__ void __launch_bounds__(128) dots_mma(
    const float* __restrict__ qkv, float* __restrict__ dots,
    const float* __restrict__ temp, int layer) {
    __shared__ float Qs[64 * 68];
    __shared__ float Ks[64 * 68];
    int bh = blockIdx.z;
    int b = bh / HEADS, h = bh - b * HEADS;
    int rt = blockIdx.y * 64, ct = blockIdx.x * 64;
    int tid = threadIdx.x;
    int wid = tid >> 5, lane = tid & 31;
    int g = lane >> 2, tg = lane & 3;

    const float* qb = qkv + (size_t)b * NN * QKVW + h * DH;
    const float* kb = qb + INNER;

    #pragma unroll
    for (int i = 0; i < 8; ++i) {
        int f = tid + i * 128;
        int r = f >> 4, c4 = (f & 15) << 2;
        *(float4*)&Qs[r * 68 + c4] = *(const float4*)(qb + (size_t)(rt + r) * QKVW + c4);
        *(float4*)&Ks[r * 68 + c4] = *(const float4*)(kb + (size_t)(ct + r) * QKVW + c4);
    }
    __syncthreads();

    float c[8][4];
    #pragma unroll
    for (int nt = 0; nt < 8; ++nt)
        #pragma unroll
        for (int k = 0; k < 4; ++k) c[nt][k] = 0.0f;

    #pragma unroll
    for (int ks = 0; ks < 8; ++ks) {
        int kb2 = ks * 8;
        int r = wid * 16 + g;
        uint32_t af[4];
        af[0] = f2tf(Qs[r * 68 + kb2 + tg]);
        af[1] = f2tf(Qs[(r + 8) * 68 + kb2 + tg]);
        af[2] = f2tf(Qs[r * 68 + kb2 + tg + 4]);
        af[3] = f2tf(Qs[(r + 8) * 68 + kb2 + tg + 4]);
        #pragma unroll
        for (int nt = 0; nt < 8; ++nt) {
            int rn = nt * 8 + g;
            uint32_t bf[2];
            bf[0] = f2tf(Ks[rn * 68 + kb2 + tg]);
            bf[1] = f2tf(Ks[rn * 68 + kb2 + tg + 4]);
            mma8(c[nt], af, bf);
        }
    }

    float scale = expf(temp[layer]);
    float* out = dots + (size_t)bh * NN * NN;
    #pragma unroll
    for (int nt = 0; nt < 8; ++nt) {
        int gj = ct + nt * 8 + 2 * tg;
        #pragma unroll
        for (int hh = 0; hh < 2; ++hh) {
            int gi = rt + wid * 16 + g + hh * 8;
            float v0 = c[nt][hh * 2 + 0] * scale;
            float v1 = c[nt][hh * 2 + 1] * scale;
            if (gi == gj)     v0 = NEGMAX;
            if (gi == gj + 1) v1 = NEGMAX;
            float2 o; o.x = v0; o.y = v1;
            *(float2*)(out + (size_t)gi * NN + gj) = o;
        }
    }
}

// ================= o = attn @ v via tf32 mma =================
// block 128 thr (4 warps), out tile 64 rows x 64 dh, K=1024 in 64-chunks.
__global__ void __launch_bounds__(128) av_mma(
    const float* __restrict__ dots, const float* __restrict__ qkv,
    float* __restrict__ o) {
    __shared__ float As[64 * 68];
    __shared__ float Vt[64 * 68];   // transposed: [dh][token]
    int bh = blockIdx.y;
    int b = bh / HEADS, h = bh - b * HEADS;
    int rt = blockIdx.x * 64;
    int tid = threadIdx.x;
    int wid = tid >> 5, lane = tid & 31;
    int g = lane >> 2, tg = lane & 3;

    const float* vb = qkv + (size_t)b * NN * QKVW + 2 * INNER + h * DH;
    const float* dp = dots + (size_t)bh * NN * NN;

    float c[8][4];
    #pragma unroll
    for (int nt = 0; nt < 8; ++nt)
        #pragma unroll
        for (int k = 0; k < 4; ++k) c[nt][k] = 0.0f;

    for (int kt = 0; kt < NN; kt += 64) {
        #pragma unroll
        for (int i = 0; i < 8; ++i) {
            int f = tid + i * 128;
            int r = f >> 4, c4 = (f & 15) << 2;
            *(float4*)&As[r * 68 + c4] = *(const float4*)(dp + (size_t)(rt + r) * NN + kt + c4);
            float4 v4 = *(const float4*)(vb + (size_t)(kt + r) * QKVW + c4);
            Vt[(c4 + 0) * 68 + r] = v4.x;
            Vt[(c4 + 1) * 68 + r] = v4.y;
            Vt[(c4 + 2) * 68 + r] = v4.z;
            Vt[(c4 + 3) * 68 + r] = v4.w;
        }
        __syncthreads();
        #pragma unroll
        for (int ks = 0; ks < 8; ++ks) {
            int kb2 = ks * 8;
            int r = wid * 16 + g;
            uint32_t af[4];
            af[0] = f2tf(As[r * 68 + kb2 + tg]);
            af[1] = f2tf(As[(r + 8) * 68 + kb2 + tg]);
            af[2] = f2tf(As[r * 68 + kb2 + tg + 4]);
            af[3] = f2tf(As[(r + 8) * 68 + kb2 + tg + 4]);
            #pragma unroll
            for (int nt = 0; nt < 8; ++nt) {
                int rn = nt * 8 + g;
                uint32_t bf[2];
                bf[0] = f2tf(Vt[rn * 68 + kb2 + tg]);
                bf[1] = f2tf(Vt[rn * 68 + kb2 + tg + 4]);
                mma8(c[nt], af, bf);
            }
        }
        __syncthreads();
    }

    #pragma unroll
    for (int nt = 0; nt < 8; ++nt) {
        int gc = h * DH + nt * 8 + 2 * tg;
        #pragma unroll
        for (int hh = 0; hh < 2; ++hh) {
            int gr = b * NN + rt + wid * 16 + g + hh * 8;
            float2 ov; ov.x = c[nt][hh * 2 + 0]; ov.y = c[nt][hh * 2 + 1];
            *(float2*)(o + (size_t)gr * INNER + gc) = ov;
        }
    }
}

// ---------------- weight transpose: dst[n][k] = src[k][n], per layer in grid.z ------
__global__ void transpose_kernel(const float* __restrict__ src, float* __restrict__ dst,
                                 int K, int N) {
    __shared__ float t[32][33];
    int z = blockIdx.z;
    src += (size_t)z * K * N;
    dst += (size_t)z * K * N;
    int k0 = blockIdx.y * 32, n0 = blockIdx.x * 32;
    int tx = threadIdx.x, ty = threadIdx.y;   // 32 x 8
    #pragma unroll
    for (int j = 0; j < 32; j += 8)
        t[ty + j][tx] = src[(size_t)(k0 + ty + j) * N + n0 + tx];
    __syncthreads();
    #pragma unroll
    for (int j = 0; j < 32; j += 8)
        dst[(size_t)(n0 + ty + j) * K + k0 + tx] = t[tx][ty + j];
}

// ---------------- LayerNorm ----------------
__global__ void ln_kernel(const float* __restrict__ x,
                          const float* __restrict__ gamma,
                          const float* __restrict__ beta,
                          float* __restrict__ y) {
    int row = blockIdx.x;
    const float* xr = x + (size_t)row * DIMV;
    float*       yr = y + (size_t)row * DIMV;
    int t = threadIdx.x;
    float v0 = xr[t], v1 = xr[t + 128], v2 = xr[t + 256];
    float s = v0 + v1 + v2;
    float q = v0 * v0 + v1 * v1 + v2 * v2;
    #pragma unroll
    for (int o = 16; o > 0; o >>= 1) {
        s += __shfl_down_sync(0xffffffffu, s, o);
        q += __shfl_down_sync(0xffffffffu, q, o);
    }
    __shared__ float shs[4], shq[4];
    __shared__ float s_mean, s_inv;
    int w = t >> 5, lane = t & 31;
    if (lane == 0) { shs[w] = s; shq[w] = q; }
    __syncthreads();
    if (t == 0) {
        float S = shs[0] + shs[1] + shs[2] + shs[3];
        float Q = shq[0] + shq[1] + shq[2] + shq[3];
        float m = S * (1.0f / 384.0f);
        float var = Q * (1.0f / 384.0f) - m * m;
        s_mean = m;
        s_inv  = rsqrtf(var + 1e-5f);
    }
    __syncthreads();
    float m = s_mean, inv = s_inv;
    yr[t]       = (v0 - m) * inv * gamma[t]       + beta[t];
    yr[t + 128] = (v1 - m) * inv * gamma[t + 128] + beta[t + 128];
    yr[t + 256] = (v2 - m) * inv * gamma[t + 256] + beta[t + 256];
}

// ---------------- Row softmax ----------------
__global__ void softmax_kernel(float* __restrict__ dots) {
    float* p = dots + ((size_t)blockIdx.y * NN + blockIdx.x) * NN;
    int t = threadIdx.x;
    float v0 = p[t], v1 = p[t + 256], v2 = p[t + 512], v3 = p[t + 768];
    float m = fmaxf(fmaxf(v0, v1), fmaxf(v2, v3));
    #pragma unroll
    for (int o = 16; o > 0; o >>= 1) m = fmaxf(m, __shfl_xor_sync(0xffffffffu, m, o));
    __shared__ float sh[8];
    __shared__ float s_m, s_s;
    int w = t >> 5, lane = t & 31;
    if (lane == 0) sh[w] = m;
    __syncthreads();
    if (t == 0) {
        float mm = sh[0];
        #pragma unroll
        for (int i = 1; i < 8; i++) mm = fmaxf(mm, sh[i]);
        s_m = mm;
    }
    __syncthreads();
    m = s_m;
    float e0 = expf(v0 - m), e1 = expf(v1 - m), e2 = expf(v2 - m), e3 = expf(v3 - m);
    float s = e0 + e1 + e2 + e3;
    #pragma unroll
    for (int o = 16; o > 0; o >>= 1) s += __shfl_xor_sync(0xffffffffu, s, o);
    if (lane == 0) sh[w] = s;
    __syncthreads();
    if (t == 0) {
        float ss = sh[0];
        #pragma unroll
        for (int i = 1; i < 8; i++) ss += sh[i];
        s_s = ss;
    }
    __syncthreads();
    float inv = 1.0f / s_s;
    p[t] = e0 * inv; p[t + 256] = e1 * inv; p[t + 512] = e2 * inv; p[t + 768] = e3 * inv;
}

// ---------------- driver ----------------
extern "C" void kernel_launch(void* const* d_in, const int* in_sizes, int n_in,
                              void* d_out, int out_size) {
    const float* x_in  = (const float*)d_in[0];
    const float* ln1_g = (const float*)d_in[1];
    const float* ln1_b = (const float*)d_in[2];
    const float* qkv_w = (const float*)d_in[3];
    const float* temp  = (const float*)d_in[4];
    const float* out_w = (const float*)d_in[5];
    const float* out_b = (const float*)d_in[6];
    const float* ln2_g = (const float*)d_in[7];
    const float* ln2_b = (const float*)d_in[8];
    const float* ff_w1 = (const float*)d_in[9];
    const float* ff_b1 = (const float*)d_in[10];
    const float* ff_w2 = (const float*)d_in[11];
    const float* ff_b2 = (const float*)d_in[12];
    float* x = (float*)d_out;

    float *p_ln, *p_qkv, *p_dots, *p_attn, *p_ff, *p_wt;
    cudaGetSymbolAddress((void**)&p_ln,   g_ln);
    cudaGetSymbolAddress((void**)&p_qkv,  g_qkv);
    cudaGetSymbolAddress((void**)&p_dots, g_dots);
    cudaGetSymbolAddress((void**)&p_attn, g_attn);
    cudaGetSymbolAddress((void**)&p_ff,   g_ff);
    cudaGetSymbolAddress((void**)&p_wt,   g_wt);

    cudaFuncSetAttribute(mma_gemm<0>, cudaFuncAttributeMaxDynamicSharedMemorySize, GS_BYTES);
    cudaFuncSetAttribute(mma_gemm<1>, cudaFuncAttributeMaxDynamicSharedMemorySize, GS_BYTES);
    cudaFuncSetAttribute(mma_gemm<2>, cudaFuncAttributeMaxDynamicSharedMemorySize, GS_BYTES);

    cudaMemcpyAsync(x, x_in, (size_t)ROWS * DIMV * sizeof(float),
                    cudaMemcpyDeviceToDevice);

    // pre-transpose all weights to K-major [N,K] (per layer)
    transpose_kernel<<<dim3(QKVW / 32, DIMV / 32, DEPTH), dim3(32, 8)>>>(
        qkv_w, p_wt + WT_QKV_OFF, DIMV, QKVW);
    transpose_kernel<<<dim3(DIMV / 32, INNER / 32, DEPTH), dim3(32, 8)>>>(
        out_w, p_wt + WT_WO_OFF, INNER, DIMV);
    transpose_kernel<<<dim3(MLPV / 32, DIMV / 32, DEPTH), dim3(32, 8)>>>(
        ff_w1, p_wt + WT_W1_OFF, DIMV, MLPV);
    transpose_kernel<<<dim3(DIMV / 32, MLPV / 32, DEPTH), dim3(32, 8)>>>(
        ff_w2, p_wt + WT_W2_OFF, MLPV, DIMV);

    for (int l = 0; l < DEPTH; l++) {
        // --- attention block ---
        ln_kernel<<<ROWS, 128>>>(x, ln1_g + l * DIMV, ln1_b + l * DIMV, p_ln);
        mma_gemm<0><<<dim3(QKVW / 128, ROWS / 128), 256, GS_BYTES>>>(
            p_ln, p_wt + WT_QKV_OFF + (size_t)l * WT_QKV_PER,
            nullptr, nullptr, p_qkv, ROWS, QKVW, DIMV);
        dots_mma<<<dim3(NN / 64, NN / 64, BHN), 128>>>(p_qkv, p_dots, temp, l);
        softmax_kernel<<<dim3(NN, BHN), 256>>>(p_dots);
        av_mma<<<dim3(NN / 64, BHN), 128>>>(p_dots, p_qkv, p_attn);
        mma_gemm<1><<<dim3(DIMV / 128, ROWS / 128), 256, GS_BYTES>>>(
            p_attn, p_wt + WT_WO_OFF + (size_t)l * WT_WO_PER,
            out_b + l * DIMV, x, x, ROWS, DIMV, INNER);
        // --- feed-forward block ---
        ln_kernel<<<ROWS, 128>>>(x, ln2_g + l * DIMV, ln2_b + l * DIMV, p_ln);
        mma_gemm<2><<<dim3(MLPV / 128, ROWS / 128), 256, GS_BYTES>>>(
            p_ln, p_wt + WT_W1_OFF + (size_t)l * WT_W1_PER,
            ff_b1 + l * MLPV, nullptr, p_ff, ROWS, MLPV, DIMV);
        mma_gemm<1><<<dim3(DIMV / 128, ROWS / 128), 256, GS_BYTES>>>(
            p_ff, p_wt + WT_W2_OFF + (size_t)l * WT_W2_PER,
            ff_b2 + l * DIMV, x, x, ROWS, DIMV, MLPV);
    }
}

// round 4
// speedup vs baseline: 3.2913x; 1.2469x over previous
#include <cuda_runtime.h>
#include <math.h>
#include <stdint.h>

#define BB     16
#define NN     1024
#define DIMV   384
#define DEPTH  6
#define HEADS  6
#define DH     64
#define INNER  384
#define MLPV   1536
#define ROWS   (BB*NN)       // 16384
#define BHN    (BB*HEADS)    // 96
#define QKVW   (3*INNER)     // 1152
#define NEGMAX -3.4028234663852886e38f

// ---------------- scratch ----------------
__device__ float g_ln[(size_t)ROWS * DIMV];
__device__ float g_qkv[(size_t)ROWS * QKVW];
__device__ float g_attn[(size_t)ROWS * INNER];
__device__ float g_ff[(size_t)ROWS * MLPV];
#define WT_QKV_OFF  0
#define WT_QKV_PER  (QKVW*DIMV)
#define WT_WO_OFF   (WT_QKV_OFF + DEPTH*WT_QKV_PER)
#define WT_WO_PER   (DIMV*INNER)
#define WT_W1_OFF   (WT_WO_OFF + DEPTH*WT_WO_PER)
#define WT_W1_PER   (MLPV*DIMV)
#define WT_W2_OFF   (WT_W1_OFF + DEPTH*WT_W1_PER)
#define WT_W2_PER   (DIMV*MLPV)
__device__ float g_wt[(size_t)(WT_W2_OFF + DEPTH*WT_W2_PER)];

// ================= helpers =================
__device__ __forceinline__ uint32_t smem_u32(const void* p) {
    uint32_t r;
    asm("{ .reg .u64 t; cvta.to.shared.u64 t, %1; cvt.u32.u64 %0, t; }" : "=r"(r) : "l"(p));
    return r;
}
__device__ __forceinline__ float rndtf(float x) {      // round-to-nearest tf32, as float
    uint32_t r;
    asm("cvt.rna.tf32.f32 %0, %1;" : "=r"(r) : "f"(x));
    return __uint_as_float(r);
}
__device__ __forceinline__ void cp16(uint32_t dst, const void* src) {
    asm volatile("cp.async.cg.shared.global [%0], [%1], 16;" :: "r"(dst), "l"(src));
}
__device__ __forceinline__ void mma8(float c[4], const uint32_t a[4], const uint32_t b[2]) {
    asm volatile(
        "mma.sync.aligned.m16n8k8.row.col.f32.tf32.tf32.f32 "
        "{%0,%1,%2,%3}, {%4,%5,%6,%7}, {%8,%9}, {%0,%1,%2,%3};"
        : "+f"(c[0]), "+f"(c[1]), "+f"(c[2]), "+f"(c[3])
        : "r"(a[0]), "r"(a[1]), "r"(a[2]), "r"(a[3]), "r"(b[0]), "r"(b[1]));
}

// ================= dense tf32 GEMM: C[M,Nn] = A[M,K] @ Bt[Nn,K]^T =================
// Inputs A and Bt are PRE-ROUNDED to tf32 values. No cvt in the inner loop.
// 128x128 tile, BK=32, 256 thr (8 warps: 2m x 4n), cp.async double-buffered.
// EPI 0: C = rnd(AB)  ; EPI 1: C = res + AB + bias ; EPI 2: C = rnd(gelu(AB + bias))
#define GS_BUF   9216u
#define GS_BYTES (2u * GS_BUF * 4u)
template <int EPI>
__global__ void __launch_bounds__(256) mma_gemm(
    const float* __restrict__ A, const float* __restrict__ Bt,
    const float* __restrict__ bias, const float* __restrict__ res,
    float* __restrict__ C, int M, int Nn, int K) {
    extern __shared__ float sm[];
    const int tid = threadIdx.x;
    const int wid = tid >> 5, lane = tid & 31;
    const int g = lane >> 2, tg = lane & 3;
    const int wm = (wid & 1) * 64, wn = (wid >> 1) * 32;
    const int m0 = blockIdx.y * 128, n0 = blockIdx.x * 128;

    float c[4][4][4];
    #pragma unroll
    for (int mt = 0; mt < 4; ++mt)
        #pragma unroll
        for (int nt = 0; nt < 4; ++nt)
            #pragma unroll
            for (int k = 0; k < 4; ++k) c[mt][nt][k] = 0.0f;

    const int nc = K >> 5;
    {
        uint32_t base = smem_u32(sm);
        #pragma unroll
        for (int i = 0; i < 4; ++i) {
            int f = tid + i * 256;
            int r = f >> 3, c4 = (f & 7) << 2;
            cp16(base + (uint32_t)(r * 36 + c4) * 4u, A + (size_t)(m0 + r) * K + c4);
            cp16(base + (4608u + (uint32_t)(r * 36 + c4)) * 4u, Bt + (size_t)(n0 + r) * K + c4);
        }
        asm volatile("cp.async.commit_group;" ::: "memory");
    }

    for (int ci = 0; ci < nc; ++ci) {
        if (ci + 1 < nc) {
            uint32_t base = smem_u32(sm) + ((ci + 1) & 1) * GS_BUF * 4u;
            int kt = (ci + 1) << 5;
            #pragma unroll
            for (int i = 0; i < 4; ++i) {
                int f = tid + i * 256;
                int r = f >> 3, c4 = (f & 7) << 2;
                cp16(base + (uint32_t)(r * 36 + c4) * 4u, A + (size_t)(m0 + r) * K + kt + c4);
                cp16(base + (4608u + (uint32_t)(r * 36 + c4)) * 4u, Bt + (size_t)(n0 + r) * K + kt + c4);
            }
            asm volatile("cp.async.commit_group;" ::: "memory");
            asm volatile("cp.async.wait_group 1;" ::: "memory");
        } else {
            asm volatile("cp.async.wait_group 0;" ::: "memory");
        }
        __syncthreads();

        const uint32_t* sA = (const uint32_t*)(sm + (ci & 1) * GS_BUF);
        const uint32_t* sB = sA + 4608;
        #pragma unroll
        for (int ks = 0; ks < 4; ++ks) {
            const int kb = ks * 8;
            uint32_t af[4][4], bf[4][2];
            #pragma unroll
            for (int mt = 0; mt < 4; ++mt) {
                int r = wm + mt * 16 + g;
                af[mt][0] = sA[r * 36 + kb + tg];
                af[mt][1] = sA[(r + 8) * 36 + kb + tg];
                af[mt][2] = sA[r * 36 + kb + tg + 4];
                af[mt][3] = sA[(r + 8) * 36 + kb + tg + 4];
            }
            #pragma unroll
            for (int nt = 0; nt < 4; ++nt) {
                int r = wn + nt * 8 + g;
                bf[nt][0] = sB[r * 36 + kb + tg];
                bf[nt][1] = sB[r * 36 + kb + tg + 4];
            }
            #pragma unroll
            for (int mt = 0; mt < 4; ++mt)
                #pragma unroll
                for (int nt = 0; nt < 4; ++nt)
                    mma8(c[mt][nt], af[mt], bf[nt]);
        }
        __syncthreads();
    }

    #pragma unroll
    for (int mt = 0; mt < 4; ++mt) {
        #pragma unroll
        for (int nt = 0; nt < 4; ++nt) {
            int col = n0 + wn + nt * 8 + 2 * tg;
            #pragma unroll
            for (int h = 0; h < 2; ++h) {
                int row = m0 + wm + mt * 16 + g + h * 8;
                float v0 = c[mt][nt][h * 2 + 0];
                float v1 = c[mt][nt][h * 2 + 1];
                if (EPI >= 1) { v0 += bias[col]; v1 += bias[col + 1]; }
                if (EPI == 1) {
                    float2 r2 = *(const float2*)(res + (size_t)row * Nn + col);
                    v0 += r2.x; v1 += r2.y;
                }
                if (EPI == 2) {
                    v0 = 0.5f * v0 * (1.0f + erff(v0 * 0.70710678118654752f));
                    v1 = 0.5f * v1 * (1.0f + erff(v1 * 0.70710678118654752f));
                }
                if (EPI != 1) { v0 = rndtf(v0); v1 = rndtf(v1); }
                float2 o; o.x = v0; o.y = v1;
                *(float2*)(C + (size_t)row * Nn + col) = o;
            }
        }
    }
}

// ================= flash attention =================
// grid (NN/128, BHN), 256 thr (8 warps). Q tile 128x64 in registers (A-frags),
// loop 16 KV tiles of 64. Online softmax on fragments; P goes through a
// per-warp-private smem strip (no cross-warp dependency -> __syncwarp only).
#define FL_DSMEM ((128*68 + 64*68 + 64*68) * 4)   // 69632 B
__global__ void __launch_bounds__(256, 2) flash_kernel(
    const float* __restrict__ qkv,   // pre-rounded tf32 values
    float* __restrict__ o,           // [ROWS, INNER], written rounded
    const float* __restrict__ temp, int layer) {
    extern __shared__ float fs[];
    float* Ps = fs;                  // 128x68 (Q staging first, then P)
    float* Ks = fs + 128 * 68;       // 64x68
    float* Vt = Ks + 64 * 68;        // 64x68 transposed [dh][token]

    int bh = blockIdx.y;
    int b = bh / HEADS, h = bh - b * HEADS;
    int rt = blockIdx.x * 128;
    int tid = threadIdx.x, wid = tid >> 5, lane = tid & 31;
    int g = lane >> 2, tg = lane & 3;

    const float* qb = qkv + (size_t)b * NN * QKVW + h * DH;
    const float* kb = qb + INNER;
    const float* vb = qb + 2 * INNER;

    // stage Q tile, build A-fragments, keep in registers
    #pragma unroll
    for (int i = 0; i < 8; ++i) {
        int f = tid + i * 256;
        int r = f >> 4, c4 = (f & 15) << 2;
        *(float4*)&Ps[r * 68 + c4] = *(const float4*)(qb + (size_t)(rt + r) * QKVW + c4);
    }
    __syncthreads();
    uint32_t qf[8][4];
    {
        int r = wid * 16 + g;
        #pragma unroll
        for (int ks = 0; ks < 8; ++ks) {
            int kb2 = ks * 8;
            qf[ks][0] = __float_as_uint(Ps[r * 68 + kb2 + tg]);
            qf[ks][1] = __float_as_uint(Ps[(r + 8) * 68 + kb2 + tg]);
            qf[ks][2] = __float_as_uint(Ps[r * 68 + kb2 + tg + 4]);
            qf[ks][3] = __float_as_uint(Ps[(r + 8) * 68 + kb2 + tg + 4]);
        }
    }

    float scale = expf(temp[layer]);
    float m0 = NEGMAX, m1 = NEGMAX, l0 = 0.0f, l1 = 0.0f;
    float oacc[8][4];
    #pragma unroll
    for (int nt = 0; nt < 8; ++nt)
        #pragma unroll
        for (int k = 0; k < 4; ++k) oacc[nt][k] = 0.0f;

    const int gi0 = rt + wid * 16 + g;
    const int gi1 = gi0 + 8;
    const int prow = wid * 16 + g;

    for (int kt = 0; kt < NN; kt += 64) {
        __syncthreads();             // all warps done with Ks/Vt of prev iter
        #pragma unroll
        for (int i = 0; i < 4; ++i) {
            int f = tid + i * 256;
            int r = f >> 4, c4 = (f & 15) << 2;
            *(float4*)&Ks[r * 68 + c4] = *(const float4*)(kb + (size_t)(kt + r) * QKVW + c4);
            float4 v4 = *(const float4*)(vb + (size_t)(kt + r) * QKVW + c4);
            Vt[(c4 + 0) * 68 + r] = v4.x;
            Vt[(c4 + 1) * 68 + r] = v4.y;
            Vt[(c4 + 2) * 68 + r] = v4.z;
            Vt[(c4 + 3) * 68 + r] = v4.w;
        }
        __syncthreads();

        // S = Q K^T  (16x64 per warp)
        float s[8][4];
        #pragma unroll
        for (int nt = 0; nt < 8; ++nt)
            #pragma unroll
            for (int k = 0; k < 4; ++k) s[nt][k] = 0.0f;
        #pragma unroll
        for (int ks = 0; ks < 8; ++ks) {
            int kb2 = ks * 8;
            #pragma unroll
            for (int nt = 0; nt < 8; ++nt) {
                int rn = nt * 8 + g;
                uint32_t bf[2];
                bf[0] = __float_as_uint(Ks[rn * 68 + kb2 + tg]);
                bf[1] = __float_as_uint(Ks[rn * 68 + kb2 + tg + 4]);
                mma8(s[nt], qf[ks], bf);
            }
        }
        // scale + LSA diagonal mask
        #pragma unroll
        for (int nt = 0; nt < 8; ++nt) {
            int gj = kt + nt * 8 + 2 * tg;
            s[nt][0] *= scale; s[nt][1] *= scale; s[nt][2] *= scale; s[nt][3] *= scale;
            if (gi0 == gj)     s[nt][0] = NEGMAX;
            if (gi0 == gj + 1) s[nt][1] = NEGMAX;
            if (gi1 == gj)     s[nt][2] = NEGMAX;
            if (gi1 == gj + 1) s[nt][3] = NEGMAX;
        }
        // row max (across nt regs, then across tg lanes)
        float mx0 = NEGMAX, mx1 = NEGMAX;
        #pragma unroll
        for (int nt = 0; nt < 8; ++nt) {
            mx0 = fmaxf(mx0, fmaxf(s[nt][0], s[nt][1]));
            mx1 = fmaxf(mx1, fmaxf(s[nt][2], s[nt][3]));
        }
        mx0 = fmaxf(mx0, __shfl_xor_sync(0xffffffffu, mx0, 1));
        mx0 = fmaxf(mx0, __shfl_xor_sync(0xffffffffu, mx0, 2));
        mx1 = fmaxf(mx1, __shfl_xor_sync(0xffffffffu, mx1, 1));
        mx1 = fmaxf(mx1, __shfl_xor_sync(0xffffffffu, mx1, 2));
        float mn0 = fmaxf(m0, mx0), mn1 = fmaxf(m1, mx1);
        float r0 = __expf(m0 - mn0), r1 = __expf(m1 - mn1);
        // P = exp(S - m), write to own smem strip (rounded), accumulate row sums
        float sum0 = 0.0f, sum1 = 0.0f;
        #pragma unroll
        for (int nt = 0; nt < 8; ++nt) {
            float p0 = __expf(s[nt][0] - mn0);
            float p1 = __expf(s[nt][1] - mn0);
            float p2 = __expf(s[nt][2] - mn1);
            float p3 = __expf(s[nt][3] - mn1);
            sum0 += p0 + p1;
            sum1 += p2 + p3;
            int col = nt * 8 + 2 * tg;
            float2 w0; w0.x = rndtf(p0); w0.y = rndtf(p1);
            float2 w1; w1.x = rndtf(p2); w1.y = rndtf(p3);
            *(float2*)&Ps[prow * 68 + col] = w0;
            *(float2*)&Ps[(prow + 8) * 68 + col] = w1;
        }
        sum0 += __shfl_xor_sync(0xffffffffu, sum0, 1);
        sum0 += __shfl_xor_sync(0xffffffffu, sum0, 2);
        sum1 += __shfl_xor_sync(0xffffffffu, sum1, 1);
        sum1 += __shfl_xor_sync(0xffffffffu, sum1, 2);
        l0 = l0 * r0 + sum0;
        l1 = l1 * r1 + sum1;
        m0 = mn0; m1 = mn1;
        // rescale O accumulators
        #pragma unroll
        for (int nt = 0; nt < 8; ++nt) {
            oacc[nt][0] *= r0; oacc[nt][1] *= r0;
            oacc[nt][2] *= r1; oacc[nt][3] *= r1;
        }
        __syncwarp();                // P strip visible within warp
        // O += P @ V
        #pragma unroll
        for (int ks = 0; ks < 8; ++ks) {
            int kb2 = ks * 8;
            uint32_t af[4];
            af[0] = __float_as_uint(Ps[prow * 68 + kb2 + tg]);
            af[1] = __float_as_uint(Ps[(prow + 8) * 68 + kb2 + tg]);
            af[2] = __float_as_uint(Ps[prow * 68 + kb2 + tg + 4]);
            af[3] = __float_as_uint(Ps[(prow + 8) * 68 + kb2 + tg + 4]);
            #pragma unroll
            for (int nt = 0; nt < 8; ++nt) {
                int rn = nt * 8 + g;
                uint32_t bf[2];
                bf[0] = __float_as_uint(Vt[rn * 68 + kb2 + tg]);
                bf[1] = __float_as_uint(Vt[rn * 68 + kb2 + tg + 4]);
                mma8(oacc[nt], af, bf);
            }
        }
    }

    float inv0 = 1.0f / l0, inv1 = 1.0f / l1;
    #pragma unroll
    for (int nt = 0; nt < 8; ++nt) {
        int gc = h * DH + nt * 8 + 2 * tg;
        int gr0 = b * NN + gi0;
        int gr1 = b * NN + gi1;
        float2 o0; o0.x = rndtf(oacc[nt][0] * inv0); o0.y = rndtf(oacc[nt][1] * inv0);
        float2 o1; o1.x = rndtf(oacc[nt][2] * inv1); o1.y = rndtf(oacc[nt][3] * inv1);
        *(float2*)(o + (size_t)gr0 * INNER + gc) = o0;
        *(float2*)(o + (size_t)gr1 * INNER + gc) = o1;
    }
}

// ---------------- weight transpose (+ tf32 rounding) ----------------
__global__ void transpose_kernel(const float* __restrict__ src, float* __restrict__ dst,
                                 int K, int N) {
    __shared__ float t[32][33];
    int z = blockIdx.z;
    src += (size_t)z * K * N;
    dst += (size_t)z * K * N;
    int k0 = blockIdx.y * 32, n0 = blockIdx.x * 32;
    int tx = threadIdx.x, ty = threadIdx.y;
    #pragma unroll
    for (int j = 0; j < 32; j += 8)
        t[ty + j][tx] = src[(size_t)(k0 + ty + j) * N + n0 + tx];
    __syncthreads();
    #pragma unroll
    for (int j = 0; j < 32; j += 8)
        dst[(size_t)(n0 + ty + j) * K + k0 + tx] = rndtf(t[tx][ty + j]);
}

// ---------------- LayerNorm (+ tf32 rounding of output) ----------------
__global__ void ln_kernel(const float* __restrict__ x,
                          const float* __restrict__ gamma,
                          const float* __restrict__ beta,
                          float* __restrict__ y) {
    int row = blockIdx.x;
    const float* xr = x + (size_t)row * DIMV;
    float*       yr = y + (size_t)row * DIMV;
    int t = threadIdx.x;
    float v0 = xr[t], v1 = xr[t + 128], v2 = xr[t + 256];
    float s = v0 + v1 + v2;
    float q = v0 * v0 + v1 * v1 + v2 * v2;
    #pragma unroll
    for (int o = 16; o > 0; o >>= 1) {
        s += __shfl_down_sync(0xffffffffu, s, o);
        q += __shfl_down_sync(0xffffffffu, q, o);
    }
    __shared__ float shs[4], shq[4];
    __shared__ float s_mean, s_inv;
    int w = t >> 5, lane = t & 31;
    if (lane == 0) { shs[w] = s; shq[w] = q; }
    __syncthreads();
    if (t == 0) {
        float S = shs[0] + shs[1] + shs[2] + shs[3];
        float Q = shq[0] + shq[1] + shq[2] + shq[3];
        float m = S * (1.0f / 384.0f);
        float var = Q * (1.0f / 384.0f) - m * m;
        s_mean = m;
        s_inv  = rsqrtf(var + 1e-5f);
    }
    __syncthreads();
    float m = s_mean, inv = s_inv;
    yr[t]       = rndtf((v0 - m) * inv * gamma[t]       + beta[t]);
    yr[t + 128] = rndtf((v1 - m) * inv * gamma[t + 128] + beta[t + 128]);
    yr[t + 256] = rndtf((v2 - m) * inv * gamma[t + 256] + beta[t + 256]);
}

// ---------------- driver ----------------
extern "C" void kernel_launch(void* const* d_in, const int* in_sizes, int n_in,
                              void* d_out, int out_size) {
    const float* x_in  = (const float*)d_in[0];
    const float* ln1_g = (const float*)d_in[1];
    const float* ln1_b = (const float*)d_in[2];
    const float* qkv_w = (const float*)d_in[3];
    const float* temp  = (const float*)d_in[4];
    const float* out_w = (const float*)d_in[5];
    const float* out_b = (const float*)d_in[6];
    const float* ln2_g = (const float*)d_in[7];
    const float* ln2_b = (const float*)d_in[8];
    const float* ff_w1 = (const float*)d_in[9];
    const float* ff_b1 = (const float*)d_in[10];
    const float* ff_w2 = (const float*)d_in[11];
    const float* ff_b2 = (const float*)d_in[12];
    float* x = (float*)d_out;

    float *p_ln, *p_qkv, *p_attn, *p_ff, *p_wt;
    cudaGetSymbolAddress((void**)&p_ln,   g_ln);
    cudaGetSymbolAddress((void**)&p_qkv,  g_qkv);
    cudaGetSymbolAddress((void**)&p_attn, g_attn);
    cudaGetSymbolAddress((void**)&p_ff,   g_ff);
    cudaGetSymbolAddress((void**)&p_wt,   g_wt);

    cudaFuncSetAttribute(mma_gemm<0>, cudaFuncAttributeMaxDynamicSharedMemorySize, GS_BYTES);
    cudaFuncSetAttribute(mma_gemm<1>, cudaFuncAttributeMaxDynamicSharedMemorySize, GS_BYTES);
    cudaFuncSetAttribute(mma_gemm<2>, cudaFuncAttributeMaxDynamicSharedMemorySize, GS_BYTES);
    cudaFuncSetAttribute(flash_kernel, cudaFuncAttributeMaxDynamicSharedMemorySize, FL_DSMEM);

    cudaMemcpyAsync(x, x_in, (size_t)ROWS * DIMV * sizeof(float),
                    cudaMemcpyDeviceToDevice);

    transpose_kernel<<<dim3(QKVW / 32, DIMV / 32, DEPTH), dim3(32, 8)>>>(
        qkv_w, p_wt + WT_QKV_OFF, DIMV, QKVW);
    transpose_kernel<<<dim3(DIMV / 32, INNER / 32, DEPTH), dim3(32, 8)>>>(
        out_w, p_wt + WT_WO_OFF, INNER, DIMV);
    transpose_kernel<<<dim3(MLPV / 32, DIMV / 32, DEPTH), dim3(32, 8)>>>(
        ff_w1, p_wt + WT_W1_OFF, DIMV, MLPV);
    transpose_kernel<<<dim3(DIMV / 32, MLPV / 32, DEPTH), dim3(32, 8)>>>(
        ff_w2, p_wt + WT_W2_OFF, MLPV, DIMV);

    for (int l = 0; l < DEPTH; l++) {
        // --- attention block ---
        ln_kernel<<<ROWS, 128>>>(x, ln1_g + l * DIMV, ln1_b + l * DIMV, p_ln);
        mma_gemm<0><<<dim3(QKVW / 128, ROWS / 128), 256, GS_BYTES>>>(
            p_ln, p_wt + WT_QKV_OFF + (size_t)l * WT_QKV_PER,
            nullptr, nullptr, p_qkv, ROWS, QKVW, DIMV);
        flash_kernel<<<dim3(NN / 128, BHN), 256, FL_DSMEM>>>(p_qkv, p_attn, temp, l);
        mma_gemm<1><<<dim3(DIMV / 128, ROWS / 128), 256, GS_BYTES>>>(
            p_attn, p_wt + WT_WO_OFF + (size_t)l * WT_WO_PER,
            out_b + l * DIMV, x, x, ROWS, DIMV, INNER);
        // --- feed-forward block ---
        ln_kernel<<<ROWS, 128>>>(x, ln2_g + l * DIMV, ln2_b + l * DIMV, p_ln);
        mma_gemm<2><<<dim3(MLPV / 128, ROWS / 128), 256, GS_BYTES>>>(
            p_ln, p_wt + WT_W1_OFF + (size_t)l * WT_W1_PER,
            ff_b1 + l * MLPV, nullptr, p_ff, ROWS, MLPV, DIMV);
        mma_gemm<1><<<dim3(DIMV / 128, ROWS / 128), 256, GS_BYTES>>>(
            p_ff, p_wt + WT_W2_OFF + (size_t)l * WT_W2_PER,
            ff_b2 + l * DIMV, x, x, ROWS, DIMV, MLPV);
    }
}

// round 5
// speedup vs baseline: 3.5340x; 1.0737x over previous
#include <cuda_runtime.h>
#include <math.h>
#include <stdint.h>

#define BB     16
#define NN     1024
#define DIMV   384
#define DEPTH  6
#define HEADS  6
#define DH     64
#define INNER  384
#define MLPV   1536
#define ROWS   (BB*NN)       // 16384
#define BHN    (BB*HEADS)    // 96
#define QKVW   (3*INNER)     // 1152
#define NEGMAX -3.4028234663852886e38f

// ---------------- scratch ----------------
__device__ float g_ln[(size_t)ROWS * DIMV];
__device__ float g_qkv[(size_t)ROWS * QKVW];
__device__ float g_attn[(size_t)ROWS * INNER];
__device__ float g_ff[(size_t)ROWS * MLPV];
#define WT_QKV_OFF  0
#define WT_QKV_PER  (QKVW*DIMV)
#define WT_WO_OFF   (WT_QKV_OFF + DEPTH*WT_QKV_PER)
#define WT_WO_PER   (DIMV*INNER)
#define WT_W1_OFF   (WT_WO_OFF + DEPTH*WT_WO_PER)
#define WT_W1_PER   (MLPV*DIMV)
#define WT_W2_OFF   (WT_W1_OFF + DEPTH*WT_W1_PER)
#define WT_W2_PER   (DIMV*MLPV)
__device__ float g_wt[(size_t)(WT_W2_OFF + DEPTH*WT_W2_PER)];

// ================= helpers =================
__device__ __forceinline__ uint32_t smem_u32(const void* p) {
    uint32_t r;
    asm("{ .reg .u64 t; cvta.to.shared.u64 t, %1; cvt.u32.u64 %0, t; }" : "=r"(r) : "l"(p));
    return r;
}
__device__ __forceinline__ float rndtf(float x) {
    uint32_t r;
    asm("cvt.rna.tf32.f32 %0, %1;" : "=r"(r) : "f"(x));
    return __uint_as_float(r);
}
__device__ __forceinline__ void cp16(uint32_t dst, const void* src) {
    asm volatile("cp.async.cg.shared.global [%0], [%1], 16;" :: "r"(dst), "l"(src));
}
__device__ __forceinline__ void mma8(float c[4], const uint32_t a[4], const uint32_t b[2]) {
    asm volatile(
        "mma.sync.aligned.m16n8k8.row.col.f32.tf32.tf32.f32 "
        "{%0,%1,%2,%3}, {%4,%5,%6,%7}, {%8,%9}, {%0,%1,%2,%3};"
        : "+f"(c[0]), "+f"(c[1]), "+f"(c[2]), "+f"(c[3])
        : "r"(a[0]), "r"(a[1]), "r"(a[2]), "r"(a[3]), "r"(b[0]), "r"(b[1]));
}

// ================= dense tf32 GEMM: C[M,Nn] = A[M,K] @ Bt[Nn,K]^T =================
// Inputs pre-rounded to tf32. 128x128 CTA tile, 4 warps (2x2), warp tile 64x64,
// BK=32, 3-stage cp.async pipeline. 1.0 LDS per MMA.
// EPI 0: C = rnd(AB) ; EPI 1: C = res + AB + bias ; EPI 2: C = rnd(gelu(AB + bias))
#define GS_STAGE 9216u                       // floats per stage (A 128x36 + B 128x36)
#define GS_BYTES (3u * GS_STAGE * 4u)        // 110592 B
template <int EPI>
__global__ void __launch_bounds__(128) mma_gemm(
    const float* __restrict__ A, const float* __restrict__ Bt,
    const float* __restrict__ bias, const float* __restrict__ res,
    float* __restrict__ C, int M, int Nn, int K) {
    extern __shared__ float sm[];
    const int tid = threadIdx.x;
    const int wid = tid >> 5, lane = tid & 31;
    const int g = lane >> 2, tg = lane & 3;
    const int wm = (wid & 1) * 64, wn = (wid >> 1) * 64;
    const int m0 = blockIdx.y * 128, n0 = blockIdx.x * 128;

    float c[4][8][4];
    #pragma unroll
    for (int mt = 0; mt < 4; ++mt)
        #pragma unroll
        for (int nt = 0; nt < 8; ++nt)
            #pragma unroll
            for (int k = 0; k < 4; ++k) c[mt][nt][k] = 0.0f;

    const int nc = K >> 5;
    const uint32_t sbase = smem_u32(sm);

    auto issue = [&](int ci) {
        uint32_t base = sbase + (uint32_t)(ci % 3) * (GS_STAGE * 4u);
        int kt = ci << 5;
        #pragma unroll
        for (int i = 0; i < 8; ++i) {
            int f = tid + i * 128;           // 0..1023
            int r = f >> 3, c4 = (f & 7) << 2;
            cp16(base + (uint32_t)(r * 36 + c4) * 4u,
                 A + (size_t)(m0 + r) * K + kt + c4);
            cp16(base + (4608u + (uint32_t)(r * 36 + c4)) * 4u,
                 Bt + (size_t)(n0 + r) * K + kt + c4);
        }
        asm volatile("cp.async.commit_group;" ::: "memory");
    };

    issue(0);
    issue(1);

    for (int ci = 0; ci < nc; ++ci) {
        if (ci + 2 < nc) {
            issue(ci + 2);
        } else {
            asm volatile("cp.async.commit_group;" ::: "memory");   // empty group
        }
        asm volatile("cp.async.wait_group 2;" ::: "memory");
        __syncthreads();

        const uint32_t* sA = (const uint32_t*)(sm + (ci % 3) * GS_STAGE);
        const uint32_t* sB = sA + 4608;
        #pragma unroll
        for (int ks = 0; ks < 4; ++ks) {
            const int kb = ks * 8;
            uint32_t af[4][4], bf[8][2];
            #pragma unroll
            for (int mt = 0; mt < 4; ++mt) {
                int r = wm + mt * 16 + g;
                af[mt][0] = sA[r * 36 + kb + tg];
                af[mt][1] = sA[(r + 8) * 36 + kb + tg];
                af[mt][2] = sA[r * 36 + kb + tg + 4];
                af[mt][3] = sA[(r + 8) * 36 + kb + tg + 4];
            }
            #pragma unroll
            for (int nt = 0; nt < 8; ++nt) {
                int r = wn + nt * 8 + g;
                bf[nt][0] = sB[r * 36 + kb + tg];
                bf[nt][1] = sB[r * 36 + kb + tg + 4];
            }
            #pragma unroll
            for (int mt = 0; mt < 4; ++mt)
                #pragma unroll
                for (int nt = 0; nt < 8; ++nt)
                    mma8(c[mt][nt], af[mt], bf[nt]);
        }
        __syncthreads();
    }

    #pragma unroll
    for (int mt = 0; mt < 4; ++mt) {
        #pragma unroll
        for (int nt = 0; nt < 8; ++nt) {
            int col = n0 + wn + nt * 8 + 2 * tg;
            #pragma unroll
            for (int h = 0; h < 2; ++h) {
                int row = m0 + wm + mt * 16 + g + h * 8;
                float v0 = c[mt][nt][h * 2 + 0];
                float v1 = c[mt][nt][h * 2 + 1];
                if (EPI >= 1) { v0 += bias[col]; v1 += bias[col + 1]; }
                if (EPI == 1) {
                    float2 r2 = *(const float2*)(res + (size_t)row * Nn + col);
                    v0 += r2.x; v1 += r2.y;
                }
                if (EPI == 2) {
                    v0 = 0.5f * v0 * (1.0f + erff(v0 * 0.70710678118654752f));
                    v1 = 0.5f * v1 * (1.0f + erff(v1 * 0.70710678118654752f));
                }
                if (EPI != 1) { v0 = rndtf(v0); v1 = rndtf(v1); }
                float2 o; o.x = v0; o.y = v1;
                *(float2*)(C + (size_t)row * Nn + col) = o;
            }
        }
    }
}

// ================= flash attention (unchanged from R4) =================
#define FL_DSMEM ((128*68 + 64*68 + 64*68) * 4)   // 69632 B
__global__ void __launch_bounds__(256, 2) flash_kernel(
    const float* __restrict__ qkv,
    float* __restrict__ o,
    const float* __restrict__ temp, int layer) {
    extern __shared__ float fs[];
    float* Ps = fs;
    float* Ks = fs + 128 * 68;
    float* Vt = Ks + 64 * 68;

    int bh = blockIdx.y;
    int b = bh / HEADS, h = bh - b * HEADS;
    int rt = blockIdx.x * 128;
    int tid = threadIdx.x, wid = tid >> 5, lane = tid & 31;
    int g = lane >> 2, tg = lane & 3;

    const float* qb = qkv + (size_t)b * NN * QKVW + h * DH;
    const float* kb = qb + INNER;
    const float* vb = qb + 2 * INNER;

    #pragma unroll
    for (int i = 0; i < 8; ++i) {
        int f = tid + i * 256;
        int r = f >> 4, c4 = (f & 15) << 2;
        *(float4*)&Ps[r * 68 + c4] = *(const float4*)(qb + (size_t)(rt + r) * QKVW + c4);
    }
    __syncthreads();
    uint32_t qf[8][4];
    {
        int r = wid * 16 + g;
        #pragma unroll
        for (int ks = 0; ks < 8; ++ks) {
            int kb2 = ks * 8;
            qf[ks][0] = __float_as_uint(Ps[r * 68 + kb2 + tg]);
            qf[ks][1] = __float_as_uint(Ps[(r + 8) * 68 + kb2 + tg]);
            qf[ks][2] = __float_as_uint(Ps[r * 68 + kb2 + tg + 4]);
            qf[ks][3] = __float_as_uint(Ps[(r + 8) * 68 + kb2 + tg + 4]);
        }
    }

    float scale = expf(temp[layer]);
    float m0 = NEGMAX, m1 = NEGMAX, l0 = 0.0f, l1 = 0.0f;
    float oacc[8][4];
    #pragma unroll
    for (int nt = 0; nt < 8; ++nt)
        #pragma unroll
        for (int k = 0; k < 4; ++k) oacc[nt][k] = 0.0f;

    const int gi0 = rt + wid * 16 + g;
    const int gi1 = gi0 + 8;
    const int prow = wid * 16 + g;

    for (int kt = 0; kt < NN; kt += 64) {
        __syncthreads();
        #pragma unroll
        for (int i = 0; i < 4; ++i) {
            int f = tid + i * 256;
            int r = f >> 4, c4 = (f & 15) << 2;
            *(float4*)&Ks[r * 68 + c4] = *(const float4*)(kb + (size_t)(kt + r) * QKVW + c4);
            float4 v4 = *(const float4*)(vb + (size_t)(kt + r) * QKVW + c4);
            Vt[(c4 + 0) * 68 + r] = v4.x;
            Vt[(c4 + 1) * 68 + r] = v4.y;
            Vt[(c4 + 2) * 68 + r] = v4.z;
            Vt[(c4 + 3) * 68 + r] = v4.w;
        }
        __syncthreads();

        float s[8][4];
        #pragma unroll
        for (int nt = 0; nt < 8; ++nt)
            #pragma unroll
            for (int k = 0; k < 4; ++k) s[nt][k] = 0.0f;
        #pragma unroll
        for (int ks = 0; ks < 8; ++ks) {
            int kb2 = ks * 8;
            #pragma unroll
            for (int nt = 0; nt < 8; ++nt) {
                int rn = nt * 8 + g;
                uint32_t bf[2];
                bf[0] = __float_as_uint(Ks[rn * 68 + kb2 + tg]);
                bf[1] = __float_as_uint(Ks[rn * 68 + kb2 + tg + 4]);
                mma8(s[nt], qf[ks], bf);
            }
        }
        #pragma unroll
        for (int nt = 0; nt < 8; ++nt) {
            int gj = kt + nt * 8 + 2 * tg;
            s[nt][0] *= scale; s[nt][1] *= scale; s[nt][2] *= scale; s[nt][3] *= scale;
            if (gi0 == gj)     s[nt][0] = NEGMAX;
            if (gi0 == gj + 1) s[nt][1] = NEGMAX;
            if (gi1 == gj)     s[nt][2] = NEGMAX;
            if (gi1 == gj + 1) s[nt][3] = NEGMAX;
        }
        float mx0 = NEGMAX, mx1 = NEGMAX;
        #pragma unroll
        for (int nt = 0; nt < 8; ++nt) {
            mx0 = fmaxf(mx0, fmaxf(s[nt][0], s[nt][1]));
            mx1 = fmaxf(mx1, fmaxf(s[nt][2], s[nt][3]));
        }
        mx0 = fmaxf(mx0, __shfl_xor_sync(0xffffffffu, mx0, 1));
        mx0 = fmaxf(mx0, __shfl_xor_sync(0xffffffffu, mx0, 2));
        mx1 = fmaxf(mx1, __shfl_xor_sync(0xffffffffu, mx1, 1));
        mx1 = fmaxf(mx1, __shfl_xor_sync(0xffffffffu, mx1, 2));
        float mn0 = fmaxf(m0, mx0), mn1 = fmaxf(m1, mx1);
        float r0 = __expf(m0 - mn0), r1 = __expf(m1 - mn1);
        float sum0 = 0.0f, sum1 = 0.0f;
        #pragma unroll
        for (int nt = 0; nt < 8; ++nt) {
            float p0 = __expf(s[nt][0] - mn0);
            float p1 = __expf(s[nt][1] - mn0);
            float p2 = __expf(s[nt][2] - mn1);
            float p3 = __expf(s[nt][3] - mn1);
            sum0 += p0 + p1;
            sum1 += p2 + p3;
            int col = nt * 8 + 2 * tg;
            float2 w0; w0.x = rndtf(p0); w0.y = rndtf(p1);
            float2 w1; w1.x = rndtf(p2); w1.y = rndtf(p3);
            *(float2*)&Ps[prow * 68 + col] = w0;
            *(float2*)&Ps[(prow + 8) * 68 + col] = w1;
        }
        sum0 += __shfl_xor_sync(0xffffffffu, sum0, 1);
        sum0 += __shfl_xor_sync(0xffffffffu, sum0, 2);
        sum1 += __shfl_xor_sync(0xffffffffu, sum1, 1);
        sum1 += __shfl_xor_sync(0xffffffffu, sum1, 2);
        l0 = l0 * r0 + sum0;
        l1 = l1 * r1 + sum1;
        m0 = mn0; m1 = mn1;
        #pragma unroll
        for (int nt = 0; nt < 8; ++nt) {
            oacc[nt][0] *= r0; oacc[nt][1] *= r0;
            oacc[nt][2] *= r1; oacc[nt][3] *= r1;
        }
        __syncwarp();
        #pragma unroll
        for (int ks = 0; ks < 8; ++ks) {
            int kb2 = ks * 8;
            uint32_t af[4];
            af[0] = __float_as_uint(Ps[prow * 68 + kb2 + tg]);
            af[1] = __float_as_uint(Ps[(prow + 8) * 68 + kb2 + tg]);
            af[2] = __float_as_uint(Ps[prow * 68 + kb2 + tg + 4]);
            af[3] = __float_as_uint(Ps[(prow + 8) * 68 + kb2 + tg + 4]);
            #pragma unroll
            for (int nt = 0; nt < 8; ++nt) {
                int rn = nt * 8 + g;
                uint32_t bf[2];
                bf[0] = __float_as_uint(Vt[rn * 68 + kb2 + tg]);
                bf[1] = __float_as_uint(Vt[rn * 68 + kb2 + tg + 4]);
                mma8(oacc[nt], af, bf);
            }
        }
    }

    float inv0 = 1.0f / l0, inv1 = 1.0f / l1;
    #pragma unroll
    for (int nt = 0; nt < 8; ++nt) {
        int gc = h * DH + nt * 8 + 2 * tg;
        int gr0 = b * NN + gi0;
        int gr1 = b * NN + gi1;
        float2 o0; o0.x = rndtf(oacc[nt][0] * inv0); o0.y = rndtf(oacc[nt][1] * inv0);
        float2 o1; o1.x = rndtf(oacc[nt][2] * inv1); o1.y = rndtf(oacc[nt][3] * inv1);
        *(float2*)(o + (size_t)gr0 * INNER + gc) = o0;
        *(float2*)(o + (size_t)gr1 * INNER + gc) = o1;
    }
}

// ---------------- weight transpose (+ tf32 rounding) ----------------
__global__ void transpose_kernel(const float* __restrict__ src, float* __restrict__ dst,
                                 int K, int N) {
    __shared__ float t[32][33];
    int z = blockIdx.z;
    src += (size_t)z * K * N;
    dst += (size_t)z * K * N;
    int k0 = blockIdx.y * 32, n0 = blockIdx.x * 32;
    int tx = threadIdx.x, ty = threadIdx.y;
    #pragma unroll
    for (int j = 0; j < 32; j += 8)
        t[ty + j][tx] = src[(size_t)(k0 + ty + j) * N + n0 + tx];
    __syncthreads();
    #pragma unroll
    for (int j = 0; j < 32; j += 8)
        dst[(size_t)(n0 + ty + j) * K + k0 + tx] = rndtf(t[tx][ty + j]);
}

// ---------------- LayerNorm (+ tf32 rounding of output) ----------------
__global__ void ln_kernel(const float* __restrict__ x,
                          const float* __restrict__ gamma,
                          const float* __restrict__ beta,
                          float* __restrict__ y) {
    int row = blockIdx.x;
    const float* xr = x + (size_t)row * DIMV;
    float*       yr = y + (size_t)row * DIMV;
    int t = threadIdx.x;
    float v0 = xr[t], v1 = xr[t + 128], v2 = xr[t + 256];
    float s = v0 + v1 + v2;
    float q = v0 * v0 + v1 * v1 + v2 * v2;
    #pragma unroll
    for (int o = 16; o > 0; o >>= 1) {
        s += __shfl_down_sync(0xffffffffu, s, o);
        q += __shfl_down_sync(0xffffffffu, q, o);
    }
    __shared__ float shs[4], shq[4];
    __shared__ float s_mean, s_inv;
    int w = t >> 5, lane = t & 31;
    if (lane == 0) { shs[w] = s; shq[w] = q; }
    __syncthreads();
    if (t == 0) {
        float S = shs[0] + shs[1] + shs[2] + shs[3];
        float Q = shq[0] + shq[1] + shq[2] + shq[3];
        float m = S * (1.0f / 384.0f);
        float var = Q * (1.0f / 384.0f) - m * m;
        s_mean = m;
        s_inv  = rsqrtf(var + 1e-5f);
    }
    __syncthreads();
    float m = s_mean, inv = s_inv;
    yr[t]       = rndtf((v0 - m) * inv * gamma[t]       + beta[t]);
    yr[t + 128] = rndtf((v1 - m) * inv * gamma[t + 128] + beta[t + 128]);
    yr[t + 256] = rndtf((v2 - m) * inv * gamma[t + 256] + beta[t + 256]);
}

// ---------------- driver ----------------
extern "C" void kernel_launch(void* const* d_in, const int* in_sizes, int n_in,
                              void* d_out, int out_size) {
    const float* x_in  = (const float*)d_in[0];
    const float* ln1_g = (const float*)d_in[1];
    const float* ln1_b = (const float*)d_in[2];
    const float* qkv_w = (const float*)d_in[3];
    const float* temp  = (const float*)d_in[4];
    const float* out_w = (const float*)d_in[5];
    const float* out_b = (const float*)d_in[6];
    const float* ln2_g = (const float*)d_in[7];
    const float* ln2_b = (const float*)d_in[8];
    const float* ff_w1 = (const float*)d_in[9];
    const float* ff_b1 = (const float*)d_in[10];
    const float* ff_w2 = (const float*)d_in[11];
    const float* ff_b2 = (const float*)d_in[12];
    float* x = (float*)d_out;

    float *p_ln, *p_qkv, *p_attn, *p_ff, *p_wt;
    cudaGetSymbolAddress((void**)&p_ln,   g_ln);
    cudaGetSymbolAddress((void**)&p_qkv,  g_qkv);
    cudaGetSymbolAddress((void**)&p_attn, g_attn);
    cudaGetSymbolAddress((void**)&p_ff,   g_ff);
    cudaGetSymbolAddress((void**)&p_wt,   g_wt);

    cudaFuncSetAttribute(mma_gemm<0>, cudaFuncAttributeMaxDynamicSharedMemorySize, GS_BYTES);
    cudaFuncSetAttribute(mma_gemm<1>, cudaFuncAttributeMaxDynamicSharedMemorySize, GS_BYTES);
    cudaFuncSetAttribute(mma_gemm<2>, cudaFuncAttributeMaxDynamicSharedMemorySize, GS_BYTES);
    cudaFuncSetAttribute(flash_kernel, cudaFuncAttributeMaxDynamicSharedMemorySize, FL_DSMEM);

    cudaMemcpyAsync(x, x_in, (size_t)ROWS * DIMV * sizeof(float),
                    cudaMemcpyDeviceToDevice);

    transpose_kernel<<<dim3(QKVW / 32, DIMV / 32, DEPTH), dim3(32, 8)>>>(
        qkv_w, p_wt + WT_QKV_OFF, DIMV, QKVW);
    transpose_kernel<<<dim3(DIMV / 32, INNER / 32, DEPTH), dim3(32, 8)>>>(
        out_w, p_wt + WT_WO_OFF, INNER, DIMV);
    transpose_kernel<<<dim3(MLPV / 32, DIMV / 32, DEPTH), dim3(32, 8)>>>(
        ff_w1, p_wt + WT_W1_OFF, DIMV, MLPV);
    transpose_kernel<<<dim3(DIMV / 32, MLPV / 32, DEPTH), dim3(32, 8)>>>(
        ff_w2, p_wt + WT_W2_OFF, MLPV, DIMV);

    for (int l = 0; l < DEPTH; l++) {
        // --- attention block ---
        ln_kernel<<<ROWS, 128>>>(x, ln1_g + l * DIMV, ln1_b + l * DIMV, p_ln);
        mma_gemm<0><<<dim3(QKVW / 128, ROWS / 128), 128, GS_BYTES>>>(
            p_ln, p_wt + WT_QKV_OFF + (size_t)l * WT_QKV_PER,
            nullptr, nullptr, p_qkv, ROWS, QKVW, DIMV);
        flash_kernel<<<dim3(NN / 128, BHN), 256, FL_DSMEM>>>(p_qkv, p_attn, temp, l);
        mma_gemm<1><<<dim3(DIMV / 128, ROWS / 128), 128, GS_BYTES>>>(
            p_attn, p_wt + WT_WO_OFF + (size_t)l * WT_WO_PER,
            out_b + l * DIMV, x, x, ROWS, DIMV, INNER);
        // --- feed-forward block ---
        ln_kernel<<<ROWS, 128>>>(x, ln2_g + l * DIMV, ln2_b + l * DIMV, p_ln);
        mma_gemm<2><<<dim3(MLPV / 128, ROWS / 128), 128, GS_BYTES>>>(
            p_ln, p_wt + WT_W1_OFF + (size_t)l * WT_W1_PER,
            ff_b1 + l * MLPV, nullptr, p_ff, ROWS, MLPV, DIMV);
        mma_gemm<1><<<dim3(DIMV / 128, ROWS / 128), 128, GS_BYTES>>>(
            p_ff, p_wt + WT_W2_OFF + (size_t)l * WT_W2_PER,
            ff_b2 + l * DIMV, x, x, ROWS, DIMV, MLPV);
    }
}

// round 6
// speedup vs baseline: 3.5812x; 1.0133x over previous
#include <cuda_runtime.h>
#include <math.h>
#include <stdint.h>

#define BB     16
#define NN     1024
#define DIMV   384
#define DEPTH  6
#define HEADS  6
#define DH     64
#define INNER  384
#define MLPV   1536
#define ROWS   (BB*NN)       // 16384
#define BHN    (BB*HEADS)    // 96
#define QKVW   (3*INNER)     // 1152
#define NEGMAX -3.4028234663852886e38f

// ---------------- scratch ----------------
__device__ float g_ln[(size_t)ROWS * DIMV];
__device__ float g_qkv[(size_t)ROWS * QKVW];
__device__ float g_attn[(size_t)ROWS * INNER];
__device__ float g_ff[(size_t)ROWS * MLPV];
#define WT_QKV_OFF  0
#define WT_QKV_PER  (QKVW*DIMV)
#define WT_WO_OFF   (WT_QKV_OFF + DEPTH*WT_QKV_PER)
#define WT_WO_PER   (DIMV*INNER)
#define WT_W1_OFF   (WT_WO_OFF + DEPTH*WT_WO_PER)
#define WT_W1_PER   (MLPV*DIMV)
#define WT_W2_OFF   (WT_W1_OFF + DEPTH*WT_W1_PER)
#define WT_W2_PER   (DIMV*MLPV)
__device__ float g_wt[(size_t)(WT_W2_OFF + DEPTH*WT_W2_PER)];

// ================= helpers =================
__device__ __forceinline__ uint32_t smem_u32(const void* p) {
    uint32_t r;
    asm("{ .reg .u64 t; cvta.to.shared.u64 t, %1; cvt.u32.u64 %0, t; }" : "=r"(r) : "l"(p));
    return r;
}
__device__ __forceinline__ float rndtf(float x) {
    uint32_t r;
    asm("cvt.rna.tf32.f32 %0, %1;" : "=r"(r) : "f"(x));
    return __uint_as_float(r);
}
__device__ __forceinline__ void cp16(uint32_t dst, const void* src) {
    asm volatile("cp.async.cg.shared.global [%0], [%1], 16;" :: "r"(dst), "l"(src));
}
__device__ __forceinline__ void mma8(float c[4], const uint32_t a[4], const uint32_t b[2]) {
    asm volatile(
        "mma.sync.aligned.m16n8k8.row.col.f32.tf32.tf32.f32 "
        "{%0,%1,%2,%3}, {%4,%5,%6,%7}, {%8,%9}, {%0,%1,%2,%3};"
        : "+f"(c[0]), "+f"(c[1]), "+f"(c[2]), "+f"(c[3])
        : "r"(a[0]), "r"(a[1]), "r"(a[2]), "r"(a[3]), "r"(b[0]), "r"(b[1]));
}

// ================= dense tf32 GEMM: C[M,Nn] = A[M,K] @ Bt[Nn,K]^T =================
// 128x128 CTA tile, 256 thr = 8 warps (2m x 4n), warp tile 64x32, BK=32,
// 3-stage cp.async pipeline. 16 warps/SM (2 CTA/SM), ~110 regs/thread.
// EPI 0: C = rnd(AB) ; EPI 1: C = res + AB + bias ; EPI 2: C = rnd(gelu(AB + bias))
#define GS_STAGE 9216u                       // floats per stage (A 128x36 + B 128x36)
#define GS_BYTES (3u * GS_STAGE * 4u)        // 110592 B
template <int EPI>
__global__ void __launch_bounds__(256, 2) mma_gemm(
    const float* __restrict__ A, const float* __restrict__ Bt,
    const float* __restrict__ bias, const float* __restrict__ res,
    float* __restrict__ C, int M, int Nn, int K) {
    extern __shared__ float sm[];
    const int tid = threadIdx.x;
    const int wid = tid >> 5, lane = tid & 31;
    const int g = lane >> 2, tg = lane & 3;
    const int wm = (wid & 1) * 64, wn = (wid >> 1) * 32;
    const int m0 = blockIdx.y * 128, n0 = blockIdx.x * 128;

    float c[4][4][4];
    #pragma unroll
    for (int mt = 0; mt < 4; ++mt)
        #pragma unroll
        for (int nt = 0; nt < 4; ++nt)
            #pragma unroll
            for (int k = 0; k < 4; ++k) c[mt][nt][k] = 0.0f;

    const int nc = K >> 5;
    const uint32_t sbase = smem_u32(sm);

    auto issue = [&](int ci) {
        uint32_t base = sbase + (uint32_t)(ci % 3) * (GS_STAGE * 4u);
        int kt = ci << 5;
        #pragma unroll
        for (int i = 0; i < 4; ++i) {
            int f = tid + i * 256;           // 0..1023
            int r = f >> 3, c4 = (f & 7) << 2;
            cp16(base + (uint32_t)(r * 36 + c4) * 4u,
                 A + (size_t)(m0 + r) * K + kt + c4);
            cp16(base + (4608u + (uint32_t)(r * 36 + c4)) * 4u,
                 Bt + (size_t)(n0 + r) * K + kt + c4);
        }
        asm volatile("cp.async.commit_group;" ::: "memory");
    };

    issue(0);
    issue(1);

    for (int ci = 0; ci < nc; ++ci) {
        if (ci + 2 < nc) {
            issue(ci + 2);
        } else {
            asm volatile("cp.async.commit_group;" ::: "memory");   // empty group
        }
        asm volatile("cp.async.wait_group 2;" ::: "memory");
        __syncthreads();

        const uint32_t* sA = (const uint32_t*)(sm + (ci % 3) * GS_STAGE);
        const uint32_t* sB = sA + 4608;
        #pragma unroll
        for (int ks = 0; ks < 4; ++ks) {
            const int kb = ks * 8;
            uint32_t af[4][4], bf[4][2];
            #pragma unroll
            for (int mt = 0; mt < 4; ++mt) {
                int r = wm + mt * 16 + g;
                af[mt][0] = sA[r * 36 + kb + tg];
                af[mt][1] = sA[(r + 8) * 36 + kb + tg];
                af[mt][2] = sA[r * 36 + kb + tg + 4];
                af[mt][3] = sA[(r + 8) * 36 + kb + tg + 4];
            }
            #pragma unroll
            for (int nt = 0; nt < 4; ++nt) {
                int r = wn + nt * 8 + g;
                bf[nt][0] = sB[r * 36 + kb + tg];
                bf[nt][1] = sB[r * 36 + kb + tg + 4];
            }
            #pragma unroll
            for (int mt = 0; mt < 4; ++mt)
                #pragma unroll
                for (int nt = 0; nt < 4; ++nt)
                    mma8(c[mt][nt], af[mt], bf[nt]);
        }
        __syncthreads();
    }

    #pragma unroll
    for (int mt = 0; mt < 4; ++mt) {
        #pragma unroll
        for (int nt = 0; nt < 4; ++nt) {
            int col = n0 + wn + nt * 8 + 2 * tg;
            #pragma unroll
            for (int h = 0; h < 2; ++h) {
                int row = m0 + wm + mt * 16 + g + h * 8;
                float v0 = c[mt][nt][h * 2 + 0];
                float v1 = c[mt][nt][h * 2 + 1];
                if (EPI >= 1) { v0 += bias[col]; v1 += bias[col + 1]; }
                if (EPI == 1) {
                    float2 r2 = *(const float2*)(res + (size_t)row * Nn + col);
                    v0 += r2.x; v1 += r2.y;
                }
                if (EPI == 2) {
                    v0 = 0.5f * v0 * (1.0f + erff(v0 * 0.70710678118654752f));
                    v1 = 0.5f * v1 * (1.0f + erff(v1 * 0.70710678118654752f));
                }
                if (EPI != 1) { v0 = rndtf(v0); v1 = rndtf(v1); }
                float2 o; o.x = v0; o.y = v1;
                *(float2*)(C + (size_t)row * Nn + col) = o;
            }
        }
    }
}

// ================= flash attention (unchanged) =================
#define FL_DSMEM ((128*68 + 64*68 + 64*68) * 4)   // 69632 B
__global__ void __launch_bounds__(256, 2) flash_kernel(
    const float* __restrict__ qkv,
    float* __restrict__ o,
    const float* __restrict__ temp, int layer) {
    extern __shared__ float fs[];
    float* Ps = fs;
    float* Ks = fs + 128 * 68;
    float* Vt = Ks + 64 * 68;

    int bh = blockIdx.y;
    int b = bh / HEADS, h = bh - b * HEADS;
    int rt = blockIdx.x * 128;
    int tid = threadIdx.x, wid = tid >> 5, lane = tid & 31;
    int g = lane >> 2, tg = lane & 3;

    const float* qb = qkv + (size_t)b * NN * QKVW + h * DH;
    const float* kb = qb + INNER;
    const float* vb = qb + 2 * INNER;

    #pragma unroll
    for (int i = 0; i < 8; ++i) {
        int f = tid + i * 256;
        int r = f >> 4, c4 = (f & 15) << 2;
        *(float4*)&Ps[r * 68 + c4] = *(const float4*)(qb + (size_t)(rt + r) * QKVW + c4);
    }
    __syncthreads();
    uint32_t qf[8][4];
    {
        int r = wid * 16 + g;
        #pragma unroll
        for (int ks = 0; ks < 8; ++ks) {
            int kb2 = ks * 8;
            qf[ks][0] = __float_as_uint(Ps[r * 68 + kb2 + tg]);
            qf[ks][1] = __float_as_uint(Ps[(r + 8) * 68 + kb2 + tg]);
            qf[ks][2] = __float_as_uint(Ps[r * 68 + kb2 + tg + 4]);
            qf[ks][3] = __float_as_uint(Ps[(r + 8) * 68 + kb2 + tg + 4]);
        }
    }

    float scale = expf(temp[layer]);
    float m0 = NEGMAX, m1 = NEGMAX, l0 = 0.0f, l1 = 0.0f;
    float oacc[8][4];
    #pragma unroll
    for (int nt = 0; nt < 8; ++nt)
        #pragma unroll
        for (int k = 0; k < 4; ++k) oacc[nt][k] = 0.0f;

    const int gi0 = rt + wid * 16 + g;
    const int gi1 = gi0 + 8;
    const int prow = wid * 16 + g;

    for (int kt = 0; kt < NN; kt += 64) {
        __syncthreads();
        #pragma unroll
        for (int i = 0; i < 4; ++i) {
            int f = tid + i * 256;
            int r = f >> 4, c4 = (f & 15) << 2;
            *(float4*)&Ks[r * 68 + c4] = *(const float4*)(kb + (size_t)(kt + r) * QKVW + c4);
            float4 v4 = *(const float4*)(vb + (size_t)(kt + r) * QKVW + c4);
            Vt[(c4 + 0) * 68 + r] = v4.x;
            Vt[(c4 + 1) * 68 + r] = v4.y;
            Vt[(c4 + 2) * 68 + r] = v4.z;
            Vt[(c4 + 3) * 68 + r] = v4.w;
        }
        __syncthreads();

        float s[8][4];
        #pragma unroll
        for (int nt = 0; nt < 8; ++nt)
            #pragma unroll
            for (int k = 0; k < 4; ++k) s[nt][k] = 0.0f;
        #pragma unroll
        for (int ks = 0; ks < 8; ++ks) {
            int kb2 = ks * 8;
            #pragma unroll
            for (int nt = 0; nt < 8; ++nt) {
                int rn = nt * 8 + g;
                uint32_t bf[2];
                bf[0] = __float_as_uint(Ks[rn * 68 + kb2 + tg]);
                bf[1] = __float_as_uint(Ks[rn * 68 + kb2 + tg + 4]);
                mma8(s[nt], qf[ks], bf);
            }
        }
        #pragma unroll
        for (int nt = 0; nt < 8; ++nt) {
            int gj = kt + nt * 8 + 2 * tg;
            s[nt][0] *= scale; s[nt][1] *= scale; s[nt][2] *= scale; s[nt][3] *= scale;
            if (gi0 == gj)     s[nt][0] = NEGMAX;
            if (gi0 == gj + 1) s[nt][1] = NEGMAX;
            if (gi1 == gj)     s[nt][2] = NEGMAX;
            if (gi1 == gj + 1) s[nt][3] = NEGMAX;
        }
        float mx0 = NEGMAX, mx1 = NEGMAX;
        #pragma unroll
        for (int nt = 0; nt < 8; ++nt) {
            mx0 = fmaxf(mx0, fmaxf(s[nt][0], s[nt][1]));
            mx1 = fmaxf(mx1, fmaxf(s[nt][2], s[nt][3]));
        }
        mx0 = fmaxf(mx0, __shfl_xor_sync(0xffffffffu, mx0, 1));
        mx0 = fmaxf(mx0, __shfl_xor_sync(0xffffffffu, mx0, 2));
        mx1 = fmaxf(mx1, __shfl_xor_sync(0xffffffffu, mx1, 1));
        mx1 = fmaxf(mx1, __shfl_xor_sync(0xffffffffu, mx1, 2));
        float mn0 = fmaxf(m0, mx0), mn1 = fmaxf(m1, mx1);
        float r0 = __expf(m0 - mn0), r1 = __expf(m1 - mn1);
        float sum0 = 0.0f, sum1 = 0.0f;
        #pragma unroll
        for (int nt = 0; nt < 8; ++nt) {
            float p0 = __expf(s[nt][0] - mn0);
            float p1 = __expf(s[nt][1] - mn0);
            float p2 = __expf(s[nt][2] - mn1);
            float p3 = __expf(s[nt][3] - mn1);
            sum0 += p0 + p1;
            sum1 += p2 + p3;
            int col = nt * 8 + 2 * tg;
            float2 w0; w0.x = rndtf(p0); w0.y = rndtf(p1);
            float2 w1; w1.x = rndtf(p2); w1.y = rndtf(p3);
            *(float2*)&Ps[prow * 68 + col] = w0;
            *(float2*)&Ps[(prow + 8) * 68 + col] = w1;
        }
        sum0 += __shfl_xor_sync(0xffffffffu, sum0, 1);
        sum0 += __shfl_xor_sync(0xffffffffu, sum0, 2);
        sum1 += __shfl_xor_sync(0xffffffffu, sum1, 1);
        sum1 += __shfl_xor_sync(0xffffffffu, sum1, 2);
        l0 = l0 * r0 + sum0;
        l1 = l1 * r1 + sum1;
        m0 = mn0; m1 = mn1;
        #pragma unroll
        for (int nt = 0; nt < 8; ++nt) {
            oacc[nt][0] *= r0; oacc[nt][1] *= r0;
            oacc[nt][2] *= r1; oacc[nt][3] *= r1;
        }
        __syncwarp();
        #pragma unroll
        for (int ks = 0; ks < 8; ++ks) {
            int kb2 = ks * 8;
            uint32_t af[4];
            af[0] = __float_as_uint(Ps[prow * 68 + kb2 + tg]);
            af[1] = __float_as_uint(Ps[(prow + 8) * 68 + kb2 + tg]);
            af[2] = __float_as_uint(Ps[prow * 68 + kb2 + tg + 4]);
            af[3] = __float_as_uint(Ps[(prow + 8) * 68 + kb2 + tg + 4]);
            #pragma unroll
            for (int nt = 0; nt < 8; ++nt) {
                int rn = nt * 8 + g;
                uint32_t bf[2];
                bf[0] = __float_as_uint(Vt[rn * 68 + kb2 + tg]);
                bf[1] = __float_as_uint(Vt[rn * 68 + kb2 + tg + 4]);
                mma8(oacc[nt], af, bf);
            }
        }
    }

    float inv0 = 1.0f / l0, inv1 = 1.0f / l1;
    #pragma unroll
    for (int nt = 0; nt < 8; ++nt) {
        int gc = h * DH + nt * 8 + 2 * tg;
        int gr0 = b * NN + gi0;
        int gr1 = b * NN + gi1;
        float2 o0; o0.x = rndtf(oacc[nt][0] * inv0); o0.y = rndtf(oacc[nt][1] * inv0);
        float2 o1; o1.x = rndtf(oacc[nt][2] * inv1); o1.y = rndtf(oacc[nt][3] * inv1);
        *(float2*)(o + (size_t)gr0 * INNER + gc) = o0;
        *(float2*)(o + (size_t)gr1 * INNER + gc) = o1;
    }
}

// ---------------- weight transpose (+ tf32 rounding) ----------------
__global__ void transpose_kernel(const float* __restrict__ src, float* __restrict__ dst,
                                 int K, int N) {
    __shared__ float t[32][33];
    int z = blockIdx.z;
    src += (size_t)z * K * N;
    dst += (size_t)z * K * N;
    int k0 = blockIdx.y * 32, n0 = blockIdx.x * 32;
    int tx = threadIdx.x, ty = threadIdx.y;
    #pragma unroll
    for (int j = 0; j < 32; j += 8)
        t[ty + j][tx] = src[(size_t)(k0 + ty + j) * N + n0 + tx];
    __syncthreads();
    #pragma unroll
    for (int j = 0; j < 32; j += 8)
        dst[(size_t)(n0 + ty + j) * K + k0 + tx] = rndtf(t[tx][ty + j]);
}

// ---------------- LayerNorm (+ tf32 rounding of output) ----------------
__global__ void ln_kernel(const float* __restrict__ x,
                          const float* __restrict__ gamma,
                          const float* __restrict__ beta,
                          float* __restrict__ y) {
    int row = blockIdx.x;
    const float* xr = x + (size_t)row * DIMV;
    float*       yr = y + (size_t)row * DIMV;
    int t = threadIdx.x;
    float v0 = xr[t], v1 = xr[t + 128], v2 = xr[t + 256];
    float s = v0 + v1 + v2;
    float q = v0 * v0 + v1 * v1 + v2 * v2;
    #pragma unroll
    for (int o = 16; o > 0; o >>= 1) {
        s += __shfl_down_sync(0xffffffffu, s, o);
        q += __shfl_down_sync(0xffffffffu, q, o);
    }
    __shared__ float shs[4], shq[4];
    __shared__ float s_mean, s_inv;
    int w = t >> 5, lane = t & 31;
    if (lane == 0) { shs[w] = s; shq[w] = q; }
    __syncthreads();
    if (t == 0) {
        float S = shs[0] + shs[1] + shs[2] + shs[3];
        float Q = shq[0] + shq[1] + shq[2] + shq[3];
        float m = S * (1.0f / 384.0f);
        float var = Q * (1.0f / 384.0f) - m * m;
        s_mean = m;
        s_inv  = rsqrtf(var + 1e-5f);
    }
    __syncthreads();
    float m = s_mean, inv = s_inv;
    yr[t]       = rndtf((v0 - m) * inv * gamma[t]       + beta[t]);
    yr[t + 128] = rndtf((v1 - m) * inv * gamma[t + 128] + beta[t + 128]);
    yr[t + 256] = rndtf((v2 - m) * inv * gamma[t + 256] + beta[t + 256]);
}

// ---------------- driver ----------------
extern "C" void kernel_launch(void* const* d_in, const int* in_sizes, int n_in,
                              void* d_out, int out_size) {
    const float* x_in  = (const float*)d_in[0];
    const float* ln1_g = (const float*)d_in[1];
    const float* ln1_b = (const float*)d_in[2];
    const float* qkv_w = (const float*)d_in[3];
    const float* temp  = (const float*)d_in[4];
    const float* out_w = (const float*)d_in[5];
    const float* out_b = (const float*)d_in[6];
    const float* ln2_g = (const float*)d_in[7];
    const float* ln2_b = (const float*)d_in[8];
    const float* ff_w1 = (const float*)d_in[9];
    const float* ff_b1 = (const float*)d_in[10];
    const float* ff_w2 = (const float*)d_in[11];
    const float* ff_b2 = (const float*)d_in[12];
    float* x = (float*)d_out;

    float *p_ln, *p_qkv, *p_attn, *p_ff, *p_wt;
    cudaGetSymbolAddress((void**)&p_ln,   g_ln);
    cudaGetSymbolAddress((void**)&p_qkv,  g_qkv);
    cudaGetSymbolAddress((void**)&p_attn, g_attn);
    cudaGetSymbolAddress((void**)&p_ff,   g_ff);
    cudaGetSymbolAddress((void**)&p_wt,   g_wt);

    cudaFuncSetAttribute(mma_gemm<0>, cudaFuncAttributeMaxDynamicSharedMemorySize, GS_BYTES);
    cudaFuncSetAttribute(mma_gemm<1>, cudaFuncAttributeMaxDynamicSharedMemorySize, GS_BYTES);
    cudaFuncSetAttribute(mma_gemm<2>, cudaFuncAttributeMaxDynamicSharedMemorySize, GS_BYTES);
    cudaFuncSetAttribute(flash_kernel, cudaFuncAttributeMaxDynamicSharedMemorySize, FL_DSMEM);

    cudaMemcpyAsync(x, x_in, (size_t)ROWS * DIMV * sizeof(float),
                    cudaMemcpyDeviceToDevice);

    transpose_kernel<<<dim3(QKVW / 32, DIMV / 32, DEPTH), dim3(32, 8)>>>(
        qkv_w, p_wt + WT_QKV_OFF, DIMV, QKVW);
    transpose_kernel<<<dim3(DIMV / 32, INNER / 32, DEPTH), dim3(32, 8)>>>(
        out_w, p_wt + WT_WO_OFF, INNER, DIMV);
    transpose_kernel<<<dim3(MLPV / 32, DIMV / 32, DEPTH), dim3(32, 8)>>>(
        ff_w1, p_wt + WT_W1_OFF, DIMV, MLPV);
    transpose_kernel<<<dim3(DIMV / 32, MLPV / 32, DEPTH), dim3(32, 8)>>>(
        ff_w2, p_wt + WT_W2_OFF, MLPV, DIMV);

    for (int l = 0; l < DEPTH; l++) {
        // --- attention block ---
        ln_kernel<<<ROWS, 128>>>(x, ln1_g + l * DIMV, ln1_b + l * DIMV, p_ln);
        mma_gemm<0><<<dim3(QKVW / 128, ROWS / 128), 256, GS_BYTES>>>(
            p_ln, p_wt + WT_QKV_OFF + (size_t)l * WT_QKV_PER,
            nullptr, nullptr, p_qkv, ROWS, QKVW, DIMV);
        flash_kernel<<<dim3(NN / 128, BHN), 256, FL_DSMEM>>>(p_qkv, p_attn, temp, l);
        mma_gemm<1><<<dim3(DIMV / 128, ROWS / 128), 256, GS_BYTES>>>(
            p_attn, p_wt + WT_WO_OFF + (size_t)l * WT_WO_PER,
            out_b + l * DIMV, x, x, ROWS, DIMV, INNER);
        // --- feed-forward block ---
        ln_kernel<<<ROWS, 128>>>(x, ln2_g + l * DIMV, ln2_b + l * DIMV, p_ln);
        mma_gemm<2><<<dim3(MLPV / 128, ROWS / 128), 256, GS_BYTES>>>(
            p_ln, p_wt + WT_W1_OFF + (size_t)l * WT_W1_PER,
            ff_b1 + l * MLPV, nullptr, p_ff, ROWS, MLPV, DIMV);
        mma_gemm<1><<<dim3(DIMV / 128, ROWS / 128), 256, GS_BYTES>>>(
            p_ff, p_wt + WT_W2_OFF + (size_t)l * WT_W2_PER,
            ff_b2 + l * DIMV, x, x, ROWS, DIMV, MLPV);
    }
}

// round 7
// speedup vs baseline: 5.4867x; 1.5321x over previous
#include <cuda_runtime.h>
#include <cuda_fp16.h>
#include <math.h>
#include <stdint.h>

#define BB     16
#define NN     1024
#define DIMV   384
#define DEPTH  6
#define HEADS  6
#define DH     64
#define INNER  384
#define MLPV   1536
#define ROWS   (BB*NN)       // 16384
#define BHN    (BB*HEADS)    // 96
#define QKVW   (3*INNER)     // 1152
#define NEGMAX -3.4028234663852886e38f

// ---------------- scratch (half precision operands) ----------------
__device__ __half g_ln[(size_t)ROWS * DIMV];
__device__ __half g_qkv[(size_t)ROWS * QKVW];
__device__ __half g_attn[(size_t)ROWS * INNER];
__device__ __half g_ff[(size_t)ROWS * MLPV];
#define WT_QKV_OFF  0
#define WT_QKV_PER  (QKVW*DIMV)
#define WT_WO_OFF   (WT_QKV_OFF + DEPTH*WT_QKV_PER)
#define WT_WO_PER   (DIMV*INNER)
#define WT_W1_OFF   (WT_WO_OFF + DEPTH*WT_WO_PER)
#define WT_W1_PER   (MLPV*DIMV)
#define WT_W2_OFF   (WT_W1_OFF + DEPTH*WT_W1_PER)
#define WT_W2_PER   (DIMV*MLPV)
__device__ __half g_wt[(size_t)(WT_W2_OFF + DEPTH*WT_W2_PER)];

// ================= helpers =================
__device__ __forceinline__ uint32_t smem_u32(const void* p) {
    uint32_t r;
    asm("{ .reg .u64 t; cvta.to.shared.u64 t, %1; cvt.u32.u64 %0, t; }" : "=r"(r) : "l"(p));
    return r;
}
__device__ __forceinline__ void cp16(uint32_t dst, const void* src) {
    asm volatile("cp.async.cg.shared.global [%0], [%1], 16;" :: "r"(dst), "l"(src));
}
// m16n8k16 fp16 MMA, fp32 accumulate
__device__ __forceinline__ void mma16(float c[4], const uint32_t a[4], const uint32_t b[2]) {
    asm volatile(
        "mma.sync.aligned.m16n8k16.row.col.f32.f16.f16.f32 "
        "{%0,%1,%2,%3}, {%4,%5,%6,%7}, {%8,%9}, {%0,%1,%2,%3};"
        : "+f"(c[0]), "+f"(c[1]), "+f"(c[2]), "+f"(c[3])
        : "r"(a[0]), "r"(a[1]), "r"(a[2]), "r"(a[3]), "r"(b[0]), "r"(b[1]));
}

// ================= dense fp16 GEMM: C[M,Nn] = A[M,K] @ Bt[Nn,K]^T =================
// A, Bt are half. 128x128 CTA tile, 256 thr = 8 warps (2m x 4n), warp tile 64x32,
// BK=32, 3-stage cp.async. Smem rows: 40 halves (20 words) -> conflict-free frags.
// EPI 0: C(half) = AB ; EPI 1: C(f32) = res + AB + bias ; EPI 2: C(half) = gelu(AB+bias)
#define GS_STAGE_H  10240u                    // halves per stage (A 128x40 + B 128x40)
#define GS_STAGE_B  (GS_STAGE_H * 2u)         // 20480 B
#define GS_BYTES    (3u * GS_STAGE_B)         // 61440 B
template <int EPI>
__global__ void __launch_bounds__(256, 2) mma_gemm(
    const __half* __restrict__ A, const __half* __restrict__ Bt,
    const float* __restrict__ bias, const float* __restrict__ res,
    void* __restrict__ Cv, int M, int Nn, int K) {
    extern __shared__ __align__(16) char smraw[];
    __half* smh = (__half*)smraw;
    const int tid = threadIdx.x;
    const int wid = tid >> 5, lane = tid & 31;
    const int g = lane >> 2, tg = lane & 3;
    const int wm = (wid & 1) * 64, wn = (wid >> 1) * 32;
    const int m0 = blockIdx.y * 128, n0 = blockIdx.x * 128;

    float c[4][4][4];
    #pragma unroll
    for (int mt = 0; mt < 4; ++mt)
        #pragma unroll
        for (int nt = 0; nt < 4; ++nt)
            #pragma unroll
            for (int k = 0; k < 4; ++k) c[mt][nt][k] = 0.0f;

    const int nc = K >> 5;                    // chunks of 32 halves
    const uint32_t sbase = smem_u32(smh);

    auto issue = [&](int ci) {
        uint32_t base = sbase + (uint32_t)(ci % 3) * GS_STAGE_B;
        int kt = ci << 5;
        #pragma unroll
        for (int i = 0; i < 2; ++i) {
            int f = tid + i * 256;            // 0..511
            int r = f >> 2, c8 = (f & 3) << 3;
            cp16(base + (uint32_t)(r * 40 + c8) * 2u,
                 A + (size_t)(m0 + r) * K + kt + c8);
        }
        #pragma unroll
        for (int i = 0; i < 2; ++i) {
            int f = tid + i * 256;
            int r = f >> 2, c8 = (f & 3) << 3;
            cp16(base + 10240u + (uint32_t)(r * 40 + c8) * 2u,
                 Bt + (size_t)(n0 + r) * K + kt + c8);
        }
        asm volatile("cp.async.commit_group;" ::: "memory");
    };

    issue(0);
    issue(1);

    for (int ci = 0; ci < nc; ++ci) {
        if (ci + 2 < nc) {
            issue(ci + 2);
        } else {
            asm volatile("cp.async.commit_group;" ::: "memory");
        }
        asm volatile("cp.async.wait_group 2;" ::: "memory");
        __syncthreads();

        const uint32_t* sAw = (const uint32_t*)(smh + (ci % 3) * GS_STAGE_H);
        const uint32_t* sBw = sAw + 2560;     // 5120 halves
        #pragma unroll
        for (int ks = 0; ks < 2; ++ks) {      // two k16 steps per 32-chunk
            const int kw = ks * 8;            // word offset
            uint32_t af[4][4], bf[4][2];
            #pragma unroll
            for (int mt = 0; mt < 4; ++mt) {
                int r = wm + mt * 16 + g;
                af[mt][0] = sAw[r * 20 + kw + tg];
                af[mt][1] = sAw[(r + 8) * 20 + kw + tg];
                af[mt][2] = sAw[r * 20 + kw + tg + 4];
                af[mt][3] = sAw[(r + 8) * 20 + kw + tg + 4];
            }
            #pragma unroll
            for (int nt = 0; nt < 4; ++nt) {
                int r = wn + nt * 8 + g;
                bf[nt][0] = sBw[r * 20 + kw + tg];
                bf[nt][1] = sBw[r * 20 + kw + tg + 4];
            }
            #pragma unroll
            for (int mt = 0; mt < 4; ++mt)
                #pragma unroll
                for (int nt = 0; nt < 4; ++nt)
                    mma16(c[mt][nt], af[mt], bf[nt]);
        }
        __syncthreads();
    }

    #pragma unroll
    for (int mt = 0; mt < 4; ++mt) {
        #pragma unroll
        for (int nt = 0; nt < 4; ++nt) {
            int col = n0 + wn + nt * 8 + 2 * tg;
            #pragma unroll
            for (int h = 0; h < 2; ++h) {
                int row = m0 + wm + mt * 16 + g + h * 8;
                float v0 = c[mt][nt][h * 2 + 0];
                float v1 = c[mt][nt][h * 2 + 1];
                if (EPI >= 1) { v0 += bias[col]; v1 += bias[col + 1]; }
                if (EPI == 1) {
                    float2 r2 = *(const float2*)(res + (size_t)row * Nn + col);
                    v0 += r2.x; v1 += r2.y;
                    *(float2*)((float*)Cv + (size_t)row * Nn + col) = make_float2(v0, v1);
                } else {
                    if (EPI == 2) {
                        v0 = 0.5f * v0 * (1.0f + erff(v0 * 0.70710678118654752f));
                        v1 = 0.5f * v1 * (1.0f + erff(v1 * 0.70710678118654752f));
                    }
                    *(__half2*)((__half*)Cv + (size_t)row * Nn + col) =
                        __floats2half2_rn(v0, v1);
                }
            }
        }
    }
}

// ================= flash attention (fp16 operands, fp32 softmax/accum) =============
// Smem: Ps 128x72h (Q stage, then P), Ks 64x72h, Vt 64x72h (transposed [dh][tok]).
#define FL_DSMEM ((128*72 + 64*72 + 64*72) * 2)   // 36864 B
__global__ void __launch_bounds__(256, 2) flash_kernel(
    const __half* __restrict__ qkv,
    __half* __restrict__ o,
    const float* __restrict__ temp, int layer) {
    extern __shared__ __align__(16) __half fsh[];
    __half* Ps = fsh;                   // 128*72
    __half* Ks = fsh + 128 * 72;        // 64*72
    __half* Vt = Ks + 64 * 72;          // 64*72
    uint32_t* Pw = (uint32_t*)Ps;
    uint32_t* Kw = (uint32_t*)Ks;
    uint32_t* Vw = (uint32_t*)Vt;

    int bh = blockIdx.y;
    int b = bh / HEADS, h = bh - b * HEADS;
    int rt = blockIdx.x * 128;
    int tid = threadIdx.x, wid = tid >> 5, lane = tid & 31;
    int g = lane >> 2, tg = lane & 3;

    const __half* qb = qkv + (size_t)b * NN * QKVW + h * DH;
    const __half* kb = qb + INNER;
    const __half* vb = qb + 2 * INNER;

    // stage Q tile (128 x 64 halves), then lift to A-fragments (4 k16 steps)
    #pragma unroll
    for (int i = 0; i < 4; ++i) {
        int f = tid + i * 256;
        int r = f >> 3, c8 = (f & 7) << 3;
        *(uint4*)&Ps[r * 72 + c8] = *(const uint4*)(qb + (size_t)(rt + r) * QKVW + c8);
    }
    __syncthreads();
    uint32_t qf[4][4];
    {
        int r = wid * 16 + g;
        #pragma unroll
        for (int ks = 0; ks < 4; ++ks) {
            int kw = ks * 8;
            qf[ks][0] = Pw[r * 36 + kw + tg];
            qf[ks][1] = Pw[(r + 8) * 36 + kw + tg];
            qf[ks][2] = Pw[r * 36 + kw + tg + 4];
            qf[ks][3] = Pw[(r + 8) * 36 + kw + tg + 4];
        }
    }

    float scale = expf(temp[layer]);
    float m0 = NEGMAX, m1 = NEGMAX, l0 = 0.0f, l1 = 0.0f;
    float oacc[8][4];
    #pragma unroll
    for (int nt = 0; nt < 8; ++nt)
        #pragma unroll
        for (int k = 0; k < 4; ++k) oacc[nt][k] = 0.0f;

    const int gi0 = rt + wid * 16 + g;
    const int gi1 = gi0 + 8;
    const int prow = wid * 16 + g;

    for (int kt = 0; kt < NN; kt += 64) {
        __syncthreads();
        // K tile 64x64 halves
        #pragma unroll
        for (int i = 0; i < 2; ++i) {
            int f = tid + i * 256;
            int r = f >> 3, c8 = (f & 7) << 3;
            *(uint4*)&Ks[r * 72 + c8] = *(const uint4*)(kb + (size_t)(kt + r) * QKVW + c8);
        }
        // V tile transposed -> Vt[dh][tok]
        #pragma unroll
        for (int i = 0; i < 2; ++i) {
            int f = tid + i * 256;
            int r = f >> 3, c8 = (f & 7) << 3;
            uint4 v = *(const uint4*)(vb + (size_t)(kt + r) * QKVW + c8);
            const __half* vh = (const __half*)&v;
            #pragma unroll
            for (int j = 0; j < 8; ++j) Vt[(c8 + j) * 72 + r] = vh[j];
        }
        __syncthreads();

        // S = Q K^T  (16x64 per warp), 4 k16 steps
        float s[8][4];
        #pragma unroll
        for (int nt = 0; nt < 8; ++nt)
            #pragma unroll
            for (int k = 0; k < 4; ++k) s[nt][k] = 0.0f;
        #pragma unroll
        for (int ks = 0; ks < 4; ++ks) {
            int kw = ks * 8;
            #pragma unroll
            for (int nt = 0; nt < 8; ++nt) {
                int rn = nt * 8 + g;
                uint32_t bf[2];
                bf[0] = Kw[rn * 36 + kw + tg];
                bf[1] = Kw[rn * 36 + kw + tg + 4];
                mma16(s[nt], qf[ks], bf);
            }
        }
        // scale + LSA diagonal mask
        #pragma unroll
        for (int nt = 0; nt < 8; ++nt) {
            int gj = kt + nt * 8 + 2 * tg;
            s[nt][0] *= scale; s[nt][1] *= scale; s[nt][2] *= scale; s[nt][3] *= scale;
            if (gi0 == gj)     s[nt][0] = NEGMAX;
            if (gi0 == gj + 1) s[nt][1] = NEGMAX;
            if (gi1 == gj)     s[nt][2] = NEGMAX;
            if (gi1 == gj + 1) s[nt][3] = NEGMAX;
        }
        float mx0 = NEGMAX, mx1 = NEGMAX;
        #pragma unroll
        for (int nt = 0; nt < 8; ++nt) {
            mx0 = fmaxf(mx0, fmaxf(s[nt][0], s[nt][1]));
            mx1 = fmaxf(mx1, fmaxf(s[nt][2], s[nt][3]));
        }
        mx0 = fmaxf(mx0, __shfl_xor_sync(0xffffffffu, mx0, 1));
        mx0 = fmaxf(mx0, __shfl_xor_sync(0xffffffffu, mx0, 2));
        mx1 = fmaxf(mx1, __shfl_xor_sync(0xffffffffu, mx1, 1));
        mx1 = fmaxf(mx1, __shfl_xor_sync(0xffffffffu, mx1, 2));
        float mn0 = fmaxf(m0, mx0), mn1 = fmaxf(m1, mx1);
        float r0 = __expf(m0 - mn0), r1 = __expf(m1 - mn1);
        float sum0 = 0.0f, sum1 = 0.0f;
        #pragma unroll
        for (int nt = 0; nt < 8; ++nt) {
            float p0 = __expf(s[nt][0] - mn0);
            float p1 = __expf(s[nt][1] - mn0);
            float p2 = __expf(s[nt][2] - mn1);
            float p3 = __expf(s[nt][3] - mn1);
            sum0 += p0 + p1;
            sum1 += p2 + p3;
            int col = nt * 8 + 2 * tg;
            *(__half2*)&Ps[prow * 72 + col] = __floats2half2_rn(p0, p1);
            *(__half2*)&Ps[(prow + 8) * 72 + col] = __floats2half2_rn(p2, p3);
        }
        sum0 += __shfl_xor_sync(0xffffffffu, sum0, 1);
        sum0 += __shfl_xor_sync(0xffffffffu, sum0, 2);
        sum1 += __shfl_xor_sync(0xffffffffu, sum1, 1);
        sum1 += __shfl_xor_sync(0xffffffffu, sum1, 2);
        l0 = l0 * r0 + sum0;
        l1 = l1 * r1 + sum1;
        m0 = mn0; m1 = mn1;
        #pragma unroll
        for (int nt = 0; nt < 8; ++nt) {
            oacc[nt][0] *= r0; oacc[nt][1] *= r0;
            oacc[nt][2] *= r1; oacc[nt][3] *= r1;
        }
        __syncwarp();
        // O += P @ V   (P 16x64 per warp, 4 k16 steps)
        #pragma unroll
        for (int ks = 0; ks < 4; ++ks) {
            int kw = ks * 8;
            uint32_t af[4];
            af[0] = Pw[prow * 36 + kw + tg];
            af[1] = Pw[(prow + 8) * 36 + kw + tg];
            af[2] = Pw[prow * 36 + kw + tg + 4];
            af[3] = Pw[(prow + 8) * 36 + kw + tg + 4];
            #pragma unroll
            for (int nt = 0; nt < 8; ++nt) {
                int rn = nt * 8 + g;
                uint32_t bf[2];
                bf[0] = Vw[rn * 36 + kw + tg];
                bf[1] = Vw[rn * 36 + kw + tg + 4];
                mma16(oacc[nt], af, bf);
            }
        }
    }

    float inv0 = 1.0f / l0, inv1 = 1.0f / l1;
    #pragma unroll
    for (int nt = 0; nt < 8; ++nt) {
        int gc = h * DH + nt * 8 + 2 * tg;
        int gr0 = b * NN + gi0;
        int gr1 = b * NN + gi1;
        *(__half2*)(o + (size_t)gr0 * INNER + gc) =
            __floats2half2_rn(oacc[nt][0] * inv0, oacc[nt][1] * inv0);
        *(__half2*)(o + (size_t)gr1 * INNER + gc) =
            __floats2half2_rn(oacc[nt][2] * inv1, oacc[nt][3] * inv1);
    }
}

// ---------------- weight transpose fp32 -> half ----------------
__global__ void transpose_kernel(const float* __restrict__ src, __half* __restrict__ dst,
                                 int K, int N) {
    __shared__ float t[32][33];
    int z = blockIdx.z;
    src += (size_t)z * K * N;
    dst += (size_t)z * K * N;
    int k0 = blockIdx.y * 32, n0 = blockIdx.x * 32;
    int tx = threadIdx.x, ty = threadIdx.y;
    #pragma unroll
    for (int j = 0; j < 32; j += 8)
        t[ty + j][tx] = src[(size_t)(k0 + ty + j) * N + n0 + tx];
    __syncthreads();
    #pragma unroll
    for (int j = 0; j < 32; j += 8)
        dst[(size_t)(n0 + ty + j) * K + k0 + tx] = __float2half_rn(t[tx][ty + j]);
}

// ---------------- LayerNorm fp32 -> half ----------------
__global__ void ln_kernel(const float* __restrict__ x,
                          const float* __restrict__ gamma,
                          const float* __restrict__ beta,
                          __half* __restrict__ y) {
    int row = blockIdx.x;
    const float* xr = x + (size_t)row * DIMV;
    __half*      yr = y + (size_t)row * DIMV;
    int t = threadIdx.x;
    float v0 = xr[t], v1 = xr[t + 128], v2 = xr[t + 256];
    float s = v0 + v1 + v2;
    float q = v0 * v0 + v1 * v1 + v2 * v2;
    #pragma unroll
    for (int o = 16; o > 0; o >>= 1) {
        s += __shfl_down_sync(0xffffffffu, s, o);
        q += __shfl_down_sync(0xffffffffu, q, o);
    }
    __shared__ float shs[4], shq[4];
    __shared__ float s_mean, s_inv;
    int w = t >> 5, lane = t & 31;
    if (lane == 0) { shs[w] = s; shq[w] = q; }
    __syncthreads();
    if (t == 0) {
        float S = shs[0] + shs[1] + shs[2] + shs[3];
        float Q = shq[0] + shq[1] + shq[2] + shq[3];
        float m = S * (1.0f / 384.0f);
        float var = Q * (1.0f / 384.0f) - m * m;
        s_mean = m;
        s_inv  = rsqrtf(var + 1e-5f);
    }
    __syncthreads();
    float m = s_mean, inv = s_inv;
    yr[t]       = __float2half_rn((v0 - m) * inv * gamma[t]       + beta[t]);
    yr[t + 128] = __float2half_rn((v1 - m) * inv * gamma[t + 128] + beta[t + 128]);
    yr[t + 256] = __float2half_rn((v2 - m) * inv * gamma[t + 256] + beta[t + 256]);
}

// ---------------- driver ----------------
extern "C" void kernel_launch(void* const* d_in, const int* in_sizes, int n_in,
                              void* d_out, int out_size) {
    const float* x_in  = (const float*)d_in[0];
    const float* ln1_g = (const float*)d_in[1];
    const float* ln1_b = (const float*)d_in[2];
    const float* qkv_w = (const float*)d_in[3];
    const float* temp  = (const float*)d_in[4];
    const float* out_w = (const float*)d_in[5];
    const float* out_b = (const float*)d_in[6];
    const float* ln2_g = (const float*)d_in[7];
    const float* ln2_b = (const float*)d_in[8];
    const float* ff_w1 = (const float*)d_in[9];
    const float* ff_b1 = (const float*)d_in[10];
    const float* ff_w2 = (const float*)d_in[11];
    const float* ff_b2 = (const float*)d_in[12];
    float* x = (float*)d_out;

    __half *p_ln, *p_qkv, *p_attn, *p_ff, *p_wt;
    cudaGetSymbolAddress((void**)&p_ln,   g_ln);
    cudaGetSymbolAddress((void**)&p_qkv,  g_qkv);
    cudaGetSymbolAddress((void**)&p_attn, g_attn);
    cudaGetSymbolAddress((void**)&p_ff,   g_ff);
    cudaGetSymbolAddress((void**)&p_wt,   g_wt);

    cudaFuncSetAttribute(mma_gemm<0>, cudaFuncAttributeMaxDynamicSharedMemorySize, GS_BYTES);
    cudaFuncSetAttribute(mma_gemm<1>, cudaFuncAttributeMaxDynamicSharedMemorySize, GS_BYTES);
    cudaFuncSetAttribute(mma_gemm<2>, cudaFuncAttributeMaxDynamicSharedMemorySize, GS_BYTES);
    cudaFuncSetAttribute(flash_kernel, cudaFuncAttributeMaxDynamicSharedMemorySize, FL_DSMEM);

    cudaMemcpyAsync(x, x_in, (size_t)ROWS * DIMV * sizeof(float),
                    cudaMemcpyDeviceToDevice);

    transpose_kernel<<<dim3(QKVW / 32, DIMV / 32, DEPTH), dim3(32, 8)>>>(
        qkv_w, p_wt + WT_QKV_OFF, DIMV, QKVW);
    transpose_kernel<<<dim3(DIMV / 32, INNER / 32, DEPTH), dim3(32, 8)>>>(
        out_w, p_wt + WT_WO_OFF, INNER, DIMV);
    transpose_kernel<<<dim3(MLPV / 32, DIMV / 32, DEPTH), dim3(32, 8)>>>(
        ff_w1, p_wt + WT_W1_OFF, DIMV, MLPV);
    transpose_kernel<<<dim3(DIMV / 32, MLPV / 32, DEPTH), dim3(32, 8)>>>(
        ff_w2, p_wt + WT_W2_OFF, MLPV, DIMV);

    for (int l = 0; l < DEPTH; l++) {
        // --- attention block ---
        ln_kernel<<<ROWS, 128>>>(x, ln1_g + l * DIMV, ln1_b + l * DIMV, p_ln);
        mma_gemm<0><<<dim3(QKVW / 128, ROWS / 128), 256, GS_BYTES>>>(
            p_ln, p_wt + WT_QKV_OFF + (size_t)l * WT_QKV_PER,
            nullptr, nullptr, p_qkv, ROWS, QKVW, DIMV);
        flash_kernel<<<dim3(NN / 128, BHN), 256, FL_DSMEM>>>(p_qkv, p_attn, temp, l);
        mma_gemm<1><<<dim3(DIMV / 128, ROWS / 128), 256, GS_BYTES>>>(
            p_attn, p_wt + WT_WO_OFF + (size_t)l * WT_WO_PER,
            out_b + l * DIMV, x, x, ROWS, DIMV, INNER);
        // --- feed-forward block ---
        ln_kernel<<<ROWS, 128>>>(x, ln2_g + l * DIMV, ln2_b + l * DIMV, p_ln);
        mma_gemm<2><<<dim3(MLPV / 128, ROWS / 128), 256, GS_BYTES>>>(
            p_ln, p_wt + WT_W1_OFF + (size_t)l * WT_W1_PER,
            ff_b1 + l * MLPV, nullptr, p_ff, ROWS, MLPV, DIMV);
        mma_gemm<1><<<dim3(DIMV / 128, ROWS / 128), 256, GS_BYTES>>>(
            p_ff, p_wt + WT_W2_OFF + (size_t)l * WT_W2_PER,
            ff_b2 + l * DIMV, x, x, ROWS, DIMV, MLPV);
    }
}

// round 10
// speedup vs baseline: 6.5212x; 1.1885x over previous
#include <cuda_runtime.h>
#include <cuda_fp16.h>
#include <math.h>
#include <stdint.h>
#include <string.h>

#define BB     16
#define NN     1024
#define DIMV   384
#define DEPTH  6
#define HEADS  6
#define DH     64
#define INNER  384
#define MLPV   1536
#define ROWS   (BB*NN)       // 16384
#define BHN    (BB*HEADS)    // 96
#define QKVW   (3*INNER)     // 1152
#define NEGMAX -3.4028234663852886e38f

// ---------------- scratch (half precision operands) ----------------
__device__ __half g_ln[(size_t)ROWS * DIMV];
__device__ __half g_qkv[(size_t)ROWS * QKVW];
__device__ __half g_attn[(size_t)ROWS * INNER];
__device__ __half g_ff[(size_t)ROWS * MLPV];
#define WT_QKV_OFF  0
#define WT_QKV_PER  (QKVW*DIMV)
#define WT_WO_OFF   (WT_QKV_OFF + DEPTH*WT_QKV_PER)
#define WT_WO_PER   (DIMV*INNER)
#define WT_W1_OFF   (WT_WO_OFF + DEPTH*WT_WO_PER)
#define WT_W1_PER   (MLPV*DIMV)
#define WT_W2_OFF   (WT_W1_OFF + DEPTH*WT_W1_PER)
#define WT_W2_PER   (DIMV*MLPV)
__device__ __half g_wt[(size_t)(WT_W2_OFF + DEPTH*WT_W2_PER)];

// ================= helpers =================
__device__ __forceinline__ uint32_t smem_u32(const void* p) {
    uint32_t r;
    asm("{ .reg .u64 t; cvta.to.shared.u64 t, %1; cvt.u32.u64 %0, t; }" : "=r"(r) : "l"(p));
    return r;
}
__device__ __forceinline__ void cp16(uint32_t dst, const void* src) {
    asm volatile("cp.async.cg.shared.global [%0], [%1], 16;" :: "r"(dst), "l"(src));
}
__device__ __forceinline__ void mma16(float c[4], const uint32_t a[4], const uint32_t b[2]) {
    asm volatile(
        "mma.sync.aligned.m16n8k16.row.col.f32.f16.f16.f32 "
        "{%0,%1,%2,%3}, {%4,%5,%6,%7}, {%8,%9}, {%0,%1,%2,%3};"
        : "+f"(c[0]), "+f"(c[1]), "+f"(c[2]), "+f"(c[3])
        : "r"(a[0]), "r"(a[1]), "r"(a[2]), "r"(a[3]), "r"(b[0]), "r"(b[1]));
}
__device__ __forceinline__ void ldm_x4(uint32_t r[4], uint32_t a) {
    asm volatile("ldmatrix.sync.aligned.m8n8.x4.shared.b16 {%0,%1,%2,%3}, [%4];"
                 : "=r"(r[0]), "=r"(r[1]), "=r"(r[2]), "=r"(r[3]) : "r"(a));
}
__device__ __forceinline__ void ldm_x2(uint32_t r[2], uint32_t a) {
    asm volatile("ldmatrix.sync.aligned.m8n8.x2.shared.b16 {%0,%1}, [%2];"
                 : "=r"(r[0]), "=r"(r[1]) : "r"(a));
}
__device__ __forceinline__ void ldm_x2t(uint32_t r[2], uint32_t a) {
    asm volatile("ldmatrix.sync.aligned.m8n8.x2.trans.shared.b16 {%0,%1}, [%2];"
                 : "=r"(r[0]), "=r"(r[1]) : "r"(a));
}
__device__ __forceinline__ uint32_t packh2(float x, float y) {
    __half2 h = __floats2half2_rn(x, y);
    uint32_t u;
    memcpy(&u, &h, 4);
    return u;
}

// ================= dense fp16 GEMM: C[M,Nn] = A[M,K] @ Bt[Nn,K]^T =================
// 128x128 CTA tile, 256 thr = 8 warps (2m x 4n), warp tile 64x32, BK=32,
// 3-stage cp.async, ldmatrix fragment loads. Stage = A(10240 B) + B(10240 B).
#define GS_STAGE_H  10240u
#define GS_STAGE_B  (GS_STAGE_H * 2u)         // 20480 B
#define GS_BYTES    (3u * GS_STAGE_B)         // 61440 B
template <int EPI>
__global__ void __launch_bounds__(256, 2) mma_gemm(
    const __half* __restrict__ A, const __half* __restrict__ Bt,
    const float* __restrict__ bias, const float* __restrict__ res,
    void* __restrict__ Cv, int M, int Nn, int K) {
    extern __shared__ __align__(16) char smraw[];
    __half* smh = (__half*)smraw;
    const int tid = threadIdx.x;
    const int wid = tid >> 5, lane = tid & 31;
    const int g = lane >> 2, tg = lane & 3;
    const int l16 = lane & 15;
    const int wm = (wid & 1) * 64, wn = (wid >> 1) * 32;
    const int m0 = blockIdx.y * 128, n0 = blockIdx.x * 128;

    float c[4][4][4];
    #pragma unroll
    for (int mt = 0; mt < 4; ++mt)
        #pragma unroll
        for (int nt = 0; nt < 4; ++nt)
            #pragma unroll
            for (int k = 0; k < 4; ++k) c[mt][nt][k] = 0.0f;

    const int nc = K >> 5;
    const uint32_t sbase = smem_u32(smh);

    auto issue = [&](int ci) {
        uint32_t base = sbase + (uint32_t)(ci % 3) * GS_STAGE_B;
        int kt = ci << 5;
        #pragma unroll
        for (int i = 0; i < 2; ++i) {
            int f = tid + i * 256;
            int r = f >> 2, c8 = (f & 3) << 3;
            cp16(base + (uint32_t)(r * 40 + c8) * 2u,
                 A + (size_t)(m0 + r) * K + kt + c8);
        }
        #pragma unroll
        for (int i = 0; i < 2; ++i) {
            int f = tid + i * 256;
            int r = f >> 2, c8 = (f & 3) << 3;
            cp16(base + 10240u + (uint32_t)(r * 40 + c8) * 2u,
                 Bt + (size_t)(n0 + r) * K + kt + c8);
        }
        asm volatile("cp.async.commit_group;" ::: "memory");
    };

    issue(0);
    issue(1);

    for (int ci = 0; ci < nc; ++ci) {
        if (ci + 2 < nc) {
            issue(ci + 2);
        } else {
            asm volatile("cp.async.commit_group;" ::: "memory");
        }
        asm volatile("cp.async.wait_group 2;" ::: "memory");
        __syncthreads();

        const uint32_t stA = sbase + (uint32_t)(ci % 3) * GS_STAGE_B;
        const uint32_t stB = stA + 10240u;
        #pragma unroll
        for (int ks = 0; ks < 2; ++ks) {
            uint32_t af[4][4], bf[4][2];
            #pragma unroll
            for (int mt = 0; mt < 4; ++mt)
                ldm_x4(af[mt], stA + (uint32_t)((wm + mt * 16 + l16) * 40
                                                + ks * 16 + (lane >> 4) * 8) * 2u);
            #pragma unroll
            for (int nt = 0; nt < 4; ++nt)
                ldm_x2(bf[nt], stB + (uint32_t)((wn + nt * 8 + (l16 & 7)) * 40
                                                + ks * 16 + (l16 >> 3) * 8) * 2u);
            #pragma unroll
            for (int mt = 0; mt < 4; ++mt)
                #pragma unroll
                for (int nt = 0; nt < 4; ++nt)
                    mma16(c[mt][nt], af[mt], bf[nt]);
        }
        __syncthreads();
    }

    #pragma unroll
    for (int mt = 0; mt < 4; ++mt) {
        #pragma unroll
        for (int nt = 0; nt < 4; ++nt) {
            int col = n0 + wn + nt * 8 + 2 * tg;
            #pragma unroll
            for (int h = 0; h < 2; ++h) {
                int row = m0 + wm + mt * 16 + g + h * 8;
                float v0 = c[mt][nt][h * 2 + 0];
                float v1 = c[mt][nt][h * 2 + 1];
                if (EPI >= 1) { v0 += bias[col]; v1 += bias[col + 1]; }
                if (EPI == 1) {
                    float2 r2 = *(const float2*)(res + (size_t)row * Nn + col);
                    v0 += r2.x; v1 += r2.y;
                    *(float2*)((float*)Cv + (size_t)row * Nn + col) = make_float2(v0, v1);
                } else {
                    if (EPI == 2) {
                        v0 = 0.5f * v0 * (1.0f + erff(v0 * 0.70710678118654752f));
                        v1 = 0.5f * v1 * (1.0f + erff(v1 * 0.70710678118654752f));
                    }
                    *(__half2*)((__half*)Cv + (size_t)row * Nn + col) =
                        __floats2half2_rn(v0, v1);
                }
            }
        }
    }
}

// ================= flash attention (register-path P, cp.async KV, ldmatrix) ========
// Smem (halves): Q stage 128x72 | 2 x (K 64x72, V 64x72 row-major)
#define FL_PS_H    (128 * 72)
#define FL_KV_H    (64 * 72)
#define FL_TOT_H   (FL_PS_H + 4 * FL_KV_H)    // 27648
#define FL_DSMEM   (FL_TOT_H * 2)             // 55296 B
__global__ void __launch_bounds__(256, 2) flash_kernel(
    const __half* __restrict__ qkv,
    __half* __restrict__ o,
    const float* __restrict__ temp, int layer) {
    extern __shared__ __align__(16) __half fsh[];

    int bh = blockIdx.y;
    int b = bh / HEADS, h = bh - b * HEADS;
    int rt = blockIdx.x * 128;
    int tid = threadIdx.x, wid = tid >> 5, lane = tid & 31;
    int g = lane >> 2, tg = lane & 3;
    int l16 = lane & 15;

    const __half* qb = qkv + (size_t)b * NN * QKVW + h * DH;
    const __half* kb = qb + INNER;
    const __half* vb = qb + 2 * INNER;
    const uint32_t sbase = smem_u32(fsh);

    // ---- stage Q tile (128x64 halves) and lift to A-fragments ----
    #pragma unroll
    for (int i = 0; i < 4; ++i) {
        int f = tid + i * 256;
        int r = f >> 3, c8 = (f & 7) << 3;
        *(uint4*)&fsh[r * 72 + c8] = *(const uint4*)(qb + (size_t)(rt + r) * QKVW + c8);
    }
    // ---- prefetch KV tile 0 while Q settles ----
    auto issue_kv = [&](int i) {
        uint32_t kbb = sbase + (uint32_t)(FL_PS_H + (i & 1) * 2 * FL_KV_H) * 2u;
        uint32_t vbb = kbb + FL_KV_H * 2u;
        int kt = i << 6;
        #pragma unroll
        for (int it = 0; it < 2; ++it) {
            int f = tid + it * 256;
            int r = f >> 3, c8 = (f & 7) << 3;
            cp16(kbb + (uint32_t)(r * 72 + c8) * 2u, kb + (size_t)(kt + r) * QKVW + c8);
            cp16(vbb + (uint32_t)(r * 72 + c8) * 2u, vb + (size_t)(kt + r) * QKVW + c8);
        }
        asm volatile("cp.async.commit_group;" ::: "memory");
    };
    issue_kv(0);
    __syncthreads();                       // Q visible to all

    uint32_t qf[4][4];
    #pragma unroll
    for (int ks = 0; ks < 4; ++ks)
        ldm_x4(qf[ks], sbase + (uint32_t)((wid * 16 + l16) * 72
                                          + ks * 16 + (lane >> 4) * 8) * 2u);

    float scale = expf(temp[layer]);
    float m0 = NEGMAX, m1 = NEGMAX, l0 = 0.0f, l1 = 0.0f;
    float oacc[8][4];
    #pragma unroll
    for (int nt = 0; nt < 8; ++nt)
        #pragma unroll
        for (int k = 0; k < 4; ++k) oacc[nt][k] = 0.0f;

    const int gi0 = rt + wid * 16 + g;
    const int gi1 = gi0 + 8;

    for (int i = 0; i < NN / 64; ++i) {
        if (i + 1 < NN / 64) {
            issue_kv(i + 1);
        } else {
            asm volatile("cp.async.commit_group;" ::: "memory");
        }
        asm volatile("cp.async.wait_group 1;" ::: "memory");
        __syncthreads();

        const uint32_t kbb = sbase + (uint32_t)(FL_PS_H + (i & 1) * 2 * FL_KV_H) * 2u;
        const uint32_t vbb = kbb + FL_KV_H * 2u;
        const int kt = i << 6;

        // ---- S = Q K^T (16x64 per warp) ----
        float s[8][4];
        #pragma unroll
        for (int nt = 0; nt < 8; ++nt)
            #pragma unroll
            for (int k = 0; k < 4; ++k) s[nt][k] = 0.0f;
        #pragma unroll
        for (int ks = 0; ks < 4; ++ks) {
            #pragma unroll
            for (int nt = 0; nt < 8; ++nt) {
                uint32_t bf[2];
                ldm_x2(bf, kbb + (uint32_t)((nt * 8 + (l16 & 7)) * 72
                                            + ks * 16 + (l16 >> 3) * 8) * 2u);
                mma16(s[nt], qf[ks], bf);
            }
        }
        // ---- scale + LSA diag mask ----
        #pragma unroll
        for (int nt = 0; nt < 8; ++nt) {
            int gj = kt + nt * 8 + 2 * tg;
            s[nt][0] *= scale; s[nt][1] *= scale; s[nt][2] *= scale; s[nt][3] *= scale;
            if (gi0 == gj)     s[nt][0] = NEGMAX;
            if (gi0 == gj + 1) s[nt][1] = NEGMAX;
            if (gi1 == gj)     s[nt][2] = NEGMAX;
            if (gi1 == gj + 1) s[nt][3] = NEGMAX;
        }
        // ---- online softmax on fragments ----
        float mx0 = NEGMAX, mx1 = NEGMAX;
        #pragma unroll
        for (int nt = 0; nt < 8; ++nt) {
            mx0 = fmaxf(mx0, fmaxf(s[nt][0], s[nt][1]));
            mx1 = fmaxf(mx1, fmaxf(s[nt][2], s[nt][3]));
        }
        mx0 = fmaxf(mx0, __shfl_xor_sync(0xffffffffu, mx0, 1));
        mx0 = fmaxf(mx0, __shfl_xor_sync(0xffffffffu, mx0, 2));
        mx1 = fmaxf(mx1, __shfl_xor_sync(0xffffffffu, mx1, 1));
        mx1 = fmaxf(mx1, __shfl_xor_sync(0xffffffffu, mx1, 2));
        float mn0 = fmaxf(m0, mx0), mn1 = fmaxf(m1, mx1);
        float r0 = __expf(m0 - mn0), r1 = __expf(m1 - mn1);
        float sum0 = 0.0f, sum1 = 0.0f;
        #pragma unroll
        for (int nt = 0; nt < 8; ++nt) {
            s[nt][0] = __expf(s[nt][0] - mn0);
            s[nt][1] = __expf(s[nt][1] - mn0);
            s[nt][2] = __expf(s[nt][2] - mn1);
            s[nt][3] = __expf(s[nt][3] - mn1);
            sum0 += s[nt][0] + s[nt][1];
            sum1 += s[nt][2] + s[nt][3];
        }
        sum0 += __shfl_xor_sync(0xffffffffu, sum0, 1);
        sum0 += __shfl_xor_sync(0xffffffffu, sum0, 2);
        sum1 += __shfl_xor_sync(0xffffffffu, sum1, 1);
        sum1 += __shfl_xor_sync(0xffffffffu, sum1, 2);
        l0 = l0 * r0 + sum0;
        l1 = l1 * r1 + sum1;
        m0 = mn0; m1 = mn1;
        #pragma unroll
        for (int nt = 0; nt < 8; ++nt) {
            oacc[nt][0] *= r0; oacc[nt][1] *= r0;
            oacc[nt][2] *= r1; oacc[nt][3] *= r1;
        }
        // ---- O += P @ V : P stays in registers (S-frag == A-frag layout) ----
        #pragma unroll
        for (int ks = 0; ks < 4; ++ks) {
            uint32_t pf[4];
            pf[0] = packh2(s[2 * ks][0],     s[2 * ks][1]);
            pf[1] = packh2(s[2 * ks][2],     s[2 * ks][3]);
            pf[2] = packh2(s[2 * ks + 1][0], s[2 * ks + 1][1]);
            pf[3] = packh2(s[2 * ks + 1][2], s[2 * ks + 1][3]);
            #pragma unroll
            for (int nt = 0; nt < 8; ++nt) {
                uint32_t bf[2];
                ldm_x2t(bf, vbb + (uint32_t)((ks * 16 + l16) * 72 + nt * 8) * 2u);
                mma16(oacc[nt], pf, bf);
            }
        }
        __syncthreads();                   // done reading buf i%2
    }

    float inv0 = 1.0f / l0, inv1 = 1.0f / l1;
    #pragma unroll
    for (int nt = 0; nt < 8; ++nt) {
        int gc = h * DH + nt * 8 + 2 * tg;
        int gr0 = b * NN + gi0;
        int gr1 = b * NN + gi1;
        *(__half2*)(o + (size_t)gr0 * INNER + gc) =
            __floats2half2_rn(oacc[nt][0] * inv0, oacc[nt][1] * inv0);
        *(__half2*)(o + (size_t)gr1 * INNER + gc) =
            __floats2half2_rn(oacc[nt][2] * inv1, oacc[nt][3] * inv1);
    }
}

// ---------------- weight transpose fp32 -> half ----------------
__global__ void transpose_kernel(const float* __restrict__ src, __half* __restrict__ dst,
                                 int K, int N) {
    __shared__ float t[32][33];
    int z = blockIdx.z;
    src += (size_t)z * K * N;
    dst += (size_t)z * K * N;
    int k0 = blockIdx.y * 32, n0 = blockIdx.x * 32;
    int tx = threadIdx.x, ty = threadIdx.y;
    #pragma unroll
    for (int j = 0; j < 32; j += 8)
        t[ty + j][tx] = src[(size_t)(k0 + ty + j) * N + n0 + tx];
    __syncthreads();
    #pragma unroll
    for (int j = 0; j < 32; j += 8)
        dst[(size_t)(n0 + ty + j) * K + k0 + tx] = __float2half_rn(t[tx][ty + j]);
}

// ---------------- LayerNorm fp32 -> half ----------------
__global__ void ln_kernel(const float* __restrict__ x,
                          const float* __restrict__ gamma,
                          const float* __restrict__ beta,
                          __half* __restrict__ y) {
    int row = blockIdx.x;
    const float* xr = x + (size_t)row * DIMV;
    __half*      yr = y + (size_t)row * DIMV;
    int t = threadIdx.x;
    float v0 = xr[t], v1 = xr[t + 128], v2 = xr[t + 256];
    float s = v0 + v1 + v2;
    float q = v0 * v0 + v1 * v1 + v2 * v2;
    #pragma unroll
    for (int o = 16; o > 0; o >>= 1) {
        s += __shfl_down_sync(0xffffffffu, s, o);
        q += __shfl_down_sync(0xffffffffu, q, o);
    }
    __shared__ float shs[4], shq[4];
    __shared__ float s_mean, s_inv;
    int w = t >> 5, lane = t & 31;
    if (lane == 0) { shs[w] = s; shq[w] = q; }
    __syncthreads();
    if (t == 0) {
        float S = shs[0] + shs[1] + shs[2] + shs[3];
        float Q = shq[0] + shq[1] + shq[2] + shq[3];
        float m = S * (1.0f / 384.0f);
        float var = Q * (1.0f / 384.0f) - m * m;
        s_mean = m;
        s_inv  = rsqrtf(var + 1e-5f);
    }
    __syncthreads();
    float m = s_mean, inv = s_inv;
    yr[t]       = __float2half_rn((v0 - m) * inv * gamma[t]       + beta[t]);
    yr[t + 128] = __float2half_rn((v1 - m) * inv * gamma[t + 128] + beta[t + 128]);
    yr[t + 256] = __float2half_rn((v2 - m) * inv * gamma[t + 256] + beta[t + 256]);
}

// ---------------- driver ----------------
extern "C" void kernel_launch(void* const* d_in, const int* in_sizes, int n_in,
                              void* d_out, int out_size) {
    const float* x_in  = (const float*)d_in[0];
    const float* ln1_g = (const float*)d_in[1];
    const float* ln1_b = (const float*)d_in[2];
    const float* qkv_w = (const float*)d_in[3];
    const float* temp  = (const float*)d_in[4];
    const float* out_w = (const float*)d_in[5];
    const float* out_b = (const float*)d_in[6];
    const float* ln2_g = (const float*)d_in[7];
    const float* ln2_b = (const float*)d_in[8];
    const float* ff_w1 = (const float*)d_in[9];
    const float* ff_b1 = (const float*)d_in[10];
    const float* ff_w2 = (const float*)d_in[11];
    const float* ff_b2 = (const float*)d_in[12];
    float* x = (float*)d_out;

    __half *p_ln, *p_qkv, *p_attn, *p_ff, *p_wt;
    cudaGetSymbolAddress((void**)&p_ln,   g_ln);
    cudaGetSymbolAddress((void**)&p_qkv,  g_qkv);
    cudaGetSymbolAddress((void**)&p_attn, g_attn);
    cudaGetSymbolAddress((void**)&p_ff,   g_ff);
    cudaGetSymbolAddress((void**)&p_wt,   g_wt);

    cudaFuncSetAttribute(mma_gemm<0>, cudaFuncAttributeMaxDynamicSharedMemorySize, GS_BYTES);
    cudaFuncSetAttribute(mma_gemm<1>, cudaFuncAttributeMaxDynamicSharedMemorySize, GS_BYTES);
    cudaFuncSetAttribute(mma_gemm<2>, cudaFuncAttributeMaxDynamicSharedMemorySize, GS_BYTES);
    cudaFuncSetAttribute(flash_kernel, cudaFuncAttributeMaxDynamicSharedMemorySize, FL_DSMEM);

    cudaMemcpyAsync(x, x_in, (size_t)ROWS * DIMV * sizeof(float),
                    cudaMemcpyDeviceToDevice);

    transpose_kernel<<<dim3(QKVW / 32, DIMV / 32, DEPTH), dim3(32, 8)>>>(
        qkv_w, p_wt + WT_QKV_OFF, DIMV, QKVW);
    transpose_kernel<<<dim3(DIMV / 32, INNER / 32, DEPTH), dim3(32, 8)>>>(
        out_w, p_wt + WT_WO_OFF, INNER, DIMV);
    transpose_kernel<<<dim3(MLPV / 32, DIMV / 32, DEPTH), dim3(32, 8)>>>(
        ff_w1, p_wt + WT_W1_OFF, DIMV, MLPV);
    transpose_kernel<<<dim3(DIMV / 32, MLPV / 32, DEPTH), dim3(32, 8)>>>(
        ff_w2, p_wt + WT_W2_OFF, MLPV, DIMV);

    for (int l = 0; l < DEPTH; l++) {
        // --- attention block ---
        ln_kernel<<<ROWS, 128>>>(x, ln1_g + l * DIMV, ln1_b + l * DIMV, p_ln);
        mma_gemm<0><<<dim3(QKVW / 128, ROWS / 128), 256, GS_BYTES>>>(
            p_ln, p_wt + WT_QKV_OFF + (size_t)l * WT_QKV_PER,
            nullptr, nullptr, p_qkv, ROWS, QKVW, DIMV);
        flash_kernel<<<dim3(NN / 128, BHN), 256, FL_DSMEM>>>(p_qkv, p_attn, temp, l);
        mma_gemm<1><<<dim3(DIMV / 128, ROWS / 128), 256, GS_BYTES>>>(
            p_attn, p_wt + WT_WO_OFF + (size_t)l * WT_WO_PER,
            out_b + l * DIMV, x, x, ROWS, DIMV, INNER);
        // --- feed-forward block ---
        ln_kernel<<<ROWS, 128>>>(x, ln2_g + l * DIMV, ln2_b + l * DIMV, p_ln);
        mma_gemm<2><<<dim3(MLPV / 128, ROWS / 128), 256, GS_BYTES>>>(
            p_ln, p_wt + WT_W1_OFF + (size_t)l * WT_W1_PER,
            ff_b1 + l * MLPV, nullptr, p_ff, ROWS, MLPV, DIMV);
        mma_gemm<1><<<dim3(DIMV / 128, ROWS / 128), 256, GS_BYTES>>>(
            p_ff, p_wt + WT_W2_OFF + (size_t)l * WT_W2_PER,
            ff_b2 + l * DIMV, x, x, ROWS, DIMV, MLPV);
    }
}

// round 11
// speedup vs baseline: 7.0132x; 1.0755x over previous
#include <cuda_runtime.h>
#include <cuda_fp16.h>
#include <math.h>
#include <stdint.h>
#include <string.h>

#define BB     16
#define NN     1024
#define DIMV   384
#define DEPTH  6
#define HEADS  6
#define DH     64
#define INNER  384
#define MLPV   1536
#define ROWS   (BB*NN)       // 16384
#define BHN    (BB*HEADS)    // 96
#define QKVW   (3*INNER)     // 1152
#define NEGMAX -3.4028234663852886e38f

// ---------------- scratch (half precision operands) ----------------
__device__ __half g_ln[(size_t)ROWS * DIMV];
__device__ __half g_qkv[(size_t)ROWS * QKVW];
__device__ __half g_attn[(size_t)ROWS * INNER];
__device__ __half g_ff[(size_t)ROWS * MLPV];
// half copies of weights, NATURAL [K][N] layout (no transpose)
#define WT_QKV_OFF  0
#define WT_QKV_PER  (DIMV*QKVW)
#define WT_WO_OFF   (WT_QKV_OFF + DEPTH*WT_QKV_PER)
#define WT_WO_PER   (INNER*DIMV)
#define WT_W1_OFF   (WT_WO_OFF + DEPTH*WT_WO_PER)
#define WT_W1_PER   (DIMV*MLPV)
#define WT_W2_OFF   (WT_W1_OFF + DEPTH*WT_W1_PER)
#define WT_W2_PER   (MLPV*DIMV)
__device__ __half g_wh[(size_t)(WT_W2_OFF + DEPTH*WT_W2_PER)];

// ================= helpers =================
__device__ __forceinline__ uint32_t smem_u32(const void* p) {
    uint32_t r;
    asm("{ .reg .u64 t; cvta.to.shared.u64 t, %1; cvt.u32.u64 %0, t; }" : "=r"(r) : "l"(p));
    return r;
}
__device__ __forceinline__ void cp16(uint32_t dst, const void* src) {
    asm volatile("cp.async.cg.shared.global [%0], [%1], 16;" :: "r"(dst), "l"(src));
}
__device__ __forceinline__ void mma16(float c[4], const uint32_t a[4], const uint32_t b[2]) {
    asm volatile(
        "mma.sync.aligned.m16n8k16.row.col.f32.f16.f16.f32 "
        "{%0,%1,%2,%3}, {%4,%5,%6,%7}, {%8,%9}, {%0,%1,%2,%3};"
        : "+f"(c[0]), "+f"(c[1]), "+f"(c[2]), "+f"(c[3])
        : "r"(a[0]), "r"(a[1]), "r"(a[2]), "r"(a[3]), "r"(b[0]), "r"(b[1]));
}
__device__ __forceinline__ void ldm_x4(uint32_t r[4], uint32_t a) {
    asm volatile("ldmatrix.sync.aligned.m8n8.x4.shared.b16 {%0,%1,%2,%3}, [%4];"
                 : "=r"(r[0]), "=r"(r[1]), "=r"(r[2]), "=r"(r[3]) : "r"(a));
}
__device__ __forceinline__ void ldm_x2(uint32_t r[2], uint32_t a) {
    asm volatile("ldmatrix.sync.aligned.m8n8.x2.shared.b16 {%0,%1}, [%2];"
                 : "=r"(r[0]), "=r"(r[1]) : "r"(a));
}
__device__ __forceinline__ void ldm_x2t(uint32_t r[2], uint32_t a) {
    asm volatile("ldmatrix.sync.aligned.m8n8.x2.trans.shared.b16 {%0,%1}, [%2];"
                 : "=r"(r[0]), "=r"(r[1]) : "r"(a));
}
__device__ __forceinline__ uint32_t packh2(float x, float y) {
    __half2 h = __floats2half2_rn(x, y);
    uint32_t u;
    memcpy(&u, &h, 4);
    return u;
}

// ================= dense fp16 GEMM: C[M,Nn] = A[M,K] @ B[K,Nn] ====================
// B in NATURAL K-major layout; B fragments via ldmatrix.trans (flash-V pattern).
// 128x128 CTA tile, 256 thr = 8 warps (2m x 4n), warp tile 64x32, BK=64,
// 3-stage cp.async. Stage: A 128x72h (18432 B) + B 64x136h (17408 B) = 35840 B.
#define GS_A_B      18432u
#define GS_STAGE_B  35840u
#define GS_BYTES    (3u * GS_STAGE_B)         // 107520 B
template <int EPI>
__global__ void __launch_bounds__(256, 2) mma_gemm(
    const __half* __restrict__ A, const __half* __restrict__ Bw,
    const float* __restrict__ bias, const float* __restrict__ res,
    void* __restrict__ Cv, int M, int Nn, int K) {
    extern __shared__ __align__(16) char smraw[];
    const int tid = threadIdx.x;
    const int wid = tid >> 5, lane = tid & 31;
    const int g = lane >> 2, tg = lane & 3;
    const int l16 = lane & 15;
    const int wm = (wid & 1) * 64, wn = (wid >> 1) * 32;
    const int m0 = blockIdx.y * 128, n0 = blockIdx.x * 128;

    float c[4][4][4];
    #pragma unroll
    for (int mt = 0; mt < 4; ++mt)
        #pragma unroll
        for (int nt = 0; nt < 4; ++nt)
            #pragma unroll
            for (int k = 0; k < 4; ++k) c[mt][nt][k] = 0.0f;

    const int nc = K >> 6;                    // chunks of 64 halves
    const uint32_t sbase = smem_u32(smraw);

    auto issue = [&](int ci) {
        uint32_t base = sbase + (uint32_t)(ci % 3) * GS_STAGE_B;
        int kt = ci << 6;
        #pragma unroll
        for (int i = 0; i < 4; ++i) {         // A: 128 rows x 64 k halves
            int f = tid + i * 256;
            int r = f >> 3, c8 = (f & 7) << 3;
            cp16(base + (uint32_t)(r * 72 + c8) * 2u,
                 A + (size_t)(m0 + r) * K + kt + c8);
        }
        #pragma unroll
        for (int i = 0; i < 4; ++i) {         // B: 64 k-rows x 128 n halves
            int f = tid + i * 256;
            int r = f >> 4, c8 = (f & 15) << 3;
            cp16(base + GS_A_B + (uint32_t)(r * 136 + c8) * 2u,
                 Bw + (size_t)(kt + r) * Nn + n0 + c8);
        }
        asm volatile("cp.async.commit_group;" ::: "memory");
    };

    issue(0);
    issue(1);

    for (int ci = 0; ci < nc; ++ci) {
        if (ci + 2 < nc) {
            issue(ci + 2);
        } else {
            asm volatile("cp.async.commit_group;" ::: "memory");
        }
        asm volatile("cp.async.wait_group 2;" ::: "memory");
        __syncthreads();

        const uint32_t stA = sbase + (uint32_t)(ci % 3) * GS_STAGE_B;
        const uint32_t stB = stA + GS_A_B;
        #pragma unroll
        for (int ks = 0; ks < 4; ++ks) {      // four k16 steps per 64-chunk
            uint32_t af[4][4], bf[4][2];
            #pragma unroll
            for (int mt = 0; mt < 4; ++mt)
                ldm_x4(af[mt], stA + (uint32_t)((wm + mt * 16 + l16) * 72
                                                + ks * 16 + (lane >> 4) * 8) * 2u);
            #pragma unroll
            for (int nt = 0; nt < 4; ++nt)
                ldm_x2t(bf[nt], stB + (uint32_t)((ks * 16 + l16) * 136
                                                 + wn + nt * 8) * 2u);
            #pragma unroll
            for (int mt = 0; mt < 4; ++mt)
                #pragma unroll
                for (int nt = 0; nt < 4; ++nt)
                    mma16(c[mt][nt], af[mt], bf[nt]);
        }
        __syncthreads();
    }

    #pragma unroll
    for (int mt = 0; mt < 4; ++mt) {
        #pragma unroll
        for (int nt = 0; nt < 4; ++nt) {
            int col = n0 + wn + nt * 8 + 2 * tg;
            #pragma unroll
            for (int h = 0; h < 2; ++h) {
                int row = m0 + wm + mt * 16 + g + h * 8;
                float v0 = c[mt][nt][h * 2 + 0];
                float v1 = c[mt][nt][h * 2 + 1];
                if (EPI >= 1) { v0 += bias[col]; v1 += bias[col + 1]; }
                if (EPI == 1) {
                    float2 r2 = *(const float2*)(res + (size_t)row * Nn + col);
                    v0 += r2.x; v1 += r2.y;
                    *(float2*)((float*)Cv + (size_t)row * Nn + col) = make_float2(v0, v1);
                } else {
                    if (EPI == 2) {
                        v0 = 0.5f * v0 * (1.0f + erff(v0 * 0.70710678118654752f));
                        v1 = 0.5f * v1 * (1.0f + erff(v1 * 0.70710678118654752f));
                    }
                    *(__half2*)((__half*)Cv + (size_t)row * Nn + col) =
                        __floats2half2_rn(v0, v1);
                }
            }
        }
    }
}

// ================= flash attention (unchanged from R10) ============================
#define FL_PS_H    (128 * 72)
#define FL_KV_H    (64 * 72)
#define FL_TOT_H   (FL_PS_H + 4 * FL_KV_H)    // 27648
#define FL_DSMEM   (FL_TOT_H * 2)             // 55296 B
__global__ void __launch_bounds__(256, 2) flash_kernel(
    const __half* __restrict__ qkv,
    __half* __restrict__ o,
    const float* __restrict__ temp, int layer) {
    extern __shared__ __align__(16) __half fsh[];

    int bh = blockIdx.y;
    int b = bh / HEADS, h = bh - b * HEADS;
    int rt = blockIdx.x * 128;
    int tid = threadIdx.x, wid = tid >> 5, lane = tid & 31;
    int g = lane >> 2, tg = lane & 3;
    int l16 = lane & 15;

    const __half* qb = qkv + (size_t)b * NN * QKVW + h * DH;
    const __half* kb = qb + INNER;
    const __half* vb = qb + 2 * INNER;
    const uint32_t sbase = smem_u32(fsh);

    #pragma unroll
    for (int i = 0; i < 4; ++i) {
        int f = tid + i * 256;
        int r = f >> 3, c8 = (f & 7) << 3;
        *(uint4*)&fsh[r * 72 + c8] = *(const uint4*)(qb + (size_t)(rt + r) * QKVW + c8);
    }
    auto issue_kv = [&](int i) {
        uint32_t kbb = sbase + (uint32_t)(FL_PS_H + (i & 1) * 2 * FL_KV_H) * 2u;
        uint32_t vbb = kbb + FL_KV_H * 2u;
        int kt = i << 6;
        #pragma unroll
        for (int it = 0; it < 2; ++it) {
            int f = tid + it * 256;
            int r = f >> 3, c8 = (f & 7) << 3;
            cp16(kbb + (uint32_t)(r * 72 + c8) * 2u, kb + (size_t)(kt + r) * QKVW + c8);
            cp16(vbb + (uint32_t)(r * 72 + c8) * 2u, vb + (size_t)(kt + r) * QKVW + c8);
        }
        asm volatile("cp.async.commit_group;" ::: "memory");
    };
    issue_kv(0);
    __syncthreads();

    uint32_t qf[4][4];
    #pragma unroll
    for (int ks = 0; ks < 4; ++ks)
        ldm_x4(qf[ks], sbase + (uint32_t)((wid * 16 + l16) * 72
                                          + ks * 16 + (lane >> 4) * 8) * 2u);

    float scale = expf(temp[layer]);
    float m0 = NEGMAX, m1 = NEGMAX, l0 = 0.0f, l1 = 0.0f;
    float oacc[8][4];
    #pragma unroll
    for (int nt = 0; nt < 8; ++nt)
        #pragma unroll
        for (int k = 0; k < 4; ++k) oacc[nt][k] = 0.0f;

    const int gi0 = rt + wid * 16 + g;
    const int gi1 = gi0 + 8;

    for (int i = 0; i < NN / 64; ++i) {
        if (i + 1 < NN / 64) {
            issue_kv(i + 1);
        } else {
            asm volatile("cp.async.commit_group;" ::: "memory");
        }
        asm volatile("cp.async.wait_group 1;" ::: "memory");
        __syncthreads();

        const uint32_t kbb = sbase + (uint32_t)(FL_PS_H + (i & 1) * 2 * FL_KV_H) * 2u;
        const uint32_t vbb = kbb + FL_KV_H * 2u;
        const int kt = i << 6;

        float s[8][4];
        #pragma unroll
        for (int nt = 0; nt < 8; ++nt)
            #pragma unroll
            for (int k = 0; k < 4; ++k) s[nt][k] = 0.0f;
        #pragma unroll
        for (int ks = 0; ks < 4; ++ks) {
            #pragma unroll
            for (int nt = 0; nt < 8; ++nt) {
                uint32_t bf[2];
                ldm_x2(bf, kbb + (uint32_t)((nt * 8 + (l16 & 7)) * 72
                                            + ks * 16 + (l16 >> 3) * 8) * 2u);
                mma16(s[nt], qf[ks], bf);
            }
        }
        #pragma unroll
        for (int nt = 0; nt < 8; ++nt) {
            int gj = kt + nt * 8 + 2 * tg;
            s[nt][0] *= scale; s[nt][1] *= scale; s[nt][2] *= scale; s[nt][3] *= scale;
            if (gi0 == gj)     s[nt][0] = NEGMAX;
            if (gi0 == gj + 1) s[nt][1] = NEGMAX;
            if (gi1 == gj)     s[nt][2] = NEGMAX;
            if (gi1 == gj + 1) s[nt][3] = NEGMAX;
        }
        float mx0 = NEGMAX, mx1 = NEGMAX;
        #pragma unroll
        for (int nt = 0; nt < 8; ++nt) {
            mx0 = fmaxf(mx0, fmaxf(s[nt][0], s[nt][1]));
            mx1 = fmaxf(mx1, fmaxf(s[nt][2], s[nt][3]));
        }
        mx0 = fmaxf(mx0, __shfl_xor_sync(0xffffffffu, mx0, 1));
        mx0 = fmaxf(mx0, __shfl_xor_sync(0xffffffffu, mx0, 2));
        mx1 = fmaxf(mx1, __shfl_xor_sync(0xffffffffu, mx1, 1));
        mx1 = fmaxf(mx1, __shfl_xor_sync(0xffffffffu, mx1, 2));
        float mn0 = fmaxf(m0, mx0), mn1 = fmaxf(m1, mx1);
        float r0 = __expf(m0 - mn0), r1 = __expf(m1 - mn1);
        float sum0 = 0.0f, sum1 = 0.0f;
        #pragma unroll
        for (int nt = 0; nt < 8; ++nt) {
            s[nt][0] = __expf(s[nt][0] - mn0);
            s[nt][1] = __expf(s[nt][1] - mn0);
            s[nt][2] = __expf(s[nt][2] - mn1);
            s[nt][3] = __expf(s[nt][3] - mn1);
            sum0 += s[nt][0] + s[nt][1];
            sum1 += s[nt][2] + s[nt][3];
        }
        sum0 += __shfl_xor_sync(0xffffffffu, sum0, 1);
        sum0 += __shfl_xor_sync(0xffffffffu, sum0, 2);
        sum1 += __shfl_xor_sync(0xffffffffu, sum1, 1);
        sum1 += __shfl_xor_sync(0xffffffffu, sum1, 2);
        l0 = l0 * r0 + sum0;
        l1 = l1 * r1 + sum1;
        m0 = mn0; m1 = mn1;
        #pragma unroll
        for (int nt = 0; nt < 8; ++nt) {
            oacc[nt][0] *= r0; oacc[nt][1] *= r0;
            oacc[nt][2] *= r1; oacc[nt][3] *= r1;
        }
        #pragma unroll
        for (int ks = 0; ks < 4; ++ks) {
            uint32_t pf[4];
            pf[0] = packh2(s[2 * ks][0],     s[2 * ks][1]);
            pf[1] = packh2(s[2 * ks][2],     s[2 * ks][3]);
            pf[2] = packh2(s[2 * ks + 1][0], s[2 * ks + 1][1]);
            pf[3] = packh2(s[2 * ks + 1][2], s[2 * ks + 1][3]);
            #pragma unroll
            for (int nt = 0; nt < 8; ++nt) {
                uint32_t bf[2];
                ldm_x2t(bf, vbb + (uint32_t)((ks * 16 + l16) * 72 + nt * 8) * 2u);
                mma16(oacc[nt], pf, bf);
            }
        }
        __syncthreads();
    }

    float inv0 = 1.0f / l0, inv1 = 1.0f / l1;
    #pragma unroll
    for (int nt = 0; nt < 8; ++nt) {
        int gc = h * DH + nt * 8 + 2 * tg;
        int gr0 = b * NN + gi0;
        int gr1 = b * NN + gi1;
        *(__half2*)(o + (size_t)gr0 * INNER + gc) =
            __floats2half2_rn(oacc[nt][0] * inv0, oacc[nt][1] * inv0);
        *(__half2*)(o + (size_t)gr1 * INNER + gc) =
            __floats2half2_rn(oacc[nt][2] * inv1, oacc[nt][3] * inv1);
    }
}

// ---------------- fp32 -> half convert (coalesced, no transpose) ----------------
__global__ void cvt_kernel(const float* __restrict__ src, __half* __restrict__ dst,
                           int n4) {
    int i = blockIdx.x * blockDim.x + threadIdx.x;
    if (i < n4) {
        float4 v = *(const float4*)(src + (size_t)i * 4);
        __half2 h0 = __floats2half2_rn(v.x, v.y);
        __half2 h1 = __floats2half2_rn(v.z, v.w);
        uint32_t u0, u1;
        memcpy(&u0, &h0, 4); memcpy(&u1, &h1, 4);
        uint2 o; o.x = u0; o.y = u1;
        *(uint2*)(dst + (size_t)i * 4) = o;
    }
}

// ---------------- LayerNorm fp32 -> half ----------------
__global__ void ln_kernel(const float* __restrict__ x,
                          const float* __restrict__ gamma,
                          const float* __restrict__ beta,
                          __half* __restrict__ y) {
    int row = blockIdx.x;
    const float* xr = x + (size_t)row * DIMV;
    __half*      yr = y + (size_t)row * DIMV;
    int t = threadIdx.x;
    float v0 = xr[t], v1 = xr[t + 128], v2 = xr[t + 256];
    float s = v0 + v1 + v2;
    float q = v0 * v0 + v1 * v1 + v2 * v2;
    #pragma unroll
    for (int o = 16; o > 0; o >>= 1) {
        s += __shfl_down_sync(0xffffffffu, s, o);
        q += __shfl_down_sync(0xffffffffu, q, o);
    }
    __shared__ float shs[4], shq[4];
    __shared__ float s_mean, s_inv;
    int w = t >> 5, lane = t & 31;
    if (lane == 0) { shs[w] = s; shq[w] = q; }
    __syncthreads();
    if (t == 0) {
        float S = shs[0] + shs[1] + shs[2] + shs[3];
        float Q = shq[0] + shq[1] + shq[2] + shq[3];
        float m = S * (1.0f / 384.0f);
        float var = Q * (1.0f / 384.0f) - m * m;
        s_mean = m;
        s_inv  = rsqrtf(var + 1e-5f);
    }
    __syncthreads();
    float m = s_mean, inv = s_inv;
    yr[t]       = __float2half_rn((v0 - m) * inv * gamma[t]       + beta[t]);
    yr[t + 128] = __float2half_rn((v1 - m) * inv * gamma[t + 128] + beta[t + 128]);
    yr[t + 256] = __float2half_rn((v2 - m) * inv * gamma[t + 256] + beta[t + 256]);
}

// ---------------- driver ----------------
extern "C" void kernel_launch(void* const* d_in, const int* in_sizes, int n_in,
                              void* d_out, int out_size) {
    const float* x_in  = (const float*)d_in[0];
    const float* ln1_g = (const float*)d_in[1];
    const float* ln1_b = (const float*)d_in[2];
    const float* qkv_w = (const float*)d_in[3];
    const float* temp  = (const float*)d_in[4];
    const float* out_w = (const float*)d_in[5];
    const float* out_b = (const float*)d_in[6];
    const float* ln2_g = (const float*)d_in[7];
    const float* ln2_b = (const float*)d_in[8];
    const float* ff_w1 = (const float*)d_in[9];
    const float* ff_b1 = (const float*)d_in[10];
    const float* ff_w2 = (const float*)d_in[11];
    const float* ff_b2 = (const float*)d_in[12];
    float* x = (float*)d_out;

    __half *p_ln, *p_qkv, *p_attn, *p_ff, *p_wh;
    cudaGetSymbolAddress((void**)&p_ln,   g_ln);
    cudaGetSymbolAddress((void**)&p_qkv,  g_qkv);
    cudaGetSymbolAddress((void**)&p_attn, g_attn);
    cudaGetSymbolAddress((void**)&p_ff,   g_ff);
    cudaGetSymbolAddress((void**)&p_wh,   g_wh);

    cudaFuncSetAttribute(mma_gemm<0>, cudaFuncAttributeMaxDynamicSharedMemorySize, GS_BYTES);
    cudaFuncSetAttribute(mma_gemm<1>, cudaFuncAttributeMaxDynamicSharedMemorySize, GS_BYTES);
    cudaFuncSetAttribute(mma_gemm<2>, cudaFuncAttributeMaxDynamicSharedMemorySize, GS_BYTES);
    cudaFuncSetAttribute(flash_kernel, cudaFuncAttributeMaxDynamicSharedMemorySize, FL_DSMEM);

    cudaMemcpyAsync(x, x_in, (size_t)ROWS * DIMV * sizeof(float),
                    cudaMemcpyDeviceToDevice);

    // straight fp32 -> half conversions (natural [K][N] layout, fully coalesced)
    cvt_kernel<<<(DEPTH * WT_QKV_PER / 4 + 255) / 256, 256>>>(
        qkv_w, p_wh + WT_QKV_OFF, DEPTH * WT_QKV_PER / 4);
    cvt_kernel<<<(DEPTH * WT_WO_PER / 4 + 255) / 256, 256>>>(
        out_w, p_wh + WT_WO_OFF, DEPTH * WT_WO_PER / 4);
    cvt_kernel<<<(DEPTH * WT_W1_PER / 4 + 255) / 256, 256>>>(
        ff_w1, p_wh + WT_W1_OFF, DEPTH * WT_W1_PER / 4);
    cvt_kernel<<<(DEPTH * WT_W2_PER / 4 + 255) / 256, 256>>>(
        ff_w2, p_wh + WT_W2_OFF, DEPTH * WT_W2_PER / 4);

    for (int l = 0; l < DEPTH; l++) {
        // --- attention block ---
        ln_kernel<<<ROWS, 128>>>(x, ln1_g + l * DIMV, ln1_b + l * DIMV, p_ln);
        mma_gemm<0><<<dim3(QKVW / 128, ROWS / 128), 256, GS_BYTES>>>(
            p_ln, p_wh + WT_QKV_OFF + (size_t)l * WT_QKV_PER,
            nullptr, nullptr, p_qkv, ROWS, QKVW, DIMV);
        flash_kernel<<<dim3(NN / 128, BHN), 256, FL_DSMEM>>>(p_qkv, p_attn, temp, l);
        mma_gemm<1><<<dim3(DIMV / 128, ROWS / 128), 256, GS_BYTES>>>(
            p_attn, p_wh + WT_WO_OFF + (size_t)l * WT_WO_PER,
            out_b + l * DIMV, x, x, ROWS, DIMV, INNER);
        // --- feed-forward block ---
        ln_kernel<<<ROWS, 128>>>(x, ln2_g + l * DIMV, ln2_b + l * DIMV, p_ln);
        mma_gemm<2><<<dim3(MLPV / 128, ROWS / 128), 256, GS_BYTES>>>(
            p_ln, p_wh + WT_W1_OFF + (size_t)l * WT_W1_PER,
            ff_b1 + l * MLPV, nullptr, p_ff, ROWS, MLPV, DIMV);
        mma_gemm<1><<<dim3(DIMV / 128, ROWS / 128), 256, GS_BYTES>>>(
            p_ff, p_wh + WT_W2_OFF + (size_t)l * WT_W2_PER,
            ff_b2 + l * DIMV, x, x, ROWS, DIMV, MLPV);
    }
}

// round 12
// speedup vs baseline: 7.1680x; 1.0221x over previous
#include <cuda_runtime.h>
#include <cuda_fp16.h>
#include <math.h>
#include <stdint.h>
#include <string.h>

#define BB     16
#define NN     1024
#define DIMV   384
#define DEPTH  6
#define HEADS  6
#define DH     64
#define INNER  384
#define MLPV   1536
#define ROWS   (BB*NN)       // 16384
#define BHN    (BB*HEADS)    // 96
#define QKVW   (3*INNER)     // 1152
#define NEGMAX -3.4028234663852886e38f

// ---------------- scratch (half precision operands) ----------------
__device__ __half g_ln[(size_t)ROWS * DIMV];
__device__ __half g_qkv[(size_t)ROWS * QKVW];
__device__ __half g_attn[(size_t)ROWS * INNER];
__device__ __half g_ff[(size_t)ROWS * MLPV];
// half copies of weights, NATURAL [K][N] layout (no transpose)
#define WT_QKV_OFF  0
#define WT_QKV_PER  (DIMV*QKVW)
#define WT_WO_OFF   (WT_QKV_OFF + DEPTH*WT_QKV_PER)
#define WT_WO_PER   (INNER*DIMV)
#define WT_W1_OFF   (WT_WO_OFF + DEPTH*WT_WO_PER)
#define WT_W1_PER   (DIMV*MLPV)
#define WT_W2_OFF   (WT_W1_OFF + DEPTH*WT_W1_PER)
#define WT_W2_PER   (MLPV*DIMV)
#define WT_TOTAL    (WT_W2_OFF + DEPTH*WT_W2_PER)
__device__ __half g_wh[(size_t)WT_TOTAL];

// ================= helpers =================
__device__ __forceinline__ uint32_t smem_u32(const void* p) {
    uint32_t r;
    asm("{ .reg .u64 t; cvta.to.shared.u64 t, %1; cvt.u32.u64 %0, t; }" : "=r"(r) : "l"(p));
    return r;
}
__device__ __forceinline__ void cp16(uint32_t dst, const void* src) {
    asm volatile("cp.async.cg.shared.global [%0], [%1], 16;" :: "r"(dst), "l"(src));
}
__device__ __forceinline__ void mma16(float c[4], const uint32_t a[4], const uint32_t b[2]) {
    asm volatile(
        "mma.sync.aligned.m16n8k16.row.col.f32.f16.f16.f32 "
        "{%0,%1,%2,%3}, {%4,%5,%6,%7}, {%8,%9}, {%0,%1,%2,%3};"
        : "+f"(c[0]), "+f"(c[1]), "+f"(c[2]), "+f"(c[3])
        : "r"(a[0]), "r"(a[1]), "r"(a[2]), "r"(a[3]), "r"(b[0]), "r"(b[1]));
}
__device__ __forceinline__ void ldm_x4(uint32_t r[4], uint32_t a) {
    asm volatile("ldmatrix.sync.aligned.m8n8.x4.shared.b16 {%0,%1,%2,%3}, [%4];"
                 : "=r"(r[0]), "=r"(r[1]), "=r"(r[2]), "=r"(r[3]) : "r"(a));
}
__device__ __forceinline__ void ldm_x2(uint32_t r[2], uint32_t a) {
    asm volatile("ldmatrix.sync.aligned.m8n8.x2.shared.b16 {%0,%1}, [%2];"
                 : "=r"(r[0]), "=r"(r[1]) : "r"(a));
}
__device__ __forceinline__ void ldm_x2t(uint32_t r[2], uint32_t a) {
    asm volatile("ldmatrix.sync.aligned.m8n8.x2.trans.shared.b16 {%0,%1}, [%2];"
                 : "=r"(r[0]), "=r"(r[1]) : "r"(a));
}
__device__ __forceinline__ uint32_t packh2(float x, float y) {
    __half2 h = __floats2half2_rn(x, y);
    uint32_t u;
    memcpy(&u, &h, 4);
    return u;
}

// ================= dense fp16 GEMM: C[M,Nn] = A[M,K] @ B[K,Nn] ====================
// (unchanged from R11)
#define GS_A_B      18432u
#define GS_STAGE_B  35840u
#define GS_BYTES    (3u * GS_STAGE_B)         // 107520 B
template <int EPI>
__global__ void __launch_bounds__(256, 2) mma_gemm(
    const __half* __restrict__ A, const __half* __restrict__ Bw,
    const float* __restrict__ bias, const float* __restrict__ res,
    void* __restrict__ Cv, int M, int Nn, int K) {
    extern __shared__ __align__(16) char smraw[];
    const int tid = threadIdx.x;
    const int wid = tid >> 5, lane = tid & 31;
    const int g = lane >> 2, tg = lane & 3;
    const int l16 = lane & 15;
    const int wm = (wid & 1) * 64, wn = (wid >> 1) * 32;
    const int m0 = blockIdx.y * 128, n0 = blockIdx.x * 128;

    float c[4][4][4];
    #pragma unroll
    for (int mt = 0; mt < 4; ++mt)
        #pragma unroll
        for (int nt = 0; nt < 4; ++nt)
            #pragma unroll
            for (int k = 0; k < 4; ++k) c[mt][nt][k] = 0.0f;

    const int nc = K >> 6;
    const uint32_t sbase = smem_u32(smraw);

    auto issue = [&](int ci) {
        uint32_t base = sbase + (uint32_t)(ci % 3) * GS_STAGE_B;
        int kt = ci << 6;
        #pragma unroll
        for (int i = 0; i < 4; ++i) {
            int f = tid + i * 256;
            int r = f >> 3, c8 = (f & 7) << 3;
            cp16(base + (uint32_t)(r * 72 + c8) * 2u,
                 A + (size_t)(m0 + r) * K + kt + c8);
        }
        #pragma unroll
        for (int i = 0; i < 4; ++i) {
            int f = tid + i * 256;
            int r = f >> 4, c8 = (f & 15) << 3;
            cp16(base + GS_A_B + (uint32_t)(r * 136 + c8) * 2u,
                 Bw + (size_t)(kt + r) * Nn + n0 + c8);
        }
        asm volatile("cp.async.commit_group;" ::: "memory");
    };

    issue(0);
    issue(1);

    for (int ci = 0; ci < nc; ++ci) {
        if (ci + 2 < nc) {
            issue(ci + 2);
        } else {
            asm volatile("cp.async.commit_group;" ::: "memory");
        }
        asm volatile("cp.async.wait_group 2;" ::: "memory");
        __syncthreads();

        const uint32_t stA = sbase + (uint32_t)(ci % 3) * GS_STAGE_B;
        const uint32_t stB = stA + GS_A_B;
        #pragma unroll
        for (int ks = 0; ks < 4; ++ks) {
            uint32_t af[4][4], bf[4][2];
            #pragma unroll
            for (int mt = 0; mt < 4; ++mt)
                ldm_x4(af[mt], stA + (uint32_t)((wm + mt * 16 + l16) * 72
                                                + ks * 16 + (lane >> 4) * 8) * 2u);
            #pragma unroll
            for (int nt = 0; nt < 4; ++nt)
                ldm_x2t(bf[nt], stB + (uint32_t)((ks * 16 + l16) * 136
                                                 + wn + nt * 8) * 2u);
            #pragma unroll
            for (int mt = 0; mt < 4; ++mt)
                #pragma unroll
                for (int nt = 0; nt < 4; ++nt)
                    mma16(c[mt][nt], af[mt], bf[nt]);
        }
        __syncthreads();
    }

    #pragma unroll
    for (int mt = 0; mt < 4; ++mt) {
        #pragma unroll
        for (int nt = 0; nt < 4; ++nt) {
            int col = n0 + wn + nt * 8 + 2 * tg;
            #pragma unroll
            for (int h = 0; h < 2; ++h) {
                int row = m0 + wm + mt * 16 + g + h * 8;
                float v0 = c[mt][nt][h * 2 + 0];
                float v1 = c[mt][nt][h * 2 + 1];
                if (EPI >= 1) { v0 += bias[col]; v1 += bias[col + 1]; }
                if (EPI == 1) {
                    float2 r2 = *(const float2*)(res + (size_t)row * Nn + col);
                    v0 += r2.x; v1 += r2.y;
                    *(float2*)((float*)Cv + (size_t)row * Nn + col) = make_float2(v0, v1);
                } else {
                    if (EPI == 2) {
                        v0 = 0.5f * v0 * (1.0f + erff(v0 * 0.70710678118654752f));
                        v1 = 0.5f * v1 * (1.0f + erff(v1 * 0.70710678118654752f));
                    }
                    *(__half2*)((__half*)Cv + (size_t)row * Nn + col) =
                        __floats2half2_rn(v0, v1);
                }
            }
        }
    }
}

// ================= flash attention: 3-stage KV pipeline ============================
// Smem (halves): Q stage 128x72 | 3 x (K 64x72, V 64x72 row-major)
#define FL_PS_H    (128 * 72)
#define FL_KV_H    (64 * 72)
#define FL_TOT_H   (FL_PS_H + 6 * FL_KV_H)    // 36864
#define FL_DSMEM   (FL_TOT_H * 2)             // 73728 B
__global__ void __launch_bounds__(256, 2) flash_kernel(
    const __half* __restrict__ qkv,
    __half* __restrict__ o,
    const float* __restrict__ temp, int layer) {
    extern __shared__ __align__(16) __half fsh[];

    int bh = blockIdx.y;
    int b = bh / HEADS, h = bh - b * HEADS;
    int rt = blockIdx.x * 128;
    int tid = threadIdx.x, wid = tid >> 5, lane = tid & 31;
    int g = lane >> 2, tg = lane & 3;
    int l16 = lane & 15;

    const __half* qb = qkv + (size_t)b * NN * QKVW + h * DH;
    const __half* kb = qb + INNER;
    const __half* vb = qb + 2 * INNER;
    const uint32_t sbase = smem_u32(fsh);

    #pragma unroll
    for (int i = 0; i < 4; ++i) {
        int f = tid + i * 256;
        int r = f >> 3, c8 = (f & 7) << 3;
        *(uint4*)&fsh[r * 72 + c8] = *(const uint4*)(qb + (size_t)(rt + r) * QKVW + c8);
    }
    auto issue_kv = [&](int i) {
        uint32_t kbb = sbase + (uint32_t)(FL_PS_H + (i % 3) * 2 * FL_KV_H) * 2u;
        uint32_t vbb = kbb + FL_KV_H * 2u;
        int kt = i << 6;
        #pragma unroll
        for (int it = 0; it < 2; ++it) {
            int f = tid + it * 256;
            int r = f >> 3, c8 = (f & 7) << 3;
            cp16(kbb + (uint32_t)(r * 72 + c8) * 2u, kb + (size_t)(kt + r) * QKVW + c8);
            cp16(vbb + (uint32_t)(r * 72 + c8) * 2u, vb + (size_t)(kt + r) * QKVW + c8);
        }
        asm volatile("cp.async.commit_group;" ::: "memory");
    };
    issue_kv(0);
    issue_kv(1);
    __syncthreads();                       // Q visible to all

    uint32_t qf[4][4];
    #pragma unroll
    for (int ks = 0; ks < 4; ++ks)
        ldm_x4(qf[ks], sbase + (uint32_t)((wid * 16 + l16) * 72
                                          + ks * 16 + (lane >> 4) * 8) * 2u);

    float scale = expf(temp[layer]);
    float m0 = NEGMAX, m1 = NEGMAX, l0 = 0.0f, l1 = 0.0f;
    float oacc[8][4];
    #pragma unroll
    for (int nt = 0; nt < 8; ++nt)
        #pragma unroll
        for (int k = 0; k < 4; ++k) oacc[nt][k] = 0.0f;

    const int gi0 = rt + wid * 16 + g;
    const int gi1 = gi0 + 8;

    for (int i = 0; i < NN / 64; ++i) {
        if (i + 2 < NN / 64) {
            issue_kv(i + 2);
        } else {
            asm volatile("cp.async.commit_group;" ::: "memory");
        }
        asm volatile("cp.async.wait_group 2;" ::: "memory");
        __syncthreads();

        const uint32_t kbb = sbase + (uint32_t)(FL_PS_H + (i % 3) * 2 * FL_KV_H) * 2u;
        const uint32_t vbb = kbb + FL_KV_H * 2u;
        const int kt = i << 6;

        float s[8][4];
        #pragma unroll
        for (int nt = 0; nt < 8; ++nt)
            #pragma unroll
            for (int k = 0; k < 4; ++k) s[nt][k] = 0.0f;
        #pragma unroll
        for (int ks = 0; ks < 4; ++ks) {
            #pragma unroll
            for (int nt = 0; nt < 8; ++nt) {
                uint32_t bf[2];
                ldm_x2(bf, kbb + (uint32_t)((nt * 8 + (l16 & 7)) * 72
                                            + ks * 16 + (l16 >> 3) * 8) * 2u);
                mma16(s[nt], qf[ks], bf);
            }
        }
        #pragma unroll
        for (int nt = 0; nt < 8; ++nt) {
            int gj = kt + nt * 8 + 2 * tg;
            s[nt][0] *= scale; s[nt][1] *= scale; s[nt][2] *= scale; s[nt][3] *= scale;
            if (gi0 == gj)     s[nt][0] = NEGMAX;
            if (gi0 == gj + 1) s[nt][1] = NEGMAX;
            if (gi1 == gj)     s[nt][2] = NEGMAX;
            if (gi1 == gj + 1) s[nt][3] = NEGMAX;
        }
        float mx0 = NEGMAX, mx1 = NEGMAX;
        #pragma unroll
        for (int nt = 0; nt < 8; ++nt) {
            mx0 = fmaxf(mx0, fmaxf(s[nt][0], s[nt][1]));
            mx1 = fmaxf(mx1, fmaxf(s[nt][2], s[nt][3]));
        }
        mx0 = fmaxf(mx0, __shfl_xor_sync(0xffffffffu, mx0, 1));
        mx0 = fmaxf(mx0, __shfl_xor_sync(0xffffffffu, mx0, 2));
        mx1 = fmaxf(mx1, __shfl_xor_sync(0xffffffffu, mx1, 1));
        mx1 = fmaxf(mx1, __shfl_xor_sync(0xffffffffu, mx1, 2));
        float mn0 = fmaxf(m0, mx0), mn1 = fmaxf(m1, mx1);
        float r0 = __expf(m0 - mn0), r1 = __expf(m1 - mn1);
        float sum0 = 0.0f, sum1 = 0.0f;
        #pragma unroll
        for (int nt = 0; nt < 8; ++nt) {
            s[nt][0] = __expf(s[nt][0] - mn0);
            s[nt][1] = __expf(s[nt][1] - mn0);
            s[nt][2] = __expf(s[nt][2] - mn1);
            s[nt][3] = __expf(s[nt][3] - mn1);
            sum0 += s[nt][0] + s[nt][1];
            sum1 += s[nt][2] + s[nt][3];
        }
        sum0 += __shfl_xor_sync(0xffffffffu, sum0, 1);
        sum0 += __shfl_xor_sync(0xffffffffu, sum0, 2);
        sum1 += __shfl_xor_sync(0xffffffffu, sum1, 1);
        sum1 += __shfl_xor_sync(0xffffffffu, sum1, 2);
        l0 = l0 * r0 + sum0;
        l1 = l1 * r1 + sum1;
        m0 = mn0; m1 = mn1;
        #pragma unroll
        for (int nt = 0; nt < 8; ++nt) {
            oacc[nt][0] *= r0; oacc[nt][1] *= r0;
            oacc[nt][2] *= r1; oacc[nt][3] *= r1;
        }
        #pragma unroll
        for (int ks = 0; ks < 4; ++ks) {
            uint32_t pf[4];
            pf[0] = packh2(s[2 * ks][0],     s[2 * ks][1]);
            pf[1] = packh2(s[2 * ks][2],     s[2 * ks][3]);
            pf[2] = packh2(s[2 * ks + 1][0], s[2 * ks + 1][1]);
            pf[3] = packh2(s[2 * ks + 1][2], s[2 * ks + 1][3]);
            #pragma unroll
            for (int nt = 0; nt < 8; ++nt) {
                uint32_t bf[2];
                ldm_x2t(bf, vbb + (uint32_t)((ks * 16 + l16) * 72 + nt * 8) * 2u);
                mma16(oacc[nt], pf, bf);
            }
        }
        __syncthreads();                   // done reading buf i%3
    }

    float inv0 = 1.0f / l0, inv1 = 1.0f / l1;
    #pragma unroll
    for (int nt = 0; nt < 8; ++nt) {
        int gc = h * DH + nt * 8 + 2 * tg;
        int gr0 = b * NN + gi0;
        int gr1 = b * NN + gi1;
        *(__half2*)(o + (size_t)gr0 * INNER + gc) =
            __floats2half2_rn(oacc[nt][0] * inv0, oacc[nt][1] * inv0);
        *(__half2*)(o + (size_t)gr1 * INNER + gc) =
            __floats2half2_rn(oacc[nt][2] * inv1, oacc[nt][3] * inv1);
    }
}

// ---------------- fused fp32 -> half convert for all 4 weight tensors ---------------
__global__ void cvt_all_kernel(const float* __restrict__ s0, int n0,
                               const float* __restrict__ s1, int n1,
                               const float* __restrict__ s2, int n2,
                               const float* __restrict__ s3,
                               __half* __restrict__ dst, int n4tot) {
    int i = blockIdx.x * blockDim.x + threadIdx.x;
    if (i >= n4tot) return;
    int e = i * 4;                // element index into g_wh
    const float* src;
    if (e < n0)                 { src = s0 + e; }
    else if (e < n0 + n1)       { src = s1 + (e - n0); }
    else if (e < n0 + n1 + n2)  { src = s2 + (e - n0 - n1); }
    else                        { src = s3 + (e - n0 - n1 - n2); }
    float4 v = *(const float4*)src;
    __half2 h0 = __floats2half2_rn(v.x, v.y);
    __half2 h1 = __floats2half2_rn(v.z, v.w);
    uint32_t u0, u1;
    memcpy(&u0, &h0, 4); memcpy(&u1, &h1, 4);
    uint2 ov; ov.x = u0; ov.y = u1;
    *(uint2*)(dst + (size_t)e) = ov;
}

// ---------------- LayerNorm: one WARP per row (no block syncs) ----------------
__global__ void ln_kernel(const float* __restrict__ x,
                          const float* __restrict__ gamma,
                          const float* __restrict__ beta,
                          __half* __restrict__ y) {
    int wid = threadIdx.x >> 5, lane = threadIdx.x & 31;
    int row = blockIdx.x * 8 + wid;
    const float* xr = x + (size_t)row * DIMV;
    __half*      yr = y + (size_t)row * DIMV;

    float4 v[3];
    #pragma unroll
    for (int j = 0; j < 3; ++j)
        v[j] = *(const float4*)(xr + j * 128 + lane * 4);

    float s = 0.0f, q = 0.0f;
    #pragma unroll
    for (int j = 0; j < 3; ++j) {
        s += v[j].x + v[j].y + v[j].z + v[j].w;
        q += v[j].x * v[j].x + v[j].y * v[j].y + v[j].z * v[j].z + v[j].w * v[j].w;
    }
    #pragma unroll
    for (int o = 16; o > 0; o >>= 1) {
        s += __shfl_xor_sync(0xffffffffu, s, o);
        q += __shfl_xor_sync(0xffffffffu, q, o);
    }
    float m   = s * (1.0f / 384.0f);
    float var = q * (1.0f / 384.0f) - m * m;
    float inv = rsqrtf(var + 1e-5f);

    #pragma unroll
    for (int j = 0; j < 3; ++j) {
        int col = j * 128 + lane * 4;
        float4 gq = *(const float4*)(gamma + col);
        float4 bq = *(const float4*)(beta + col);
        float o0 = (v[j].x - m) * inv * gq.x + bq.x;
        float o1 = (v[j].y - m) * inv * gq.y + bq.y;
        float o2 = (v[j].z - m) * inv * gq.z + bq.z;
        float o3 = (v[j].w - m) * inv * gq.w + bq.w;
        __half2 h0 = __floats2half2_rn(o0, o1);
        __half2 h1 = __floats2half2_rn(o2, o3);
        uint32_t u0, u1;
        memcpy(&u0, &h0, 4); memcpy(&u1, &h1, 4);
        uint2 ov; ov.x = u0; ov.y = u1;
        *(uint2*)(yr + col) = ov;
    }
}

// ---------------- driver ----------------
extern "C" void kernel_launch(void* const* d_in, const int* in_sizes, int n_in,
                              void* d_out, int out_size) {
    const float* x_in  = (const float*)d_in[0];
    const float* ln1_g = (const float*)d_in[1];
    const float* ln1_b = (const float*)d_in[2];
    const float* qkv_w = (const float*)d_in[3];
    const float* temp  = (const float*)d_in[4];
    const float* out_w = (const float*)d_in[5];
    const float* out_b = (const float*)d_in[6];
    const float* ln2_g = (const float*)d_in[7];
    const float* ln2_b = (const float*)d_in[8];
    const float* ff_w1 = (const float*)d_in[9];
    const float* ff_b1 = (const float*)d_in[10];
    const float* ff_w2 = (const float*)d_in[11];
    const float* ff_b2 = (const float*)d_in[12];
    float* x = (float*)d_out;

    __half *p_ln, *p_qkv, *p_attn, *p_ff, *p_wh;
    cudaGetSymbolAddress((void**)&p_ln,   g_ln);
    cudaGetSymbolAddress((void**)&p_qkv,  g_qkv);
    cudaGetSymbolAddress((void**)&p_attn, g_attn);
    cudaGetSymbolAddress((void**)&p_ff,   g_ff);
    cudaGetSymbolAddress((void**)&p_wh,   g_wh);

    cudaFuncSetAttribute(mma_gemm<0>, cudaFuncAttributeMaxDynamicSharedMemorySize, GS_BYTES);
    cudaFuncSetAttribute(mma_gemm<1>, cudaFuncAttributeMaxDynamicSharedMemorySize, GS_BYTES);
    cudaFuncSetAttribute(mma_gemm<2>, cudaFuncAttributeMaxDynamicSharedMemorySize, GS_BYTES);
    cudaFuncSetAttribute(flash_kernel, cudaFuncAttributeMaxDynamicSharedMemorySize, FL_DSMEM);

    cudaMemcpyAsync(x, x_in, (size_t)ROWS * DIMV * sizeof(float),
                    cudaMemcpyDeviceToDevice);

    // single fused fp32 -> half conversion of all weights
    {
        int n0 = DEPTH * WT_QKV_PER, n1 = DEPTH * WT_WO_PER;
        int n2 = DEPTH * WT_W1_PER;
        int n4tot = WT_TOTAL / 4;
        cvt_all_kernel<<<(n4tot + 255) / 256, 256>>>(
            qkv_w, n0, out_w, n1, ff_w1, n2, ff_w2, p_wh, n4tot);
    }

    for (int l = 0; l < DEPTH; l++) {
        // --- attention block ---
        ln_kernel<<<ROWS / 8, 256>>>(x, ln1_g + l * DIMV, ln1_b + l * DIMV, p_ln);
        mma_gemm<0><<<dim3(QKVW / 128, ROWS / 128), 256, GS_BYTES>>>(
            p_ln, p_wh + WT_QKV_OFF + (size_t)l * WT_QKV_PER,
            nullptr, nullptr, p_qkv, ROWS, QKVW, DIMV);
        flash_kernel<<<dim3(NN / 128, BHN), 256, FL_DSMEM>>>(p_qkv, p_attn, temp, l);
        mma_gemm<1><<<dim3(DIMV / 128, ROWS / 128), 256, GS_BYTES>>>(
            p_attn, p_wh + WT_WO_OFF + (size_t)l * WT_WO_PER,
            out_b + l * DIMV, x, x, ROWS, DIMV, INNER);
        // --- feed-forward block ---
        ln_kernel<<<ROWS / 8, 256>>>(x, ln2_g + l * DIMV, ln2_b + l * DIMV, p_ln);
        mma_gemm<2><<<dim3(MLPV / 128, ROWS / 128), 256, GS_BYTES>>>(
            p_ln, p_wh + WT_W1_OFF + (size_t)l * WT_W1_PER,
            ff_b1 + l * MLPV, nullptr, p_ff, ROWS, MLPV, DIMV);
        mma_gemm<1><<<dim3(DIMV / 128, ROWS / 128), 256, GS_BYTES>>>(
            p_ff, p_wh + WT_W2_OFF + (size_t)l * WT_W2_PER,
            ff_b2 + l * DIMV, x, x, ROWS, DIMV, MLPV);
    }
}